// round 11
// baseline (speedup 1.0000x reference)
#include <cuda_runtime.h>
#include <cuda_bf16.h>
#include <math.h>
#include <stdint.h>

// ---------------- problem dims ----------------
#define BATCH   4
#define S_IN    1028
#define D_IN    64
#define S1      1026
#define SEQ     1024
#define DH      512
#define D_MODEL 1024
#define NHEAD   16
#define HDIM    64
#define NLAYER  4
#define FFDIM   2048
#define QKV3    3072
#define EPSF    1e-6f

typedef __nv_bfloat16 bf16;

// ---------------- scratch (device globals; no allocation allowed) ----------------
__device__ float g_h   [BATCH*SEQ*D_MODEL];
__device__ float g_qkvb[NLAYER*QKV3];
__device__ float g_pool[BATCH*D_MODEL];

// split-bf16 activation buffers (hi/lo planes)
__device__ bf16 ga_h[4096*2048], ga_l[4096*2048];
__device__ bf16 gb_h[4096*2048], gb_l[4096*2048];
__device__ bf16 g_qkvh[(size_t)4096*QKV3], g_qkvl[(size_t)4096*QKV3];
// split-bf16 weights
__device__ bf16 bw_qkv_h[NLAYER*QKV3*1024], bw_qkv_l[NLAYER*QKV3*1024];
__device__ bf16 bw_o_h  [NLAYER*1024*1024], bw_o_l  [NLAYER*1024*1024];
__device__ bf16 bw_f1_h [NLAYER*2048*1024], bw_f1_l [NLAYER*2048*1024];
__device__ bf16 bw_f2_h [NLAYER*1024*2048], bw_f2_l [NLAYER*1024*2048];
__device__ bf16 bw_c1_h [512*192],          bw_c1_l [512*192];
__device__ bf16 bw_c2_h [1024*1536],        bw_c2_l [1024*1536];

// ================= helpers =================
__device__ __forceinline__ uint32_t smem_u32(const void* p) {
    uint32_t a;
    asm("{ .reg .u64 t; cvta.to.shared.u64 t, %1; cvt.u32.u64 %0, t; }" : "=r"(a) : "l"(p));
    return a;
}
// pack 2 fp32 -> bf16x2 (first arg -> low 16 bits)
__device__ __forceinline__ uint32_t bf16x2_of(float lo, float hi) {
    uint32_t r;
    asm("cvt.rn.bf16x2.f32 %0, %1, %2;" : "=r"(r) : "f"(hi), "f"(lo));
    return r;
}
__device__ __forceinline__ uint32_t split_lo(float v0, float v1, uint32_t hp) {
    float r0 = v0 - __uint_as_float(hp << 16);
    float r1 = v1 - __uint_as_float(hp & 0xffff0000u);
    return bf16x2_of(r0, r1);
}
#define LDSM_X4(r, addr) \
    asm volatile("ldmatrix.sync.aligned.m8n8.x4.shared.b16 {%0,%1,%2,%3}, [%4];" \
        : "=r"((r)[0]), "=r"((r)[1]), "=r"((r)[2]), "=r"((r)[3]) : "r"(addr))
#define LDSM_X4T(r, addr) \
    asm volatile("ldmatrix.sync.aligned.m8n8.x4.trans.shared.b16 {%0,%1,%2,%3}, [%4];" \
        : "=r"((r)[0]), "=r"((r)[1]), "=r"((r)[2]), "=r"((r)[3]) : "r"(addr))
#define MMA16816(d, a, b) \
    asm volatile("mma.sync.aligned.m16n8k16.row.col.f32.bf16.bf16.f32 " \
        "{%0,%1,%2,%3}, {%4,%5,%6,%7}, {%8,%9}, {%0,%1,%2,%3};" \
        : "+f"((d)[0]), "+f"((d)[1]), "+f"((d)[2]), "+f"((d)[3]) \
        : "r"((a)[0]), "r"((a)[1]), "r"((a)[2]), "r"((a)[3]), "r"((b)[0]), "r"((b)[1]))
#define CP_ASYNC16(dst, src) \
    asm volatile("cp.async.cg.shared.global [%0], [%1], 16;" :: "r"(dst), "l"(src) : "memory")
#define CP_COMMIT()  asm volatile("cp.async.commit_group;" ::: "memory")
#define CP_WAIT3()   asm volatile("cp.async.wait_group 3;" ::: "memory")
#define CP_WAIT2()   asm volatile("cp.async.wait_group 2;" ::: "memory")
#define CP_WAIT1()   asm volatile("cp.async.wait_group 1;" ::: "memory")

// ================= split-bf16 cp.async GEMM (BN=128): kept for conv1 (N=512) =================
#define STAGE_B  32768u
#define GEMM_SMEM (4u * STAGE_B)

template<bool SPLIT, bool RELU, bool RESID>
__global__ void __launch_bounds__(512, 1) gemm_bf5(
    const bf16* __restrict__ Ah, const bf16* __restrict__ Al,
    const bf16* __restrict__ Bh, const bf16* __restrict__ Bl,
    const float* __restrict__ bias, const float* __restrict__ resid,
    float* __restrict__ Cf, bf16* __restrict__ Ch, bf16* __restrict__ Cl,
    int M, int N, int K)
{
    extern __shared__ char smem[];
    const uint32_t sb = smem_u32(smem);
    const int tid = threadIdx.x, lane = tid & 31, wid = tid >> 5;
    const int crow = blockIdx.y * 128, ccol = blockIdx.x * 128;
    const int NK = K >> 5;

    const int lrow = tid >> 2;
    const int q    = tid & 3;
    const int pl   = q >> 1;
    const int sub  = q & 1;
    const uint32_t rxor = (uint32_t)(lrow & 7);
    int garow = crow + lrow; if (garow > M - 1) garow = M - 1;
    const bf16* baseA = (pl ? Al : Ah) + (size_t)garow * K;
    const bf16* baseB = (pl ? Bl : Bh) + (size_t)(ccol + lrow) * K;
    const uint32_t dAr = (uint32_t)lrow * 128u;
    const uint32_t dBr = 16384u + (uint32_t)lrow * 128u;
    const uint32_t cc0 = (uint32_t)(sub * 2);

    const int wm = wid & 3, wn = wid >> 2;
    const uint32_t aoff = (uint32_t)(wm * 32 + (lane & 15)) * 128u;
    const uint32_t boff = 16384u + (uint32_t)(wn * 32 + (lane & 15)) * 128u;
    const uint32_t sel  = (uint32_t)(lane >> 4);
    const uint32_t axor = (uint32_t)(lane & 7);

    float acc[2][4][4];
#pragma unroll
    for (int i = 0; i < 2; i++)
#pragma unroll
        for (int j = 0; j < 4; j++)
#pragma unroll
            for (int e = 0; e < 4; e++) acc[i][j][e] = 0.f;

    auto issue = [&](int kb) {
        if (kb < NK) {
            const bf16* sA = baseA + kb * 32;
            const bf16* sB = baseB + kb * 32;
            const uint32_t st = sb + (uint32_t)(kb & 3) * STAGE_B;
#pragma unroll
            for (int u = 0; u < 2; u++) {
                const uint32_t cc = cc0 + u;
                const uint32_t off = (((uint32_t)(pl * 4) + cc) ^ rxor) << 4;
                CP_ASYNC16(st + dAr + off, sA + cc * 8);
                CP_ASYNC16(st + dBr + off, sB + cc * 8);
            }
        }
        CP_COMMIT();
    };

    issue(0); issue(1); issue(2); issue(3);

    for (int kb = 0; kb < NK; kb++) {
        CP_WAIT3();
        __syncthreads();
        const uint32_t st = sb + (uint32_t)(kb & 3) * STAGE_B;
#pragma unroll
        for (int ks = 0; ks < 2; ks++) {
            const uint32_t chh = (((uint32_t)(ks * 2) + sel) ^ axor) << 4;
            const uint32_t chl = (((uint32_t)(4 + ks * 2) + sel) ^ axor) << 4;
            uint32_t bh[4][2], bl[4][2];
#pragma unroll
            for (int jj = 0; jj < 2; jj++) {
                uint32_t t4[4];
                LDSM_X4(t4, st + boff + (uint32_t)jj * (16u * 128u) + chh);
                bh[2 * jj][0] = t4[0]; bh[2 * jj][1] = t4[2];
                bh[2 * jj + 1][0] = t4[1]; bh[2 * jj + 1][1] = t4[3];
                LDSM_X4(t4, st + boff + (uint32_t)jj * (16u * 128u) + chl);
                bl[2 * jj][0] = t4[0]; bl[2 * jj][1] = t4[2];
                bl[2 * jj + 1][0] = t4[1]; bl[2 * jj + 1][1] = t4[3];
            }
#pragma unroll
            for (int i = 0; i < 2; i++) {
                const uint32_t ra = st + aoff + (uint32_t)i * (16u * 128u);
                uint32_t ah[4], al[4];
                LDSM_X4(ah, ra + chh);
                LDSM_X4(al, ra + chl);
#pragma unroll
                for (int j = 0; j < 4; j++) {
                    MMA16816(acc[i][j], ah, bh[j]);
                    MMA16816(acc[i][j], ah, bl[j]);
                    MMA16816(acc[i][j], al, bh[j]);
                }
            }
        }
        __syncthreads();
        issue(kb + 4);
    }

#pragma unroll
    for (int i = 0; i < 2; i++) {
        const int rb_ = crow + wm * 32 + i * 16 + (lane >> 2);
#pragma unroll
        for (int h = 0; h < 2; h++) {
            const int r = rb_ + h * 8;
            if (r >= M) continue;
            const size_t ro = (size_t)r * N;
#pragma unroll
            for (int j = 0; j < 4; j++) {
                const int c = ccol + wn * 32 + j * 8 + (lane & 3) * 2;
                float v0 = acc[i][j][2 * h]     + bias[c];
                float v1 = acc[i][j][2 * h + 1] + bias[c + 1];
                if (RELU) { v0 = fmaxf(v0, 0.f); v1 = fmaxf(v1, 0.f); }
                if (RESID) { v0 += resid[ro + c]; v1 += resid[ro + c + 1]; }
                if (SPLIT) {
                    uint32_t hp = bf16x2_of(v0, v1);
                    uint32_t lp = split_lo(v0, v1, hp);
                    *reinterpret_cast<uint32_t*>(&Ch[ro + c]) = hp;
                    *reinterpret_cast<uint32_t*>(&Cl[ro + c]) = lp;
                } else {
                    *reinterpret_cast<float2*>(&Cf[ro + c]) = make_float2(v0, v1);
                }
            }
        }
    }
}

// ================= wide GEMM (BN=256): 16 warps, warp tile 32x64, 3-stage pipeline =================
// stage: A 128x128B (16KB) + B 256x128B (32KB) = 48KB; 3 stages = 144KB.
#define WSTAGE 49152u
#define WGEMM_SMEM (3u * WSTAGE)

template<bool SPLIT, bool RELU, bool RESID>
__global__ void __launch_bounds__(512, 1) gemm_wide(
    const bf16* __restrict__ Ah, const bf16* __restrict__ Al,
    const bf16* __restrict__ Bh, const bf16* __restrict__ Bl,
    const float* __restrict__ bias, const float* __restrict__ resid,
    float* __restrict__ Cf, bf16* __restrict__ Ch, bf16* __restrict__ Cl,
    int M, int N, int K)
{
    extern __shared__ char smem[];
    const uint32_t sb = smem_u32(smem);
    const int tid = threadIdx.x, lane = tid & 31, wid = tid >> 5;
    const int crow = blockIdx.y * 128, ccol = blockIdx.x * 256;
    const int NK = K >> 5;

    // ---- loader precompute: 6 chunks/thread over 384 rows x 8 chunks ----
    const bf16* srcs[6];
    uint32_t dsts[6];
#pragma unroll
    for (int i = 0; i < 6; i++) {
        const int idx = tid + i * 512;
        const int row = idx >> 3;
        const int c = idx & 7;
        const int pl = c >> 2, q4 = c & 3;
        uint32_t d;
        const bf16* s;
        if (row < 128) {
            int gr = crow + row; if (gr > M - 1) gr = M - 1;
            s = (pl ? Al : Ah) + (size_t)gr * K + q4 * 8;
            d = (uint32_t)row * 128u;
        } else {
            const int br = row - 128;
            s = (pl ? Bl : Bh) + (size_t)(ccol + br) * K + q4 * 8;
            d = 16384u + (uint32_t)br * 128u;
        }
        srcs[i] = s;
        dsts[i] = d + ((uint32_t)(c ^ (row & 7)) << 4);
    }

    auto issue = [&](int kb) {
        if (kb < NK) {
            const uint32_t st = sb + (uint32_t)(kb % 3) * WSTAGE;
            const int ko = kb * 32;
#pragma unroll
            for (int i = 0; i < 6; i++)
                CP_ASYNC16(st + dsts[i], srcs[i] + ko);
        }
        CP_COMMIT();
    };

    const int wm = wid & 3, wn = wid >> 2;
    const uint32_t aoff = (uint32_t)(wm * 32 + (lane & 15)) * 128u;
    const uint32_t boff = 16384u + (uint32_t)(wn * 64 + (lane & 15)) * 128u;
    const uint32_t sel  = (uint32_t)(lane >> 4);
    const uint32_t axor = (uint32_t)(lane & 7);

    float acc[2][8][4];
#pragma unroll
    for (int i = 0; i < 2; i++)
#pragma unroll
        for (int j = 0; j < 8; j++)
#pragma unroll
            for (int e = 0; e < 4; e++) acc[i][j][e] = 0.f;

    issue(0); issue(1); issue(2);

    for (int kb = 0; kb < NK; kb++) {
        CP_WAIT2();
        __syncthreads();
        const uint32_t st = sb + (uint32_t)(kb % 3) * WSTAGE;
#pragma unroll
        for (int ks = 0; ks < 2; ks++) {
            const uint32_t chh = (((uint32_t)(ks * 2) + sel) ^ axor) << 4;
            const uint32_t chl = (((uint32_t)(4 + ks * 2) + sel) ^ axor) << 4;
            uint32_t ah[2][4], al[2][4];
#pragma unroll
            for (int i = 0; i < 2; i++) {
                const uint32_t ra = st + aoff + (uint32_t)i * (16u * 128u);
                LDSM_X4(ah[i], ra + chh);
                LDSM_X4(al[i], ra + chl);
            }
#pragma unroll
            for (int jj = 0; jj < 4; jj++) {
                const uint32_t rb = st + boff + (uint32_t)jj * (16u * 128u);
                uint32_t th[4], tl[4];
                LDSM_X4(th, rb + chh);
                LDSM_X4(tl, rb + chl);
                uint32_t b0h[2] = {th[0], th[2]}, b1h[2] = {th[1], th[3]};
                uint32_t b0l[2] = {tl[0], tl[2]}, b1l[2] = {tl[1], tl[3]};
#pragma unroll
                for (int i = 0; i < 2; i++) {
                    MMA16816(acc[i][2 * jj],     ah[i], b0h);
                    MMA16816(acc[i][2 * jj],     ah[i], b0l);
                    MMA16816(acc[i][2 * jj],     al[i], b0h);
                    MMA16816(acc[i][2 * jj + 1], ah[i], b1h);
                    MMA16816(acc[i][2 * jj + 1], ah[i], b1l);
                    MMA16816(acc[i][2 * jj + 1], al[i], b1h);
                }
            }
        }
        __syncthreads();
        issue(kb + 3);
    }

    // ---- epilogue ----
#pragma unroll
    for (int i = 0; i < 2; i++) {
        const int rb_ = crow + wm * 32 + i * 16 + (lane >> 2);
#pragma unroll
        for (int h = 0; h < 2; h++) {
            const int r = rb_ + h * 8;
            if (r >= M) continue;
            const size_t ro = (size_t)r * N;
#pragma unroll
            for (int j = 0; j < 8; j++) {
                const int c = ccol + wn * 64 + j * 8 + (lane & 3) * 2;
                float v0 = acc[i][j][2 * h]     + bias[c];
                float v1 = acc[i][j][2 * h + 1] + bias[c + 1];
                if (RELU) { v0 = fmaxf(v0, 0.f); v1 = fmaxf(v1, 0.f); }
                if (RESID) { v0 += resid[ro + c]; v1 += resid[ro + c + 1]; }
                if (SPLIT) {
                    uint32_t hp = bf16x2_of(v0, v1);
                    uint32_t lp = split_lo(v0, v1, hp);
                    *reinterpret_cast<uint32_t*>(&Ch[ro + c]) = hp;
                    *reinterpret_cast<uint32_t*>(&Cl[ro + c]) = lp;
                } else {
                    *reinterpret_cast<float2*>(&Cf[ro + c]) = make_float2(v0, v1);
                }
            }
        }
    }
}

// ================= MMA attention: softsign(QK^T/8) @ V, all split-bf16 =================
#define ATT_SMEM (96 * 1024)

__global__ void __launch_bounds__(256, 1) attention_mma(
    const bf16* __restrict__ QKVh, const bf16* __restrict__ QKVl,
    bf16* __restrict__ Oh, bf16* __restrict__ Ol)
{
    extern __shared__ char smem[];
    const uint32_t sb = smem_u32(smem);
    const int tid = threadIdx.x, lane = tid & 31, wid = tid >> 5;
    const int qt = blockIdx.x;
    const int h  = blockIdx.y;
    const int b  = blockIdx.z;
    const uint32_t QS = sb + 65536u;

    {
        const bf16* src = ((tid & 1) ? QKVl : QKVh);
        const int row = tid >> 1;
        const bf16* s = src + (size_t)(b * SEQ + qt * 128 + row) * QKV3 + h * HDIM;
        const uint32_t d = QS + (uint32_t)(tid & 1) * 16384u + (uint32_t)row * 128u;
        const uint32_t rx = (uint32_t)(row & 7);
#pragma unroll
        for (int c = 0; c < 8; c++)
            CP_ASYNC16(d + (((uint32_t)c ^ rx) << 4), s + c * 8);
    }

    auto issueKV = [&](int jt) {
        if (jt < 16) {
            const int mat = tid & 1;
            const int pl  = (tid >> 1) & 1;
            const int row = tid >> 2;
            const bf16* src = (pl ? QKVl : QKVh);
            const bf16* s = src + (size_t)(b * SEQ + jt * 64 + row) * QKV3
                          + 1024 + mat * 1024 + h * HDIM;
            const uint32_t d = sb + (uint32_t)(jt & 1) * 32768u + (uint32_t)mat * 16384u
                             + (uint32_t)pl * 8192u + (uint32_t)row * 128u;
            const uint32_t rx = (uint32_t)(row & 7);
#pragma unroll
            for (int c = 0; c < 8; c++)
                CP_ASYNC16(d + (((uint32_t)c ^ rx) << 4), s + c * 8);
        }
        CP_COMMIT();
    };

    issueKV(0);
    issueKV(1);

    CP_WAIT1();
    __syncthreads();

    const uint32_t sel = (uint32_t)(lane >> 4);
    uint32_t qh[4][4], ql[4][4];
    {
        const uint32_t arow = (uint32_t)(wid * 16 + (lane & 15));
        const uint32_t swz = arow & 7u;
        const uint32_t ra = QS + arow * 128u;
#pragma unroll
        for (int kt = 0; kt < 4; kt++) {
            const uint32_t ch = (((uint32_t)(2 * kt) + sel) ^ swz) << 4;
            LDSM_X4(qh[kt], ra + ch);
            LDSM_X4(ql[kt], ra + 16384u + ch);
        }
    }

    float o[8][4];
#pragma unroll
    for (int j = 0; j < 8; j++)
#pragma unroll
        for (int e = 0; e < 4; e++) o[j][e] = 0.f;

    for (int jt = 0; jt < 16; jt++) {
        const uint32_t ST = sb + (uint32_t)(jt & 1) * 32768u;

        float s[8][4];
#pragma unroll
        for (int j = 0; j < 8; j++)
#pragma unroll
            for (int e = 0; e < 4; e++) s[j][e] = 0.f;

        const uint32_t brow = (uint32_t)(lane & 15);
#pragma unroll
        for (int kt = 0; kt < 4; kt++) {
#pragma unroll
            for (int ng = 0; ng < 4; ng++) {
                const uint32_t r = (uint32_t)(ng * 16) + brow;
                const uint32_t ch = (((uint32_t)(2 * kt) + sel) ^ (r & 7u)) << 4;
                const uint32_t addr = ST + r * 128u + ch;
                uint32_t kh[4], kl[4];
                LDSM_X4(kh, addr);
                LDSM_X4(kl, addr + 8192u);
                uint32_t bh0[2] = {kh[0], kh[2]}, bh1[2] = {kh[1], kh[3]};
                uint32_t bl0[2] = {kl[0], kl[2]}, bl1[2] = {kl[1], kl[3]};
                MMA16816(s[2 * ng],     qh[kt], bh0);
                MMA16816(s[2 * ng],     qh[kt], bl0);
                MMA16816(s[2 * ng],     ql[kt], bh0);
                MMA16816(s[2 * ng + 1], qh[kt], bh1);
                MMA16816(s[2 * ng + 1], qh[kt], bl1);
                MMA16816(s[2 * ng + 1], ql[kt], bh1);
            }
        }

#pragma unroll
        for (int j = 0; j < 8; j++)
#pragma unroll
            for (int e = 0; e < 4; e++) {
                float t = s[j][e] * 0.125f;
                s[j][e] = __fdividef(t, 1.0f + fabsf(t));
            }

        uint32_t phi[4][4], plo[4][4];
#pragma unroll
        for (int kt = 0; kt < 4; kt++) {
            const float* p0 = s[2 * kt];
            const float* p1 = s[2 * kt + 1];
            phi[kt][0] = bf16x2_of(p0[0], p0[1]);
            phi[kt][1] = bf16x2_of(p0[2], p0[3]);
            phi[kt][2] = bf16x2_of(p1[0], p1[1]);
            phi[kt][3] = bf16x2_of(p1[2], p1[3]);
            plo[kt][0] = split_lo(p0[0], p0[1], phi[kt][0]);
            plo[kt][1] = split_lo(p0[2], p0[3], phi[kt][1]);
            plo[kt][2] = split_lo(p1[0], p1[1], phi[kt][2]);
            plo[kt][3] = split_lo(p1[2], p1[3], phi[kt][3]);
        }

#pragma unroll
        for (int dg = 0; dg < 8; dg++) {
#pragma unroll
            for (int jh = 0; jh < 2; jh++) {
                const uint32_t r = (uint32_t)(jh * 32 + lane);
                const uint32_t ch = ((uint32_t)dg ^ (r & 7u)) << 4;
                const uint32_t addr = ST + 16384u + r * 128u + ch;
                uint32_t vh[4], vl[4];
                LDSM_X4T(vh, addr);
                LDSM_X4T(vl, addr + 8192u);
                uint32_t bh0[2] = {vh[0], vh[1]}, bh1[2] = {vh[2], vh[3]};
                uint32_t bl0[2] = {vl[0], vl[1]}, bl1[2] = {vl[2], vl[3]};
                const int k0 = 2 * jh, k1 = 2 * jh + 1;
                MMA16816(o[dg], phi[k0], bh0);
                MMA16816(o[dg], phi[k0], bl0);
                MMA16816(o[dg], plo[k0], bh0);
                MMA16816(o[dg], phi[k1], bh1);
                MMA16816(o[dg], phi[k1], bl1);
                MMA16816(o[dg], plo[k1], bh1);
            }
        }

        __syncthreads();
        issueKV(jt + 2);
        if (jt + 1 < 16) { CP_WAIT1(); __syncthreads(); }
    }

    const int grow = b * SEQ + qt * 128 + wid * 16 + (lane >> 2);
    const int cbase = h * HDIM + (lane & 3) * 2;
#pragma unroll
    for (int dg = 0; dg < 8; dg++) {
        const int col = cbase + dg * 8;
        uint32_t hp0 = bf16x2_of(o[dg][0], o[dg][1]);
        uint32_t lp0 = split_lo(o[dg][0], o[dg][1], hp0);
        size_t off0 = (size_t)grow * D_MODEL + col;
        *reinterpret_cast<uint32_t*>(&Oh[off0]) = hp0;
        *reinterpret_cast<uint32_t*>(&Ol[off0]) = lp0;
        uint32_t hp1 = bf16x2_of(o[dg][2], o[dg][3]);
        uint32_t lp1 = split_lo(o[dg][2], o[dg][3], hp1);
        size_t off1 = off0 + (size_t)8 * D_MODEL;
        *reinterpret_cast<uint32_t*>(&Oh[off1]) = hp1;
        *reinterpret_cast<uint32_t*>(&Ol[off1]) = lp1;
    }
}

// ================= weight preparation =================
__global__ void wsplit4(const float* __restrict__ src, bf16* __restrict__ h,
                        bf16* __restrict__ l, int n4)
{
    int i = blockIdx.x * 256 + threadIdx.x;
    if (i >= n4) return;
    float4 v = reinterpret_cast<const float4*>(src)[i];
    uint32_t h0 = bf16x2_of(v.x, v.y), h1 = bf16x2_of(v.z, v.w);
    uint32_t l0 = split_lo(v.x, v.y, h0), l1 = split_lo(v.z, v.w, h1);
    reinterpret_cast<uint2*>(h)[i] = make_uint2(h0, h1);
    reinterpret_cast<uint2*>(l)[i] = make_uint2(l0, l1);
}

__global__ void qkv_pack(const float* __restrict__ q, const float* __restrict__ k,
                         const float* __restrict__ v, bf16* __restrict__ h, bf16* __restrict__ l)
{
    int i = blockIdx.x * 256 + threadIdx.x;
    if (i >= NLAYER * QKV3 * 256) return;
    int e = i * 4;
    int lay = e / (QKV3 * 1024);
    int rem = e - lay * (QKV3 * 1024);
    int n = rem >> 10, kk = rem & 1023;
    const float* src = (n < 1024) ? q : (n < 2048) ? k : v;
    float4 val = *reinterpret_cast<const float4*>(
        src + (size_t)lay * 1048576 + (size_t)(n & 1023) * 1024 + kk);
    uint32_t h0 = bf16x2_of(val.x, val.y), h1 = bf16x2_of(val.z, val.w);
    uint32_t l0 = split_lo(val.x, val.y, h0), l1 = split_lo(val.z, val.w, h1);
    reinterpret_cast<uint2*>(h)[i] = make_uint2(h0, h1);
    reinterpret_cast<uint2*>(l)[i] = make_uint2(l0, l1);
}

__global__ void qkvb_pack(const float* __restrict__ q, const float* __restrict__ k,
                          const float* __restrict__ v, float* __restrict__ out)
{
    int i = blockIdx.x * 256 + threadIdx.x;
    if (i >= NLAYER * QKV3) return;
    int lay = i / QKV3, n = i % QKV3;
    const float* src = (n < 1024) ? q : (n < 2048) ? k : v;
    out[i] = src[lay * 1024 + (n & 1023)];
}

__global__ void conv_repack(const float* __restrict__ w, bf16* __restrict__ h,
                            bf16* __restrict__ l, int OC, int IC)
{
    int K = IC * 3;
    int idx = blockIdx.x * 256 + threadIdx.x;
    if (idx >= OC * K) return;
    int c = idx / K, r = idx % K;
    int kk = r / IC, ic = r % IC;
    float v = w[(size_t)c * K + ic * 3 + kk];
    bf16 hv = __float2bfloat16_rn(v);
    h[idx] = hv;
    l[idx] = __float2bfloat16_rn(v - __bfloat162float(hv));
}

// ================= im2col (split outputs) =================
__global__ void im2col1s(const float* __restrict__ x, bf16* __restrict__ oh, bf16* __restrict__ ol)
{
    const int C4 = 192 / 4;
    int idx = blockIdx.x * 256 + threadIdx.x;
    if (idx >= BATCH * S1 * C4) return;
    int m = idx / C4, c4 = (idx % C4) * 4;
    int b = m / S1, s = m % S1;
    int kk = c4 / D_IN, ic = c4 % D_IN;
    float4 v = *reinterpret_cast<const float4*>(&x[((size_t)(b * S_IN + s + kk)) * D_IN + ic]);
    uint32_t h0 = bf16x2_of(v.x, v.y), h1 = bf16x2_of(v.z, v.w);
    uint32_t l0 = split_lo(v.x, v.y, h0), l1 = split_lo(v.z, v.w, h1);
    *reinterpret_cast<uint2*>(&oh[(size_t)m * 192 + c4]) = make_uint2(h0, h1);
    *reinterpret_cast<uint2*>(&ol[(size_t)m * 192 + c4]) = make_uint2(l0, l1);
}

__global__ void im2col2s(const bf16* __restrict__ ih, const bf16* __restrict__ il,
                         bf16* __restrict__ oh, bf16* __restrict__ ol)
{
    const int C8 = 1536 / 8;
    int idx = blockIdx.x * 256 + threadIdx.x;
    if (idx >= BATCH * SEQ * C8) return;
    int m = idx / C8, c8 = (idx % C8) * 8;
    int b = m / SEQ, s = m % SEQ;
    int kk = c8 / DH, ic = c8 % DH;
    size_t si = ((size_t)(b * S1 + s + kk)) * DH + ic;
    size_t di = (size_t)m * 1536 + c8;
    *reinterpret_cast<uint4*>(&oh[di]) = *reinterpret_cast<const uint4*>(&ih[si]);
    *reinterpret_cast<uint4*>(&ol[di]) = *reinterpret_cast<const uint4*>(&il[si]);
}

// ---------------- positional encoding add ----------------
__global__ void pos_add_kernel(float* __restrict__ h)
{
    int idx = blockIdx.x * 256 + threadIdx.x;
    if (idx >= BATCH * SEQ * D_MODEL) return;
    int d = idx & (D_MODEL - 1);
    int s = (idx >> 10) & (SEQ - 1);
    int i2 = d & ~1;
    float freq = expf((float)i2 * (-9.210340371976184f / 1024.0f));
    float ang  = (float)s * freq;
    double angd = (double)ang;
    double kq = rint(angd * 0.15915494309189535);
    float r = (float)(angd - kq * 6.283185307179586);
    float pe = (d & 1) ? cosf(r) : sinf(r);
    h[idx] += pe;
}

// ---------------- LayerNorm (torch-style) -> split bf16 output ----------------
__global__ void __launch_bounds__(256) layernorm_kernel(
    const float* __restrict__ x, const float* __restrict__ w,
    const float* __restrict__ b, bf16* __restrict__ yh, bf16* __restrict__ yl)
{
    __shared__ float red[8];
    __shared__ float sh_mean, sh_inv;
    const int row = blockIdx.x;
    const int t = threadIdx.x;
    const float* xr = x + (size_t)row * D_MODEL;
    float4 v = *reinterpret_cast<const float4*>(&xr[t * 4]);

    float s = v.x + v.y + v.z + v.w;
#pragma unroll
    for (int o = 16; o > 0; o >>= 1) s += __shfl_xor_sync(0xffffffffu, s, o);
    if ((t & 31) == 0) red[t >> 5] = s;
    __syncthreads();
    if (t == 0) {
        float tot = 0.f;
#pragma unroll
        for (int i = 0; i < 8; i++) tot += red[i];
        sh_mean = tot * (1.0f / 1024.0f);
    }
    __syncthreads();
    float mean = sh_mean;
    float d0 = v.x - mean, d1 = v.y - mean, d2 = v.z - mean, d3 = v.w - mean;
    float sq = d0 * d0 + d1 * d1 + d2 * d2 + d3 * d3;
#pragma unroll
    for (int o = 16; o > 0; o >>= 1) sq += __shfl_xor_sync(0xffffffffu, sq, o);
    if ((t & 31) == 0) red[t >> 5] = sq;
    __syncthreads();
    if (t == 0) {
        float tot = 0.f;
#pragma unroll
        for (int i = 0; i < 8; i++) tot += red[i];
        float var = tot * (1.0f / 1023.0f);
        sh_inv = 1.0f / (sqrtf(var) + EPSF);
    }
    __syncthreads();
    float inv = sh_inv;
    float4 w4 = *reinterpret_cast<const float4*>(&w[t * 4]);
    float4 b4 = *reinterpret_cast<const float4*>(&b[t * 4]);
    float o0 = w4.x * d0 * inv + b4.x;
    float o1 = w4.y * d1 * inv + b4.y;
    float o2 = w4.z * d2 * inv + b4.z;
    float o3 = w4.w * d3 * inv + b4.w;
    uint32_t h01 = bf16x2_of(o0, o1), h23 = bf16x2_of(o2, o3);
    uint32_t l01 = split_lo(o0, o1, h01), l23 = split_lo(o2, o3, h23);
    size_t off = (size_t)row * D_MODEL + t * 4;
    *reinterpret_cast<uint2*>(&yh[off]) = make_uint2(h01, h23);
    *reinterpret_cast<uint2*>(&yl[off]) = make_uint2(l01, l23);
}

// ---------------- mean pool + final fc ----------------
__global__ void pool_kernel(const float* __restrict__ h, float* __restrict__ out)
{
    int idx = blockIdx.x * 256 + threadIdx.x;
    if (idx >= BATCH * D_MODEL) return;
    int b = idx >> 10, d = idx & (D_MODEL - 1);
    const float* p = h + (size_t)(b * SEQ) * D_MODEL + d;
    float a[8];
#pragma unroll
    for (int i = 0; i < 8; i++) a[i] = 0.f;
    for (int i = 0; i < SEQ; i += 8) {
#pragma unroll
        for (int u = 0; u < 8; u++) a[u] += p[(size_t)(i + u) * D_MODEL];
    }
    float s = ((a[0] + a[1]) + (a[2] + a[3])) + ((a[4] + a[5]) + (a[6] + a[7]));
    out[idx] = s * (1.0f / 1024.0f);
}

__global__ void fc_kernel(const float* __restrict__ pool, const float* __restrict__ fcw,
                          const float* __restrict__ fcb, float* __restrict__ out)
{
    __shared__ float red[8];
    int b = blockIdx.x, t = threadIdx.x;
    float4 p  = *reinterpret_cast<const float4*>(&pool[b * D_MODEL + t * 4]);
    float4 w4 = *reinterpret_cast<const float4*>(&fcw[t * 4]);
    float s = p.x * w4.x + p.y * w4.y + p.z * w4.z + p.w * w4.w;
#pragma unroll
    for (int o = 16; o > 0; o >>= 1) s += __shfl_xor_sync(0xffffffffu, s, o);
    if ((t & 31) == 0) red[t >> 5] = s;
    __syncthreads();
    if (t == 0) {
        float tot = 0.f;
#pragma unroll
        for (int i = 0; i < 8; i++) tot += red[i];
        out[b] = tot + fcb[0];
    }
}

// ---------------- host orchestration ----------------
#define SYM(p, s) cudaGetSymbolAddress((void**)&p, s)

extern "C" void kernel_launch(void* const* d_in, const int* in_sizes, int n_in,
                              void* d_out, int out_size)
{
    (void)in_sizes; (void)n_in; (void)out_size;
    const float* x       = (const float*)d_in[0];
    const float* conv1_w = (const float*)d_in[1];
    const float* conv1_b = (const float*)d_in[2];
    const float* conv2_w = (const float*)d_in[3];
    const float* conv2_b = (const float*)d_in[4];
    const float* lnA_w   = (const float*)d_in[5];
    const float* lnA_b   = (const float*)d_in[6];
    const float* q_w     = (const float*)d_in[7];
    const float* q_b     = (const float*)d_in[8];
    const float* k_w     = (const float*)d_in[9];
    const float* k_b     = (const float*)d_in[10];
    const float* v_w     = (const float*)d_in[11];
    const float* v_b     = (const float*)d_in[12];
    const float* o_w     = (const float*)d_in[13];
    const float* o_b     = (const float*)d_in[14];
    const float* lnB_w   = (const float*)d_in[15];
    const float* lnB_b   = (const float*)d_in[16];
    const float* f1_w    = (const float*)d_in[17];
    const float* f1_b    = (const float*)d_in[18];
    const float* f2_w    = (const float*)d_in[19];
    const float* f2_b    = (const float*)d_in[20];
    const float* fc_w    = (const float*)d_in[21];
    const float* fc_b    = (const float*)d_in[22];
    float* out = (float*)d_out;

    float *p_h, *p_qkvb, *p_pool;
    bf16 *p_gah, *p_gal, *p_gbh, *p_gbl, *p_qvh, *p_qvl;
    bf16 *p_qkvh, *p_qkvl, *p_oh, *p_ol, *p_f1h, *p_f1l, *p_f2h, *p_f2l;
    bf16 *p_c1h, *p_c1l, *p_c2h, *p_c2l;
    SYM(p_h, g_h); SYM(p_qkvb, g_qkvb); SYM(p_pool, g_pool);
    SYM(p_gah, ga_h); SYM(p_gal, ga_l); SYM(p_gbh, gb_h); SYM(p_gbl, gb_l);
    SYM(p_qvh, g_qkvh); SYM(p_qvl, g_qkvl);
    SYM(p_qkvh, bw_qkv_h); SYM(p_qkvl, bw_qkv_l);
    SYM(p_oh, bw_o_h); SYM(p_ol, bw_o_l);
    SYM(p_f1h, bw_f1_h); SYM(p_f1l, bw_f1_l);
    SYM(p_f2h, bw_f2_h); SYM(p_f2l, bw_f2_l);
    SYM(p_c1h, bw_c1_h); SYM(p_c1l, bw_c1_l);
    SYM(p_c2h, bw_c2_h); SYM(p_c2l, bw_c2_l);

    cudaFuncSetAttribute(attention_mma, cudaFuncAttributeMaxDynamicSharedMemorySize, ATT_SMEM);
    cudaFuncSetAttribute(gemm_bf5<true, false, false>, cudaFuncAttributeMaxDynamicSharedMemorySize, GEMM_SMEM);
    cudaFuncSetAttribute(gemm_wide<false, false, false>, cudaFuncAttributeMaxDynamicSharedMemorySize, WGEMM_SMEM);
    cudaFuncSetAttribute(gemm_wide<false, false, true>,  cudaFuncAttributeMaxDynamicSharedMemorySize, WGEMM_SMEM);
    cudaFuncSetAttribute(gemm_wide<true, false, false>,  cudaFuncAttributeMaxDynamicSharedMemorySize, WGEMM_SMEM);
    cudaFuncSetAttribute(gemm_wide<true, true, false>,   cudaFuncAttributeMaxDynamicSharedMemorySize, WGEMM_SMEM);

    // ---- weight prep (split to bf16 hi/lo) ----
    qkv_pack<<<(NLAYER * QKV3 * 256 + 255) / 256, 256>>>(q_w, k_w, v_w, p_qkvh, p_qkvl);
    qkvb_pack<<<(NLAYER * QKV3 + 255) / 256, 256>>>(q_b, k_b, v_b, p_qkvb);
    wsplit4<<<(NLAYER * 1024 * 256 + 255) / 256, 256>>>(o_w, p_oh, p_ol, NLAYER * 1024 * 256);
    wsplit4<<<(NLAYER * 2048 * 256 + 255) / 256, 256>>>(f1_w, p_f1h, p_f1l, NLAYER * 2048 * 256);
    wsplit4<<<(NLAYER * 2048 * 256 + 255) / 256, 256>>>(f2_w, p_f2h, p_f2l, NLAYER * 2048 * 256);
    conv_repack<<<(512 * 192 + 255) / 256, 256>>>(conv1_w, p_c1h, p_c1l, 512, D_IN);
    conv_repack<<<(1024 * 1536 + 255) / 256, 256>>>(conv2_w, p_c2h, p_c2l, 1024, DH);

    // ---- conv frontend ----
    im2col1s<<<(BATCH * S1 * 48 + 255) / 256, 256>>>(x, p_gah, p_gal);
    gemm_bf5<true, false, false><<<dim3(4, 33), 512, GEMM_SMEM>>>(
        p_gah, p_gal, p_c1h, p_c1l, conv1_b, nullptr, nullptr, p_gbh, p_gbl,
        BATCH * S1, DH, 192);
    im2col2s<<<(BATCH * SEQ * 192 + 255) / 256, 256>>>(p_gbh, p_gbl, p_gah, p_gal);
    gemm_wide<false, false, false><<<dim3(4, 32), 512, WGEMM_SMEM>>>(
        p_gah, p_gal, p_c2h, p_c2l, conv2_b, nullptr, p_h, nullptr, nullptr,
        BATCH * SEQ, D_MODEL, 1536);
    pos_add_kernel<<<(BATCH * SEQ * D_MODEL) / 256, 256>>>(p_h);

    const int M = BATCH * SEQ;  // 4096

    for (int l = 0; l < NLAYER; l++) {
        size_t qkvo = (size_t)l * QKV3 * 1024;
        size_t oo   = (size_t)l * 1024 * 1024;
        size_t f1o  = (size_t)l * 2048 * 1024;
        size_t f2o  = (size_t)l * 1024 * 2048;
        size_t bo   = (size_t)l * D_MODEL;

        layernorm_kernel<<<M, 256>>>(p_h, lnA_w + bo, lnA_b + bo, p_gah, p_gal);
        gemm_wide<true, false, false><<<dim3(QKV3 / 256, 32), 512, WGEMM_SMEM>>>(
            p_gah, p_gal, p_qkvh + qkvo, p_qkvl + qkvo, p_qkvb + (size_t)l * QKV3,
            nullptr, nullptr, p_qvh, p_qvl, M, QKV3, 1024);

        attention_mma<<<dim3(SEQ / 128, NHEAD, BATCH), 256, ATT_SMEM>>>(
            p_qvh, p_qvl, p_gah, p_gal);

        gemm_wide<false, false, true><<<dim3(4, 32), 512, WGEMM_SMEM>>>(
            p_gah, p_gal, p_oh + oo, p_ol + oo, o_b + bo, p_h, p_h, nullptr, nullptr,
            M, D_MODEL, 1024);

        layernorm_kernel<<<M, 256>>>(p_h, lnB_w + bo, lnB_b + bo, p_gah, p_gal);
        gemm_wide<true, true, false><<<dim3(FFDIM / 256, 32), 512, WGEMM_SMEM>>>(
            p_gah, p_gal, p_f1h + f1o, p_f1l + f1o, f1_b + (size_t)l * FFDIM,
            nullptr, nullptr, p_gbh, p_gbl, M, FFDIM, 1024);
        gemm_wide<false, false, true><<<dim3(4, 32), 512, WGEMM_SMEM>>>(
            p_gbh, p_gbl, p_f2h + f2o, p_f2l + f2o, f2_b + bo, p_h, p_h, nullptr, nullptr,
            M, D_MODEL, 2048);
    }

    pool_kernel<<<(BATCH * D_MODEL) / 256, 256>>>(p_h, p_pool);
    fc_kernel<<<BATCH, 256>>>(p_pool, fc_w, fc_b, out);
}

// round 12
// speedup vs baseline: 1.0950x; 1.0950x over previous
#include <cuda_runtime.h>
#include <cuda_bf16.h>
#include <math.h>
#include <stdint.h>

// ---------------- problem dims ----------------
#define BATCH   4
#define S_IN    1028
#define D_IN    64
#define S1      1026
#define SEQ     1024
#define DH      512
#define D_MODEL 1024
#define NHEAD   16
#define HDIM    64
#define NLAYER  4
#define FFDIM   2048
#define QKV3    3072
#define EPSF    1e-6f

typedef __nv_bfloat16 bf16;

// ---------------- scratch (device globals; no allocation allowed) ----------------
__device__ float g_h   [BATCH*SEQ*D_MODEL];
__device__ float g_qkvb[NLAYER*QKV3];
__device__ float g_pool[BATCH*D_MODEL];

// split-bf16 activation buffers (hi/lo planes)
__device__ bf16 ga_h[4096*2048], ga_l[4096*2048];
__device__ bf16 gb_h[4096*2048], gb_l[4096*2048];
__device__ bf16 g_qkvh[(size_t)4096*QKV3], g_qkvl[(size_t)4096*QKV3];
// split-bf16 weights
__device__ bf16 bw_qkv_h[NLAYER*QKV3*1024], bw_qkv_l[NLAYER*QKV3*1024];
__device__ bf16 bw_o_h  [NLAYER*1024*1024], bw_o_l  [NLAYER*1024*1024];
__device__ bf16 bw_f1_h [NLAYER*2048*1024], bw_f1_l [NLAYER*2048*1024];
__device__ bf16 bw_f2_h [NLAYER*1024*2048], bw_f2_l [NLAYER*1024*2048];
__device__ bf16 bw_c1_h [512*192],          bw_c1_l [512*192];
__device__ bf16 bw_c2_h [1024*1536],        bw_c2_l [1024*1536];

// ================= helpers =================
__device__ __forceinline__ uint32_t smem_u32(const void* p) {
    uint32_t a;
    asm("{ .reg .u64 t; cvta.to.shared.u64 t, %1; cvt.u32.u64 %0, t; }" : "=r"(a) : "l"(p));
    return a;
}
// pack 2 fp32 -> bf16x2 (first arg -> low 16 bits)
__device__ __forceinline__ uint32_t bf16x2_of(float lo, float hi) {
    uint32_t r;
    asm("cvt.rn.bf16x2.f32 %0, %1, %2;" : "=r"(r) : "f"(hi), "f"(lo));
    return r;
}
__device__ __forceinline__ uint32_t split_lo(float v0, float v1, uint32_t hp) {
    float r0 = v0 - __uint_as_float(hp << 16);
    float r1 = v1 - __uint_as_float(hp & 0xffff0000u);
    return bf16x2_of(r0, r1);
}
#define LDSM_X4(r, addr) \
    asm volatile("ldmatrix.sync.aligned.m8n8.x4.shared.b16 {%0,%1,%2,%3}, [%4];" \
        : "=r"((r)[0]), "=r"((r)[1]), "=r"((r)[2]), "=r"((r)[3]) : "r"(addr))
#define LDSM_X4T(r, addr) \
    asm volatile("ldmatrix.sync.aligned.m8n8.x4.trans.shared.b16 {%0,%1,%2,%3}, [%4];" \
        : "=r"((r)[0]), "=r"((r)[1]), "=r"((r)[2]), "=r"((r)[3]) : "r"(addr))
#define MMA16816(d, a, b) \
    asm volatile("mma.sync.aligned.m16n8k16.row.col.f32.bf16.bf16.f32 " \
        "{%0,%1,%2,%3}, {%4,%5,%6,%7}, {%8,%9}, {%0,%1,%2,%3};" \
        : "+f"((d)[0]), "+f"((d)[1]), "+f"((d)[2]), "+f"((d)[3]) \
        : "r"((a)[0]), "r"((a)[1]), "r"((a)[2]), "r"((a)[3]), "r"((b)[0]), "r"((b)[1]))
#define CP_ASYNC16(dst, src) \
    asm volatile("cp.async.cg.shared.global [%0], [%1], 16;" :: "r"(dst), "l"(src) : "memory")
#define CP_COMMIT()  asm volatile("cp.async.commit_group;" ::: "memory")
#define CP_WAIT3()   asm volatile("cp.async.wait_group 3;" ::: "memory")
#define CP_WAIT1()   asm volatile("cp.async.wait_group 1;" ::: "memory")

// ================= split-bf16 cp.async GEMM (BN=128): kept for conv1 (N=512) =================
#define STAGE_B  32768u
#define GEMM_SMEM (4u * STAGE_B)

template<bool SPLIT, bool RELU, bool RESID>
__global__ void __launch_bounds__(512, 1) gemm_bf5(
    const bf16* __restrict__ Ah, const bf16* __restrict__ Al,
    const bf16* __restrict__ Bh, const bf16* __restrict__ Bl,
    const float* __restrict__ bias, const float* __restrict__ resid,
    float* __restrict__ Cf, bf16* __restrict__ Ch, bf16* __restrict__ Cl,
    int M, int N, int K)
{
    extern __shared__ char smem[];
    const uint32_t sb = smem_u32(smem);
    const int tid = threadIdx.x, lane = tid & 31, wid = tid >> 5;
    const int crow = blockIdx.y * 128, ccol = blockIdx.x * 128;
    const int NK = K >> 5;

    const int lrow = tid >> 2;
    const int q    = tid & 3;
    const int pl   = q >> 1;
    const int sub  = q & 1;
    const uint32_t rxor = (uint32_t)(lrow & 7);
    int garow = crow + lrow; if (garow > M - 1) garow = M - 1;
    const bf16* baseA = (pl ? Al : Ah) + (size_t)garow * K;
    const bf16* baseB = (pl ? Bl : Bh) + (size_t)(ccol + lrow) * K;
    const uint32_t dAr = (uint32_t)lrow * 128u;
    const uint32_t dBr = 16384u + (uint32_t)lrow * 128u;
    const uint32_t cc0 = (uint32_t)(sub * 2);

    const int wm = wid & 3, wn = wid >> 2;
    const uint32_t aoff = (uint32_t)(wm * 32 + (lane & 15)) * 128u;
    const uint32_t boff = 16384u + (uint32_t)(wn * 32 + (lane & 15)) * 128u;
    const uint32_t sel  = (uint32_t)(lane >> 4);
    const uint32_t axor = (uint32_t)(lane & 7);

    float acc[2][4][4];
#pragma unroll
    for (int i = 0; i < 2; i++)
#pragma unroll
        for (int j = 0; j < 4; j++)
#pragma unroll
            for (int e = 0; e < 4; e++) acc[i][j][e] = 0.f;

    auto issue = [&](int kb) {
        if (kb < NK) {
            const bf16* sA = baseA + kb * 32;
            const bf16* sB = baseB + kb * 32;
            const uint32_t st = sb + (uint32_t)(kb & 3) * STAGE_B;
#pragma unroll
            for (int u = 0; u < 2; u++) {
                const uint32_t cc = cc0 + u;
                const uint32_t off = (((uint32_t)(pl * 4) + cc) ^ rxor) << 4;
                CP_ASYNC16(st + dAr + off, sA + cc * 8);
                CP_ASYNC16(st + dBr + off, sB + cc * 8);
            }
        }
        CP_COMMIT();
    };

    issue(0); issue(1); issue(2); issue(3);

    for (int kb = 0; kb < NK; kb++) {
        CP_WAIT3();
        __syncthreads();
        const uint32_t st = sb + (uint32_t)(kb & 3) * STAGE_B;
#pragma unroll
        for (int ks = 0; ks < 2; ks++) {
            const uint32_t chh = (((uint32_t)(ks * 2) + sel) ^ axor) << 4;
            const uint32_t chl = (((uint32_t)(4 + ks * 2) + sel) ^ axor) << 4;
            uint32_t bh[4][2], bl[4][2];
#pragma unroll
            for (int jj = 0; jj < 2; jj++) {
                uint32_t t4[4];
                LDSM_X4(t4, st + boff + (uint32_t)jj * (16u * 128u) + chh);
                bh[2 * jj][0] = t4[0]; bh[2 * jj][1] = t4[2];
                bh[2 * jj + 1][0] = t4[1]; bh[2 * jj + 1][1] = t4[3];
                LDSM_X4(t4, st + boff + (uint32_t)jj * (16u * 128u) + chl);
                bl[2 * jj][0] = t4[0]; bl[2 * jj][1] = t4[2];
                bl[2 * jj + 1][0] = t4[1]; bl[2 * jj + 1][1] = t4[3];
            }
#pragma unroll
            for (int i = 0; i < 2; i++) {
                const uint32_t ra = st + aoff + (uint32_t)i * (16u * 128u);
                uint32_t ah[4], al[4];
                LDSM_X4(ah, ra + chh);
                LDSM_X4(al, ra + chl);
#pragma unroll
                for (int j = 0; j < 4; j++) {
                    MMA16816(acc[i][j], ah, bh[j]);
                    MMA16816(acc[i][j], ah, bl[j]);
                    MMA16816(acc[i][j], al, bh[j]);
                }
            }
        }
        __syncthreads();
        issue(kb + 4);
    }

#pragma unroll
    for (int i = 0; i < 2; i++) {
        const int rb_ = crow + wm * 32 + i * 16 + (lane >> 2);
#pragma unroll
        for (int h = 0; h < 2; h++) {
            const int r = rb_ + h * 8;
            if (r >= M) continue;
            const size_t ro = (size_t)r * N;
#pragma unroll
            for (int j = 0; j < 4; j++) {
                const int c = ccol + wn * 32 + j * 8 + (lane & 3) * 2;
                float v0 = acc[i][j][2 * h]     + bias[c];
                float v1 = acc[i][j][2 * h + 1] + bias[c + 1];
                if (RELU) { v0 = fmaxf(v0, 0.f); v1 = fmaxf(v1, 0.f); }
                if (RESID) { v0 += resid[ro + c]; v1 += resid[ro + c + 1]; }
                if (SPLIT) {
                    uint32_t hp = bf16x2_of(v0, v1);
                    uint32_t lp = split_lo(v0, v1, hp);
                    *reinterpret_cast<uint32_t*>(&Ch[ro + c]) = hp;
                    *reinterpret_cast<uint32_t*>(&Cl[ro + c]) = lp;
                } else {
                    *reinterpret_cast<float2*>(&Cf[ro + c]) = make_float2(v0, v1);
                }
            }
        }
    }
}

// ================= wide GEMM (BN=256): 16 warps, warp tile 32x64, BK=64, 2 stages =================
// row = 256B (hi 128B | lo 128B). stage: A 128x256B (32KB) + B 256x256B (64KB) = 96KB; x2 = 192KB.
// M must be a multiple of 128 (all call sites satisfy this).
#define WSTAGE 98304u
#define WGEMM_SMEM (2u * WSTAGE)

template<bool SPLIT, bool RELU, bool RESID>
__global__ void __launch_bounds__(512, 1) gemm_wide(
    const bf16* __restrict__ Ah, const bf16* __restrict__ Al,
    const bf16* __restrict__ Bh, const bf16* __restrict__ Bl,
    const float* __restrict__ bias, const float* __restrict__ resid,
    float* __restrict__ Cf, bf16* __restrict__ Ch, bf16* __restrict__ Cl,
    int M, int N, int K)
{
    extern __shared__ char smem[];
    const uint32_t sb = smem_u32(smem);
    const int tid = threadIdx.x, lane = tid & 31, wid = tid >> 5;
    const int crow = blockIdx.y * 128, ccol = blockIdx.x * 256;
    const int NK = K >> 6;

    // ---- loader: row0 = tid>>4 (0..31), fixed chunk c = tid&15 per thread ----
    const int row0 = tid >> 4;
    const int c    = tid & 15;
    const int pl   = c >> 3;                 // 0 = hi half, 1 = lo half
    const uint32_t swz = ((uint32_t)(((c & 7) ^ (row0 & 7)) << 4)) | ((uint32_t)(c & 8) << 4);
    const bf16* srcA = (pl ? Al : Ah) + (size_t)(crow + row0) * K + (c & 7) * 8;
    const bf16* srcB = (pl ? Bl : Bh) + (size_t)(ccol + row0) * K + (c & 7) * 8;
    const uint32_t dA0 = (uint32_t)row0 * 256u + swz;
    const uint32_t dB0 = 32768u + (uint32_t)row0 * 256u + swz;
    const size_t rstep = (size_t)32 * K;     // 32 rows per step

    auto issue = [&](int kb) {
        if (kb < NK) {
            const uint32_t st = sb + (uint32_t)(kb & 1) * WSTAGE;
            const int ko = kb * 64;
#pragma unroll
            for (int i = 0; i < 4; i++)
                CP_ASYNC16(st + dA0 + (uint32_t)i * 8192u, srcA + (size_t)i * rstep + ko);
#pragma unroll
            for (int i = 0; i < 8; i++)
                CP_ASYNC16(st + dB0 + (uint32_t)i * 8192u, srcB + (size_t)i * rstep + ko);
        }
        CP_COMMIT();
    };

    const int wm = wid & 3, wn = wid >> 2;
    const uint32_t aoff = (uint32_t)(wm * 32 + (lane & 15)) * 256u;
    const uint32_t boff = 32768u + (uint32_t)(wn * 64 + (lane & 15)) * 256u;
    const uint32_t sel  = (uint32_t)(lane >> 4);
    const uint32_t axor = (uint32_t)(lane & 7);

    float acc[2][8][4];
#pragma unroll
    for (int i = 0; i < 2; i++)
#pragma unroll
        for (int j = 0; j < 8; j++)
#pragma unroll
            for (int e = 0; e < 4; e++) acc[i][j][e] = 0.f;

    issue(0); issue(1);

    for (int kb = 0; kb < NK; kb++) {
        CP_WAIT1();
        __syncthreads();
        const uint32_t st = sb + (uint32_t)(kb & 1) * WSTAGE;
#pragma unroll
        for (int ks = 0; ks < 4; ks++) {
            const uint32_t chh = (((uint32_t)(ks * 2) + sel) ^ axor) << 4;   // hi half: 0..127
            const uint32_t chl = chh + 128u;                                  // lo half: +128B
            uint32_t ah[2][4], al[2][4];
#pragma unroll
            for (int i = 0; i < 2; i++) {
                const uint32_t ra = st + aoff + (uint32_t)i * (16u * 256u);
                LDSM_X4(ah[i], ra + chh);
                LDSM_X4(al[i], ra + chl);
            }
#pragma unroll
            for (int jj = 0; jj < 4; jj++) {
                const uint32_t rb = st + boff + (uint32_t)jj * (16u * 256u);
                uint32_t th[4], tl[4];
                LDSM_X4(th, rb + chh);
                LDSM_X4(tl, rb + chl);
                uint32_t b0h[2] = {th[0], th[2]}, b1h[2] = {th[1], th[3]};
                uint32_t b0l[2] = {tl[0], tl[2]}, b1l[2] = {tl[1], tl[3]};
#pragma unroll
                for (int i = 0; i < 2; i++) {
                    MMA16816(acc[i][2 * jj],     ah[i], b0h);
                    MMA16816(acc[i][2 * jj],     ah[i], b0l);
                    MMA16816(acc[i][2 * jj],     al[i], b0h);
                    MMA16816(acc[i][2 * jj + 1], ah[i], b1h);
                    MMA16816(acc[i][2 * jj + 1], ah[i], b1l);
                    MMA16816(acc[i][2 * jj + 1], al[i], b1h);
                }
            }
        }
        __syncthreads();
        issue(kb + 2);
    }

    // ---- epilogue ----
#pragma unroll
    for (int i = 0; i < 2; i++) {
        const int rb_ = crow + wm * 32 + i * 16 + (lane >> 2);
#pragma unroll
        for (int h = 0; h < 2; h++) {
            const int r = rb_ + h * 8;
            const size_t ro = (size_t)r * N;
#pragma unroll
            for (int j = 0; j < 8; j++) {
                const int c2 = ccol + wn * 64 + j * 8 + (lane & 3) * 2;
                float v0 = acc[i][j][2 * h]     + bias[c2];
                float v1 = acc[i][j][2 * h + 1] + bias[c2 + 1];
                if (RELU) { v0 = fmaxf(v0, 0.f); v1 = fmaxf(v1, 0.f); }
                if (RESID) { v0 += resid[ro + c2]; v1 += resid[ro + c2 + 1]; }
                if (SPLIT) {
                    uint32_t hp = bf16x2_of(v0, v1);
                    uint32_t lp = split_lo(v0, v1, hp);
                    *reinterpret_cast<uint32_t*>(&Ch[ro + c2]) = hp;
                    *reinterpret_cast<uint32_t*>(&Cl[ro + c2]) = lp;
                } else {
                    *reinterpret_cast<float2*>(&Cf[ro + c2]) = make_float2(v0, v1);
                }
            }
        }
    }
}

// ================= MMA attention: softsign(QK^T/8) @ V, all split-bf16 =================
#define ATT_SMEM (96 * 1024)

__global__ void __launch_bounds__(256, 1) attention_mma(
    const bf16* __restrict__ QKVh, const bf16* __restrict__ QKVl,
    bf16* __restrict__ Oh, bf16* __restrict__ Ol)
{
    extern __shared__ char smem[];
    const uint32_t sb = smem_u32(smem);
    const int tid = threadIdx.x, lane = tid & 31, wid = tid >> 5;
    const int qt = blockIdx.x;
    const int h  = blockIdx.y;
    const int b  = blockIdx.z;
    const uint32_t QS = sb + 65536u;

    {
        const bf16* src = ((tid & 1) ? QKVl : QKVh);
        const int row = tid >> 1;
        const bf16* s = src + (size_t)(b * SEQ + qt * 128 + row) * QKV3 + h * HDIM;
        const uint32_t d = QS + (uint32_t)(tid & 1) * 16384u + (uint32_t)row * 128u;
        const uint32_t rx = (uint32_t)(row & 7);
#pragma unroll
        for (int c = 0; c < 8; c++)
            CP_ASYNC16(d + (((uint32_t)c ^ rx) << 4), s + c * 8);
    }

    auto issueKV = [&](int jt) {
        if (jt < 16) {
            const int mat = tid & 1;
            const int pl  = (tid >> 1) & 1;
            const int row = tid >> 2;
            const bf16* src = (pl ? QKVl : QKVh);
            const bf16* s = src + (size_t)(b * SEQ + jt * 64 + row) * QKV3
                          + 1024 + mat * 1024 + h * HDIM;
            const uint32_t d = sb + (uint32_t)(jt & 1) * 32768u + (uint32_t)mat * 16384u
                             + (uint32_t)pl * 8192u + (uint32_t)row * 128u;
            const uint32_t rx = (uint32_t)(row & 7);
#pragma unroll
            for (int c = 0; c < 8; c++)
                CP_ASYNC16(d + (((uint32_t)c ^ rx) << 4), s + c * 8);
        }
        CP_COMMIT();
    };

    issueKV(0);
    issueKV(1);

    CP_WAIT1();
    __syncthreads();

    const uint32_t sel = (uint32_t)(lane >> 4);
    uint32_t qh[4][4], ql[4][4];
    {
        const uint32_t arow = (uint32_t)(wid * 16 + (lane & 15));
        const uint32_t swz = arow & 7u;
        const uint32_t ra = QS + arow * 128u;
#pragma unroll
        for (int kt = 0; kt < 4; kt++) {
            const uint32_t ch = (((uint32_t)(2 * kt) + sel) ^ swz) << 4;
            LDSM_X4(qh[kt], ra + ch);
            LDSM_X4(ql[kt], ra + 16384u + ch);
        }
    }

    float o[8][4];
#pragma unroll
    for (int j = 0; j < 8; j++)
#pragma unroll
        for (int e = 0; e < 4; e++) o[j][e] = 0.f;

    for (int jt = 0; jt < 16; jt++) {
        const uint32_t ST = sb + (uint32_t)(jt & 1) * 32768u;

        float s[8][4];
#pragma unroll
        for (int j = 0; j < 8; j++)
#pragma unroll
            for (int e = 0; e < 4; e++) s[j][e] = 0.f;

        const uint32_t brow = (uint32_t)(lane & 15);
#pragma unroll
        for (int kt = 0; kt < 4; kt++) {
#pragma unroll
            for (int ng = 0; ng < 4; ng++) {
                const uint32_t r = (uint32_t)(ng * 16) + brow;
                const uint32_t ch = (((uint32_t)(2 * kt) + sel) ^ (r & 7u)) << 4;
                const uint32_t addr = ST + r * 128u + ch;
                uint32_t kh[4], kl[4];
                LDSM_X4(kh, addr);
                LDSM_X4(kl, addr + 8192u);
                uint32_t bh0[2] = {kh[0], kh[2]}, bh1[2] = {kh[1], kh[3]};
                uint32_t bl0[2] = {kl[0], kl[2]}, bl1[2] = {kl[1], kl[3]};
                MMA16816(s[2 * ng],     qh[kt], bh0);
                MMA16816(s[2 * ng],     qh[kt], bl0);
                MMA16816(s[2 * ng],     ql[kt], bh0);
                MMA16816(s[2 * ng + 1], qh[kt], bh1);
                MMA16816(s[2 * ng + 1], qh[kt], bl1);
                MMA16816(s[2 * ng + 1], ql[kt], bh1);
            }
        }

#pragma unroll
        for (int j = 0; j < 8; j++)
#pragma unroll
            for (int e = 0; e < 4; e++) {
                float t = s[j][e] * 0.125f;
                s[j][e] = __fdividef(t, 1.0f + fabsf(t));
            }

        uint32_t phi[4][4], plo[4][4];
#pragma unroll
        for (int kt = 0; kt < 4; kt++) {
            const float* p0 = s[2 * kt];
            const float* p1 = s[2 * kt + 1];
            phi[kt][0] = bf16x2_of(p0[0], p0[1]);
            phi[kt][1] = bf16x2_of(p0[2], p0[3]);
            phi[kt][2] = bf16x2_of(p1[0], p1[1]);
            phi[kt][3] = bf16x2_of(p1[2], p1[3]);
            plo[kt][0] = split_lo(p0[0], p0[1], phi[kt][0]);
            plo[kt][1] = split_lo(p0[2], p0[3], phi[kt][1]);
            plo[kt][2] = split_lo(p1[0], p1[1], phi[kt][2]);
            plo[kt][3] = split_lo(p1[2], p1[3], phi[kt][3]);
        }

#pragma unroll
        for (int dg = 0; dg < 8; dg++) {
#pragma unroll
            for (int jh = 0; jh < 2; jh++) {
                const uint32_t r = (uint32_t)(jh * 32 + lane);
                const uint32_t ch = ((uint32_t)dg ^ (r & 7u)) << 4;
                const uint32_t addr = ST + 16384u + r * 128u + ch;
                uint32_t vh[4], vl[4];
                LDSM_X4T(vh, addr);
                LDSM_X4T(vl, addr + 8192u);
                uint32_t bh0[2] = {vh[0], vh[1]}, bh1[2] = {vh[2], vh[3]};
                uint32_t bl0[2] = {vl[0], vl[1]}, bl1[2] = {vl[2], vl[3]};
                const int k0 = 2 * jh, k1 = 2 * jh + 1;
                MMA16816(o[dg], phi[k0], bh0);
                MMA16816(o[dg], phi[k0], bl0);
                MMA16816(o[dg], plo[k0], bh0);
                MMA16816(o[dg], phi[k1], bh1);
                MMA16816(o[dg], phi[k1], bl1);
                MMA16816(o[dg], plo[k1], bh1);
            }
        }

        __syncthreads();
        issueKV(jt + 2);
        if (jt + 1 < 16) { CP_WAIT1(); __syncthreads(); }
    }

    const int grow = b * SEQ + qt * 128 + wid * 16 + (lane >> 2);
    const int cbase = h * HDIM + (lane & 3) * 2;
#pragma unroll
    for (int dg = 0; dg < 8; dg++) {
        const int col = cbase + dg * 8;
        uint32_t hp0 = bf16x2_of(o[dg][0], o[dg][1]);
        uint32_t lp0 = split_lo(o[dg][0], o[dg][1], hp0);
        size_t off0 = (size_t)grow * D_MODEL + col;
        *reinterpret_cast<uint32_t*>(&Oh[off0]) = hp0;
        *reinterpret_cast<uint32_t*>(&Ol[off0]) = lp0;
        uint32_t hp1 = bf16x2_of(o[dg][2], o[dg][3]);
        uint32_t lp1 = split_lo(o[dg][2], o[dg][3], hp1);
        size_t off1 = off0 + (size_t)8 * D_MODEL;
        *reinterpret_cast<uint32_t*>(&Oh[off1]) = hp1;
        *reinterpret_cast<uint32_t*>(&Ol[off1]) = lp1;
    }
}

// ================= weight preparation =================
__global__ void wsplit4(const float* __restrict__ src, bf16* __restrict__ h,
                        bf16* __restrict__ l, int n4)
{
    int i = blockIdx.x * 256 + threadIdx.x;
    if (i >= n4) return;
    float4 v = reinterpret_cast<const float4*>(src)[i];
    uint32_t h0 = bf16x2_of(v.x, v.y), h1 = bf16x2_of(v.z, v.w);
    uint32_t l0 = split_lo(v.x, v.y, h0), l1 = split_lo(v.z, v.w, h1);
    reinterpret_cast<uint2*>(h)[i] = make_uint2(h0, h1);
    reinterpret_cast<uint2*>(l)[i] = make_uint2(l0, l1);
}

__global__ void qkv_pack(const float* __restrict__ q, const float* __restrict__ k,
                         const float* __restrict__ v, bf16* __restrict__ h, bf16* __restrict__ l)
{
    int i = blockIdx.x * 256 + threadIdx.x;
    if (i >= NLAYER * QKV3 * 256) return;
    int e = i * 4;
    int lay = e / (QKV3 * 1024);
    int rem = e - lay * (QKV3 * 1024);
    int n = rem >> 10, kk = rem & 1023;
    const float* src = (n < 1024) ? q : (n < 2048) ? k : v;
    float4 val = *reinterpret_cast<const float4*>(
        src + (size_t)lay * 1048576 + (size_t)(n & 1023) * 1024 + kk);
    uint32_t h0 = bf16x2_of(val.x, val.y), h1 = bf16x2_of(val.z, val.w);
    uint32_t l0 = split_lo(val.x, val.y, h0), l1 = split_lo(val.z, val.w, h1);
    reinterpret_cast<uint2*>(h)[i] = make_uint2(h0, h1);
    reinterpret_cast<uint2*>(l)[i] = make_uint2(l0, l1);
}

__global__ void qkvb_pack(const float* __restrict__ q, const float* __restrict__ k,
                          const float* __restrict__ v, float* __restrict__ out)
{
    int i = blockIdx.x * 256 + threadIdx.x;
    if (i >= NLAYER * QKV3) return;
    int lay = i / QKV3, n = i % QKV3;
    const float* src = (n < 1024) ? q : (n < 2048) ? k : v;
    out[i] = src[lay * 1024 + (n & 1023)];
}

__global__ void conv_repack(const float* __restrict__ w, bf16* __restrict__ h,
                            bf16* __restrict__ l, int OC, int IC)
{
    int K = IC * 3;
    int idx = blockIdx.x * 256 + threadIdx.x;
    if (idx >= OC * K) return;
    int c = idx / K, r = idx % K;
    int kk = r / IC, ic = r % IC;
    float v = w[(size_t)c * K + ic * 3 + kk];
    bf16 hv = __float2bfloat16_rn(v);
    h[idx] = hv;
    l[idx] = __float2bfloat16_rn(v - __bfloat162float(hv));
}

// ================= im2col (split outputs) =================
__global__ void im2col1s(const float* __restrict__ x, bf16* __restrict__ oh, bf16* __restrict__ ol)
{
    const int C4 = 192 / 4;
    int idx = blockIdx.x * 256 + threadIdx.x;
    if (idx >= BATCH * S1 * C4) return;
    int m = idx / C4, c4 = (idx % C4) * 4;
    int b = m / S1, s = m % S1;
    int kk = c4 / D_IN, ic = c4 % D_IN;
    float4 v = *reinterpret_cast<const float4*>(&x[((size_t)(b * S_IN + s + kk)) * D_IN + ic]);
    uint32_t h0 = bf16x2_of(v.x, v.y), h1 = bf16x2_of(v.z, v.w);
    uint32_t l0 = split_lo(v.x, v.y, h0), l1 = split_lo(v.z, v.w, h1);
    *reinterpret_cast<uint2*>(&oh[(size_t)m * 192 + c4]) = make_uint2(h0, h1);
    *reinterpret_cast<uint2*>(&ol[(size_t)m * 192 + c4]) = make_uint2(l0, l1);
}

__global__ void im2col2s(const bf16* __restrict__ ih, const bf16* __restrict__ il,
                         bf16* __restrict__ oh, bf16* __restrict__ ol)
{
    const int C8 = 1536 / 8;
    int idx = blockIdx.x * 256 + threadIdx.x;
    if (idx >= BATCH * SEQ * C8) return;
    int m = idx / C8, c8 = (idx % C8) * 8;
    int b = m / SEQ, s = m % SEQ;
    int kk = c8 / DH, ic = c8 % DH;
    size_t si = ((size_t)(b * S1 + s + kk)) * DH + ic;
    size_t di = (size_t)m * 1536 + c8;
    *reinterpret_cast<uint4*>(&oh[di]) = *reinterpret_cast<const uint4*>(&ih[si]);
    *reinterpret_cast<uint4*>(&ol[di]) = *reinterpret_cast<const uint4*>(&il[si]);
}

// ---------------- positional encoding add ----------------
__global__ void pos_add_kernel(float* __restrict__ h)
{
    int idx = blockIdx.x * 256 + threadIdx.x;
    if (idx >= BATCH * SEQ * D_MODEL) return;
    int d = idx & (D_MODEL - 1);
    int s = (idx >> 10) & (SEQ - 1);
    int i2 = d & ~1;
    float freq = expf((float)i2 * (-9.210340371976184f / 1024.0f));
    float ang  = (float)s * freq;
    double angd = (double)ang;
    double kq = rint(angd * 0.15915494309189535);
    float r = (float)(angd - kq * 6.283185307179586);
    float pe = (d & 1) ? cosf(r) : sinf(r);
    h[idx] += pe;
}

// ---------------- LayerNorm (torch-style) -> split bf16 output ----------------
__global__ void __launch_bounds__(256) layernorm_kernel(
    const float* __restrict__ x, const float* __restrict__ w,
    const float* __restrict__ b, bf16* __restrict__ yh, bf16* __restrict__ yl)
{
    __shared__ float red[8];
    __shared__ float sh_mean, sh_inv;
    const int row = blockIdx.x;
    const int t = threadIdx.x;
    const float* xr = x + (size_t)row * D_MODEL;
    float4 v = *reinterpret_cast<const float4*>(&xr[t * 4]);

    float s = v.x + v.y + v.z + v.w;
#pragma unroll
    for (int o = 16; o > 0; o >>= 1) s += __shfl_xor_sync(0xffffffffu, s, o);
    if ((t & 31) == 0) red[t >> 5] = s;
    __syncthreads();
    if (t == 0) {
        float tot = 0.f;
#pragma unroll
        for (int i = 0; i < 8; i++) tot += red[i];
        sh_mean = tot * (1.0f / 1024.0f);
    }
    __syncthreads();
    float mean = sh_mean;
    float d0 = v.x - mean, d1 = v.y - mean, d2 = v.z - mean, d3 = v.w - mean;
    float sq = d0 * d0 + d1 * d1 + d2 * d2 + d3 * d3;
#pragma unroll
    for (int o = 16; o > 0; o >>= 1) sq += __shfl_xor_sync(0xffffffffu, sq, o);
    if ((t & 31) == 0) red[t >> 5] = sq;
    __syncthreads();
    if (t == 0) {
        float tot = 0.f;
#pragma unroll
        for (int i = 0; i < 8; i++) tot += red[i];
        float var = tot * (1.0f / 1023.0f);
        sh_inv = 1.0f / (sqrtf(var) + EPSF);
    }
    __syncthreads();
    float inv = sh_inv;
    float4 w4 = *reinterpret_cast<const float4*>(&w[t * 4]);
    float4 b4 = *reinterpret_cast<const float4*>(&b[t * 4]);
    float o0 = w4.x * d0 * inv + b4.x;
    float o1 = w4.y * d1 * inv + b4.y;
    float o2 = w4.z * d2 * inv + b4.z;
    float o3 = w4.w * d3 * inv + b4.w;
    uint32_t h01 = bf16x2_of(o0, o1), h23 = bf16x2_of(o2, o3);
    uint32_t l01 = split_lo(o0, o1, h01), l23 = split_lo(o2, o3, h23);
    size_t off = (size_t)row * D_MODEL + t * 4;
    *reinterpret_cast<uint2*>(&yh[off]) = make_uint2(h01, h23);
    *reinterpret_cast<uint2*>(&yl[off]) = make_uint2(l01, l23);
}

// ---------------- mean pool + final fc ----------------
__global__ void pool_kernel(const float* __restrict__ h, float* __restrict__ out)
{
    int idx = blockIdx.x * 256 + threadIdx.x;
    if (idx >= BATCH * D_MODEL) return;
    int b = idx >> 10, d = idx & (D_MODEL - 1);
    const float* p = h + (size_t)(b * SEQ) * D_MODEL + d;
    float a[8];
#pragma unroll
    for (int i = 0; i < 8; i++) a[i] = 0.f;
    for (int i = 0; i < SEQ; i += 8) {
#pragma unroll
        for (int u = 0; u < 8; u++) a[u] += p[(size_t)(i + u) * D_MODEL];
    }
    float s = ((a[0] + a[1]) + (a[2] + a[3])) + ((a[4] + a[5]) + (a[6] + a[7]));
    out[idx] = s * (1.0f / 1024.0f);
}

__global__ void fc_kernel(const float* __restrict__ pool, const float* __restrict__ fcw,
                          const float* __restrict__ fcb, float* __restrict__ out)
{
    __shared__ float red[8];
    int b = blockIdx.x, t = threadIdx.x;
    float4 p  = *reinterpret_cast<const float4*>(&pool[b * D_MODEL + t * 4]);
    float4 w4 = *reinterpret_cast<const float4*>(&fcw[t * 4]);
    float s = p.x * w4.x + p.y * w4.y + p.z * w4.z + p.w * w4.w;
#pragma unroll
    for (int o = 16; o > 0; o >>= 1) s += __shfl_xor_sync(0xffffffffu, s, o);
    if ((t & 31) == 0) red[t >> 5] = s;
    __syncthreads();
    if (t == 0) {
        float tot = 0.f;
#pragma unroll
        for (int i = 0; i < 8; i++) tot += red[i];
        out[b] = tot + fcb[0];
    }
}

// ---------------- host orchestration ----------------
#define SYM(p, s) cudaGetSymbolAddress((void**)&p, s)

extern "C" void kernel_launch(void* const* d_in, const int* in_sizes, int n_in,
                              void* d_out, int out_size)
{
    (void)in_sizes; (void)n_in; (void)out_size;
    const float* x       = (const float*)d_in[0];
    const float* conv1_w = (const float*)d_in[1];
    const float* conv1_b = (const float*)d_in[2];
    const float* conv2_w = (const float*)d_in[3];
    const float* conv2_b = (const float*)d_in[4];
    const float* lnA_w   = (const float*)d_in[5];
    const float* lnA_b   = (const float*)d_in[6];
    const float* q_w     = (const float*)d_in[7];
    const float* q_b     = (const float*)d_in[8];
    const float* k_w     = (const float*)d_in[9];
    const float* k_b     = (const float*)d_in[10];
    const float* v_w     = (const float*)d_in[11];
    const float* v_b     = (const float*)d_in[12];
    const float* o_w     = (const float*)d_in[13];
    const float* o_b     = (const float*)d_in[14];
    const float* lnB_w   = (const float*)d_in[15];
    const float* lnB_b   = (const float*)d_in[16];
    const float* f1_w    = (const float*)d_in[17];
    const float* f1_b    = (const float*)d_in[18];
    const float* f2_w    = (const float*)d_in[19];
    const float* f2_b    = (const float*)d_in[20];
    const float* fc_w    = (const float*)d_in[21];
    const float* fc_b    = (const float*)d_in[22];
    float* out = (float*)d_out;

    float *p_h, *p_qkvb, *p_pool;
    bf16 *p_gah, *p_gal, *p_gbh, *p_gbl, *p_qvh, *p_qvl;
    bf16 *p_qkvh, *p_qkvl, *p_oh, *p_ol, *p_f1h, *p_f1l, *p_f2h, *p_f2l;
    bf16 *p_c1h, *p_c1l, *p_c2h, *p_c2l;
    SYM(p_h, g_h); SYM(p_qkvb, g_qkvb); SYM(p_pool, g_pool);
    SYM(p_gah, ga_h); SYM(p_gal, ga_l); SYM(p_gbh, gb_h); SYM(p_gbl, gb_l);
    SYM(p_qvh, g_qkvh); SYM(p_qvl, g_qkvl);
    SYM(p_qkvh, bw_qkv_h); SYM(p_qkvl, bw_qkv_l);
    SYM(p_oh, bw_o_h); SYM(p_ol, bw_o_l);
    SYM(p_f1h, bw_f1_h); SYM(p_f1l, bw_f1_l);
    SYM(p_f2h, bw_f2_h); SYM(p_f2l, bw_f2_l);
    SYM(p_c1h, bw_c1_h); SYM(p_c1l, bw_c1_l);
    SYM(p_c2h, bw_c2_h); SYM(p_c2l, bw_c2_l);

    cudaFuncSetAttribute(attention_mma, cudaFuncAttributeMaxDynamicSharedMemorySize, ATT_SMEM);
    cudaFuncSetAttribute(gemm_bf5<true, false, false>, cudaFuncAttributeMaxDynamicSharedMemorySize, GEMM_SMEM);
    cudaFuncSetAttribute(gemm_wide<false, false, false>, cudaFuncAttributeMaxDynamicSharedMemorySize, WGEMM_SMEM);
    cudaFuncSetAttribute(gemm_wide<false, false, true>,  cudaFuncAttributeMaxDynamicSharedMemorySize, WGEMM_SMEM);
    cudaFuncSetAttribute(gemm_wide<true, false, false>,  cudaFuncAttributeMaxDynamicSharedMemorySize, WGEMM_SMEM);
    cudaFuncSetAttribute(gemm_wide<true, true, false>,   cudaFuncAttributeMaxDynamicSharedMemorySize, WGEMM_SMEM);

    // ---- weight prep (split to bf16 hi/lo) ----
    qkv_pack<<<(NLAYER * QKV3 * 256 + 255) / 256, 256>>>(q_w, k_w, v_w, p_qkvh, p_qkvl);
    qkvb_pack<<<(NLAYER * QKV3 + 255) / 256, 256>>>(q_b, k_b, v_b, p_qkvb);
    wsplit4<<<(NLAYER * 1024 * 256 + 255) / 256, 256>>>(o_w, p_oh, p_ol, NLAYER * 1024 * 256);
    wsplit4<<<(NLAYER * 2048 * 256 + 255) / 256, 256>>>(f1_w, p_f1h, p_f1l, NLAYER * 2048 * 256);
    wsplit4<<<(NLAYER * 2048 * 256 + 255) / 256, 256>>>(f2_w, p_f2h, p_f2l, NLAYER * 2048 * 256);
    conv_repack<<<(512 * 192 + 255) / 256, 256>>>(conv1_w, p_c1h, p_c1l, 512, D_IN);
    conv_repack<<<(1024 * 1536 + 255) / 256, 256>>>(conv2_w, p_c2h, p_c2l, 1024, DH);

    // ---- conv frontend ----
    im2col1s<<<(BATCH * S1 * 48 + 255) / 256, 256>>>(x, p_gah, p_gal);
    gemm_bf5<true, false, false><<<dim3(4, 33), 512, GEMM_SMEM>>>(
        p_gah, p_gal, p_c1h, p_c1l, conv1_b, nullptr, nullptr, p_gbh, p_gbl,
        BATCH * S1, DH, 192);
    im2col2s<<<(BATCH * SEQ * 192 + 255) / 256, 256>>>(p_gbh, p_gbl, p_gah, p_gal);
    gemm_wide<false, false, false><<<dim3(4, 32), 512, WGEMM_SMEM>>>(
        p_gah, p_gal, p_c2h, p_c2l, conv2_b, nullptr, p_h, nullptr, nullptr,
        BATCH * SEQ, D_MODEL, 1536);
    pos_add_kernel<<<(BATCH * SEQ * D_MODEL) / 256, 256>>>(p_h);

    const int M = BATCH * SEQ;  // 4096

    for (int l = 0; l < NLAYER; l++) {
        size_t qkvo = (size_t)l * QKV3 * 1024;
        size_t oo   = (size_t)l * 1024 * 1024;
        size_t f1o  = (size_t)l * 2048 * 1024;
        size_t f2o  = (size_t)l * 1024 * 2048;
        size_t bo   = (size_t)l * D_MODEL;

        layernorm_kernel<<<M, 256>>>(p_h, lnA_w + bo, lnA_b + bo, p_gah, p_gal);
        gemm_wide<true, false, false><<<dim3(QKV3 / 256, 32), 512, WGEMM_SMEM>>>(
            p_gah, p_gal, p_qkvh + qkvo, p_qkvl + qkvo, p_qkvb + (size_t)l * QKV3,
            nullptr, nullptr, p_qvh, p_qvl, M, QKV3, 1024);

        attention_mma<<<dim3(SEQ / 128, NHEAD, BATCH), 256, ATT_SMEM>>>(
            p_qvh, p_qvl, p_gah, p_gal);

        gemm_wide<false, false, true><<<dim3(4, 32), 512, WGEMM_SMEM>>>(
            p_gah, p_gal, p_oh + oo, p_ol + oo, o_b + bo, p_h, p_h, nullptr, nullptr,
            M, D_MODEL, 1024);

        layernorm_kernel<<<M, 256>>>(p_h, lnB_w + bo, lnB_b + bo, p_gah, p_gal);
        gemm_wide<true, true, false><<<dim3(FFDIM / 256, 32), 512, WGEMM_SMEM>>>(
            p_gah, p_gal, p_f1h + f1o, p_f1l + f1o, f1_b + (size_t)l * FFDIM,
            nullptr, nullptr, p_gbh, p_gbl, M, FFDIM, 1024);
        gemm_wide<false, false, true><<<dim3(4, 32), 512, WGEMM_SMEM>>>(
            p_gbh, p_gbl, p_f2h + f2o, p_f2l + f2o, f2_b + bo, p_h, p_h, nullptr, nullptr,
            M, D_MODEL, 2048);
    }

    pool_kernel<<<(BATCH * D_MODEL) / 256, 256>>>(p_h, p_pool);
    fc_kernel<<<BATCH, 256>>>(p_pool, fc_w, fc_b, out);
}

// round 13
// speedup vs baseline: 1.1107x; 1.0143x over previous
#include <cuda_runtime.h>
#include <cuda_bf16.h>
#include <math.h>
#include <stdint.h>

// ---------------- problem dims ----------------
#define BATCH   4
#define S_IN    1028
#define D_IN    64
#define S1      1026
#define SEQ     1024
#define DH      512
#define D_MODEL 1024
#define NHEAD   16
#define HDIM    64
#define NLAYER  4
#define FFDIM   2048
#define QKV3    3072
#define EPSF    1e-6f

typedef __nv_bfloat16 bf16;

// ---------------- scratch (device globals; no allocation allowed) ----------------
__device__ float g_h   [BATCH*SEQ*D_MODEL];
__device__ float g_qkvb[NLAYER*QKV3];
__device__ float g_pool[BATCH*D_MODEL];

// split-bf16 activation buffers (hi/lo planes)
__device__ bf16 ga_h[4096*2048], ga_l[4096*2048];
__device__ bf16 gb_h[4096*2048], gb_l[4096*2048];
__device__ bf16 g_qkvh[(size_t)4096*QKV3], g_qkvl[(size_t)4096*QKV3];
// split-bf16 weights
__device__ bf16 bw_qkv_h[NLAYER*QKV3*1024], bw_qkv_l[NLAYER*QKV3*1024];
__device__ bf16 bw_o_h  [NLAYER*1024*1024], bw_o_l  [NLAYER*1024*1024];
__device__ bf16 bw_f1_h [NLAYER*2048*1024], bw_f1_l [NLAYER*2048*1024];
__device__ bf16 bw_f2_h [NLAYER*1024*2048], bw_f2_l [NLAYER*1024*2048];
__device__ bf16 bw_c1_h [512*192],          bw_c1_l [512*192];
__device__ bf16 bw_c2_h [1024*1536],        bw_c2_l [1024*1536];

// ================= helpers =================
__device__ __forceinline__ uint32_t smem_u32(const void* p) {
    uint32_t a;
    asm("{ .reg .u64 t; cvta.to.shared.u64 t, %1; cvt.u32.u64 %0, t; }" : "=r"(a) : "l"(p));
    return a;
}
// pack 2 fp32 -> bf16x2 (first arg -> low 16 bits)
__device__ __forceinline__ uint32_t bf16x2_of(float lo, float hi) {
    uint32_t r;
    asm("cvt.rn.bf16x2.f32 %0, %1, %2;" : "=r"(r) : "f"(hi), "f"(lo));
    return r;
}
__device__ __forceinline__ uint32_t split_lo(float v0, float v1, uint32_t hp) {
    float r0 = v0 - __uint_as_float(hp << 16);
    float r1 = v1 - __uint_as_float(hp & 0xffff0000u);
    return bf16x2_of(r0, r1);
}
#define LDSM_X4(r, addr) \
    asm volatile("ldmatrix.sync.aligned.m8n8.x4.shared.b16 {%0,%1,%2,%3}, [%4];" \
        : "=r"((r)[0]), "=r"((r)[1]), "=r"((r)[2]), "=r"((r)[3]) : "r"(addr))
#define LDSM_X4T(r, addr) \
    asm volatile("ldmatrix.sync.aligned.m8n8.x4.trans.shared.b16 {%0,%1,%2,%3}, [%4];" \
        : "=r"((r)[0]), "=r"((r)[1]), "=r"((r)[2]), "=r"((r)[3]) : "r"(addr))
#define MMA16816(d, a, b) \
    asm volatile("mma.sync.aligned.m16n8k16.row.col.f32.bf16.bf16.f32 " \
        "{%0,%1,%2,%3}, {%4,%5,%6,%7}, {%8,%9}, {%0,%1,%2,%3};" \
        : "+f"((d)[0]), "+f"((d)[1]), "+f"((d)[2]), "+f"((d)[3]) \
        : "r"((a)[0]), "r"((a)[1]), "r"((a)[2]), "r"((a)[3]), "r"((b)[0]), "r"((b)[1]))
#define CP_ASYNC16(dst, src) \
    asm volatile("cp.async.cg.shared.global [%0], [%1], 16;" :: "r"(dst), "l"(src) : "memory")
#define CP_COMMIT()  asm volatile("cp.async.commit_group;" ::: "memory")
#define CP_WAIT3()   asm volatile("cp.async.wait_group 3;" ::: "memory")
#define CP_WAIT1()   asm volatile("cp.async.wait_group 1;" ::: "memory")

// ================= split-bf16 cp.async GEMM (BN=128): kept for conv1 (N=512) =================
#define STAGE_B  32768u
#define GEMM_SMEM (4u * STAGE_B)

template<bool SPLIT, bool RELU, bool RESID>
__global__ void __launch_bounds__(512, 1) gemm_bf5(
    const bf16* __restrict__ Ah, const bf16* __restrict__ Al,
    const bf16* __restrict__ Bh, const bf16* __restrict__ Bl,
    const float* __restrict__ bias, const float* __restrict__ resid,
    float* __restrict__ Cf, bf16* __restrict__ Ch, bf16* __restrict__ Cl,
    int M, int N, int K)
{
    extern __shared__ char smem[];
    const uint32_t sb = smem_u32(smem);
    const int tid = threadIdx.x, lane = tid & 31, wid = tid >> 5;
    const int crow = blockIdx.y * 128, ccol = blockIdx.x * 128;
    const int NK = K >> 5;

    const int lrow = tid >> 2;
    const int q    = tid & 3;
    const int pl   = q >> 1;
    const int sub  = q & 1;
    const uint32_t rxor = (uint32_t)(lrow & 7);
    int garow = crow + lrow; if (garow > M - 1) garow = M - 1;
    const bf16* baseA = (pl ? Al : Ah) + (size_t)garow * K;
    const bf16* baseB = (pl ? Bl : Bh) + (size_t)(ccol + lrow) * K;
    const uint32_t dAr = (uint32_t)lrow * 128u;
    const uint32_t dBr = 16384u + (uint32_t)lrow * 128u;
    const uint32_t cc0 = (uint32_t)(sub * 2);

    const int wm = wid & 3, wn = wid >> 2;
    const uint32_t aoff = (uint32_t)(wm * 32 + (lane & 15)) * 128u;
    const uint32_t boff = 16384u + (uint32_t)(wn * 32 + (lane & 15)) * 128u;
    const uint32_t sel  = (uint32_t)(lane >> 4);
    const uint32_t axor = (uint32_t)(lane & 7);

    float acc[2][4][4];
#pragma unroll
    for (int i = 0; i < 2; i++)
#pragma unroll
        for (int j = 0; j < 4; j++)
#pragma unroll
            for (int e = 0; e < 4; e++) acc[i][j][e] = 0.f;

    auto issue = [&](int kb) {
        if (kb < NK) {
            const bf16* sA = baseA + kb * 32;
            const bf16* sB = baseB + kb * 32;
            const uint32_t st = sb + (uint32_t)(kb & 3) * STAGE_B;
#pragma unroll
            for (int u = 0; u < 2; u++) {
                const uint32_t cc = cc0 + u;
                const uint32_t off = (((uint32_t)(pl * 4) + cc) ^ rxor) << 4;
                CP_ASYNC16(st + dAr + off, sA + cc * 8);
                CP_ASYNC16(st + dBr + off, sB + cc * 8);
            }
        }
        CP_COMMIT();
    };

    issue(0); issue(1); issue(2); issue(3);

    for (int kb = 0; kb < NK; kb++) {
        CP_WAIT3();
        __syncthreads();
        const uint32_t st = sb + (uint32_t)(kb & 3) * STAGE_B;
#pragma unroll
        for (int ks = 0; ks < 2; ks++) {
            const uint32_t chh = (((uint32_t)(ks * 2) + sel) ^ axor) << 4;
            const uint32_t chl = (((uint32_t)(4 + ks * 2) + sel) ^ axor) << 4;
            uint32_t bh[4][2], bl[4][2];
#pragma unroll
            for (int jj = 0; jj < 2; jj++) {
                uint32_t t4[4];
                LDSM_X4(t4, st + boff + (uint32_t)jj * (16u * 128u) + chh);
                bh[2 * jj][0] = t4[0]; bh[2 * jj][1] = t4[2];
                bh[2 * jj + 1][0] = t4[1]; bh[2 * jj + 1][1] = t4[3];
                LDSM_X4(t4, st + boff + (uint32_t)jj * (16u * 128u) + chl);
                bl[2 * jj][0] = t4[0]; bl[2 * jj][1] = t4[2];
                bl[2 * jj + 1][0] = t4[1]; bl[2 * jj + 1][1] = t4[3];
            }
#pragma unroll
            for (int i = 0; i < 2; i++) {
                const uint32_t ra = st + aoff + (uint32_t)i * (16u * 128u);
                uint32_t ah[4], al[4];
                LDSM_X4(ah, ra + chh);
                LDSM_X4(al, ra + chl);
#pragma unroll
                for (int j = 0; j < 4; j++) MMA16816(acc[i][j], ah, bh[j]);
#pragma unroll
                for (int j = 0; j < 4; j++) MMA16816(acc[i][j], ah, bl[j]);
#pragma unroll
                for (int j = 0; j < 4; j++) MMA16816(acc[i][j], al, bh[j]);
            }
        }
        __syncthreads();
        issue(kb + 4);
    }

#pragma unroll
    for (int i = 0; i < 2; i++) {
        const int rb_ = crow + wm * 32 + i * 16 + (lane >> 2);
#pragma unroll
        for (int h = 0; h < 2; h++) {
            const int r = rb_ + h * 8;
            if (r >= M) continue;
            const size_t ro = (size_t)r * N;
#pragma unroll
            for (int j = 0; j < 4; j++) {
                const int c = ccol + wn * 32 + j * 8 + (lane & 3) * 2;
                float v0 = acc[i][j][2 * h]     + bias[c];
                float v1 = acc[i][j][2 * h + 1] + bias[c + 1];
                if (RELU) { v0 = fmaxf(v0, 0.f); v1 = fmaxf(v1, 0.f); }
                if (RESID) { v0 += resid[ro + c]; v1 += resid[ro + c + 1]; }
                if (SPLIT) {
                    uint32_t hp = bf16x2_of(v0, v1);
                    uint32_t lp = split_lo(v0, v1, hp);
                    *reinterpret_cast<uint32_t*>(&Ch[ro + c]) = hp;
                    *reinterpret_cast<uint32_t*>(&Cl[ro + c]) = lp;
                } else {
                    *reinterpret_cast<float2*>(&Cf[ro + c]) = make_float2(v0, v1);
                }
            }
        }
    }
}

// ================= wide GEMM (BN=256): 16 warps, warp tile 32x64, BK=64, 2 stages =================
// row = 256B (hi 128B | lo 128B). stage: A 128x256B (32KB) + B 256x256B (64KB) = 96KB; x2 = 192KB.
// M must be a multiple of 128 (all call sites satisfy this).
#define WSTAGE 98304u
#define WGEMM_SMEM (2u * WSTAGE)

template<bool SPLIT, bool RELU, bool RESID>
__global__ void __launch_bounds__(512, 1) gemm_wide(
    const bf16* __restrict__ Ah, const bf16* __restrict__ Al,
    const bf16* __restrict__ Bh, const bf16* __restrict__ Bl,
    const float* __restrict__ bias, const float* __restrict__ resid,
    float* __restrict__ Cf, bf16* __restrict__ Ch, bf16* __restrict__ Cl,
    int M, int N, int K)
{
    extern __shared__ char smem[];
    const uint32_t sb = smem_u32(smem);
    const int tid = threadIdx.x, lane = tid & 31, wid = tid >> 5;
    const int crow = blockIdx.y * 128, ccol = blockIdx.x * 256;
    const int NK = K >> 6;

    // ---- loader: row0 = tid>>4 (0..31), fixed chunk c = tid&15 per thread ----
    const int row0 = tid >> 4;
    const int c    = tid & 15;
    const int pl   = c >> 3;                 // 0 = hi half, 1 = lo half
    const uint32_t swz = ((uint32_t)(((c & 7) ^ (row0 & 7)) << 4)) | ((uint32_t)(c & 8) << 4);
    const bf16* srcA = (pl ? Al : Ah) + (size_t)(crow + row0) * K + (c & 7) * 8;
    const bf16* srcB = (pl ? Bl : Bh) + (size_t)(ccol + row0) * K + (c & 7) * 8;
    const uint32_t dA0 = (uint32_t)row0 * 256u + swz;
    const uint32_t dB0 = 32768u + (uint32_t)row0 * 256u + swz;
    const size_t rstep = (size_t)32 * K;     // 32 rows per step

    auto issue = [&](int kb) {
        if (kb < NK) {
            const uint32_t st = sb + (uint32_t)(kb & 1) * WSTAGE;
            const int ko = kb * 64;
#pragma unroll
            for (int i = 0; i < 4; i++)
                CP_ASYNC16(st + dA0 + (uint32_t)i * 8192u, srcA + (size_t)i * rstep + ko);
#pragma unroll
            for (int i = 0; i < 8; i++)
                CP_ASYNC16(st + dB0 + (uint32_t)i * 8192u, srcB + (size_t)i * rstep + ko);
        }
        CP_COMMIT();
    };

    const int wm = wid & 3, wn = wid >> 2;
    const uint32_t aoff = (uint32_t)(wm * 32 + (lane & 15)) * 256u;
    const uint32_t boff = 32768u + (uint32_t)(wn * 64 + (lane & 15)) * 256u;
    const uint32_t sel  = (uint32_t)(lane >> 4);
    const uint32_t axor = (uint32_t)(lane & 7);

    float acc[2][8][4];
#pragma unroll
    for (int i = 0; i < 2; i++)
#pragma unroll
        for (int j = 0; j < 8; j++)
#pragma unroll
            for (int e = 0; e < 4; e++) acc[i][j][e] = 0.f;

    issue(0); issue(1);

    for (int kb = 0; kb < NK; kb++) {
        CP_WAIT1();
        __syncthreads();
        const uint32_t st = sb + (uint32_t)(kb & 1) * WSTAGE;
#pragma unroll
        for (int ks = 0; ks < 4; ks++) {
            const uint32_t chh = (((uint32_t)(ks * 2) + sel) ^ axor) << 4;   // hi half: 0..127
            const uint32_t chl = chh + 128u;                                  // lo half: +128B
            uint32_t ah[2][4], al[2][4];
#pragma unroll
            for (int i = 0; i < 2; i++) {
                const uint32_t ra = st + aoff + (uint32_t)i * (16u * 256u);
                LDSM_X4(ah[i], ra + chh);
                LDSM_X4(al[i], ra + chl);
            }
#pragma unroll
            for (int jj = 0; jj < 4; jj++) {
                const uint32_t rb = st + boff + (uint32_t)jj * (16u * 256u);
                uint32_t th[4], tl[4];
                LDSM_X4(th, rb + chh);
                LDSM_X4(tl, rb + chl);
                uint32_t b0h[2] = {th[0], th[2]}, b1h[2] = {th[1], th[3]};
                uint32_t b0l[2] = {tl[0], tl[2]}, b1l[2] = {tl[1], tl[3]};
                // pass 1: Ahi x Bhi  (4 independent accumulators)
                MMA16816(acc[0][2 * jj],     ah[0], b0h);
                MMA16816(acc[1][2 * jj],     ah[1], b0h);
                MMA16816(acc[0][2 * jj + 1], ah[0], b1h);
                MMA16816(acc[1][2 * jj + 1], ah[1], b1h);
                // pass 2: Ahi x Blo
                MMA16816(acc[0][2 * jj],     ah[0], b0l);
                MMA16816(acc[1][2 * jj],     ah[1], b0l);
                MMA16816(acc[0][2 * jj + 1], ah[0], b1l);
                MMA16816(acc[1][2 * jj + 1], ah[1], b1l);
                // pass 3: Alo x Bhi
                MMA16816(acc[0][2 * jj],     al[0], b0h);
                MMA16816(acc[1][2 * jj],     al[1], b0h);
                MMA16816(acc[0][2 * jj + 1], al[0], b1h);
                MMA16816(acc[1][2 * jj + 1], al[1], b1h);
            }
        }
        __syncthreads();
        issue(kb + 2);
    }

    // ---- epilogue ----
#pragma unroll
    for (int i = 0; i < 2; i++) {
        const int rb_ = crow + wm * 32 + i * 16 + (lane >> 2);
#pragma unroll
        for (int h = 0; h < 2; h++) {
            const int r = rb_ + h * 8;
            const size_t ro = (size_t)r * N;
#pragma unroll
            for (int j = 0; j < 8; j++) {
                const int c2 = ccol + wn * 64 + j * 8 + (lane & 3) * 2;
                float v0 = acc[i][j][2 * h]     + bias[c2];
                float v1 = acc[i][j][2 * h + 1] + bias[c2 + 1];
                if (RELU) { v0 = fmaxf(v0, 0.f); v1 = fmaxf(v1, 0.f); }
                if (RESID) { v0 += resid[ro + c2]; v1 += resid[ro + c2 + 1]; }
                if (SPLIT) {
                    uint32_t hp = bf16x2_of(v0, v1);
                    uint32_t lp = split_lo(v0, v1, hp);
                    *reinterpret_cast<uint32_t*>(&Ch[ro + c2]) = hp;
                    *reinterpret_cast<uint32_t*>(&Cl[ro + c2]) = lp;
                } else {
                    *reinterpret_cast<float2*>(&Cf[ro + c2]) = make_float2(v0, v1);
                }
            }
        }
    }
}

// ================= MMA attention: softsign(QK^T/8) @ V, all split-bf16 =================
#define ATT_SMEM (96 * 1024)

__global__ void __launch_bounds__(256, 1) attention_mma(
    const bf16* __restrict__ QKVh, const bf16* __restrict__ QKVl,
    bf16* __restrict__ Oh, bf16* __restrict__ Ol)
{
    extern __shared__ char smem[];
    const uint32_t sb = smem_u32(smem);
    const int tid = threadIdx.x, lane = tid & 31, wid = tid >> 5;
    const int qt = blockIdx.x;
    const int h  = blockIdx.y;
    const int b  = blockIdx.z;
    const uint32_t QS = sb + 65536u;

    {
        const bf16* src = ((tid & 1) ? QKVl : QKVh);
        const int row = tid >> 1;
        const bf16* s = src + (size_t)(b * SEQ + qt * 128 + row) * QKV3 + h * HDIM;
        const uint32_t d = QS + (uint32_t)(tid & 1) * 16384u + (uint32_t)row * 128u;
        const uint32_t rx = (uint32_t)(row & 7);
#pragma unroll
        for (int c = 0; c < 8; c++)
            CP_ASYNC16(d + (((uint32_t)c ^ rx) << 4), s + c * 8);
    }

    auto issueKV = [&](int jt) {
        if (jt < 16) {
            const int mat = tid & 1;
            const int pl  = (tid >> 1) & 1;
            const int row = tid >> 2;
            const bf16* src = (pl ? QKVl : QKVh);
            const bf16* s = src + (size_t)(b * SEQ + jt * 64 + row) * QKV3
                          + 1024 + mat * 1024 + h * HDIM;
            const uint32_t d = sb + (uint32_t)(jt & 1) * 32768u + (uint32_t)mat * 16384u
                             + (uint32_t)pl * 8192u + (uint32_t)row * 128u;
            const uint32_t rx = (uint32_t)(row & 7);
#pragma unroll
            for (int c = 0; c < 8; c++)
                CP_ASYNC16(d + (((uint32_t)c ^ rx) << 4), s + c * 8);
        }
        CP_COMMIT();
    };

    issueKV(0);
    issueKV(1);

    CP_WAIT1();
    __syncthreads();

    const uint32_t sel = (uint32_t)(lane >> 4);
    uint32_t qh[4][4], ql[4][4];
    {
        const uint32_t arow = (uint32_t)(wid * 16 + (lane & 15));
        const uint32_t swz = arow & 7u;
        const uint32_t ra = QS + arow * 128u;
#pragma unroll
        for (int kt = 0; kt < 4; kt++) {
            const uint32_t ch = (((uint32_t)(2 * kt) + sel) ^ swz) << 4;
            LDSM_X4(qh[kt], ra + ch);
            LDSM_X4(ql[kt], ra + 16384u + ch);
        }
    }

    float o[8][4];
#pragma unroll
    for (int j = 0; j < 8; j++)
#pragma unroll
        for (int e = 0; e < 4; e++) o[j][e] = 0.f;

    for (int jt = 0; jt < 16; jt++) {
        const uint32_t ST = sb + (uint32_t)(jt & 1) * 32768u;

        float s[8][4];
#pragma unroll
        for (int j = 0; j < 8; j++)
#pragma unroll
            for (int e = 0; e < 4; e++) s[j][e] = 0.f;

        const uint32_t brow = (uint32_t)(lane & 15);
#pragma unroll
        for (int kt = 0; kt < 4; kt++) {
#pragma unroll
            for (int ng = 0; ng < 4; ng++) {
                const uint32_t r = (uint32_t)(ng * 16) + brow;
                const uint32_t ch = (((uint32_t)(2 * kt) + sel) ^ (r & 7u)) << 4;
                const uint32_t addr = ST + r * 128u + ch;
                uint32_t kh[4], kl[4];
                LDSM_X4(kh, addr);
                LDSM_X4(kl, addr + 8192u);
                uint32_t bh0[2] = {kh[0], kh[2]}, bh1[2] = {kh[1], kh[3]};
                uint32_t bl0[2] = {kl[0], kl[2]}, bl1[2] = {kl[1], kl[3]};
                MMA16816(s[2 * ng],     qh[kt], bh0);
                MMA16816(s[2 * ng + 1], qh[kt], bh1);
                MMA16816(s[2 * ng],     qh[kt], bl0);
                MMA16816(s[2 * ng + 1], qh[kt], bl1);
                MMA16816(s[2 * ng],     ql[kt], bh0);
                MMA16816(s[2 * ng + 1], ql[kt], bh1);
            }
        }

#pragma unroll
        for (int j = 0; j < 8; j++)
#pragma unroll
            for (int e = 0; e < 4; e++) {
                float t = s[j][e] * 0.125f;
                s[j][e] = __fdividef(t, 1.0f + fabsf(t));
            }

        uint32_t phi[4][4], plo[4][4];
#pragma unroll
        for (int kt = 0; kt < 4; kt++) {
            const float* p0 = s[2 * kt];
            const float* p1 = s[2 * kt + 1];
            phi[kt][0] = bf16x2_of(p0[0], p0[1]);
            phi[kt][1] = bf16x2_of(p0[2], p0[3]);
            phi[kt][2] = bf16x2_of(p1[0], p1[1]);
            phi[kt][3] = bf16x2_of(p1[2], p1[3]);
            plo[kt][0] = split_lo(p0[0], p0[1], phi[kt][0]);
            plo[kt][1] = split_lo(p0[2], p0[3], phi[kt][1]);
            plo[kt][2] = split_lo(p1[0], p1[1], phi[kt][2]);
            plo[kt][3] = split_lo(p1[2], p1[3], phi[kt][3]);
        }

#pragma unroll
        for (int dg = 0; dg < 8; dg++) {
#pragma unroll
            for (int jh = 0; jh < 2; jh++) {
                const uint32_t r = (uint32_t)(jh * 32 + lane);
                const uint32_t ch = ((uint32_t)dg ^ (r & 7u)) << 4;
                const uint32_t addr = ST + 16384u + r * 128u + ch;
                uint32_t vh[4], vl[4];
                LDSM_X4T(vh, addr);
                LDSM_X4T(vl, addr + 8192u);
                uint32_t bh0[2] = {vh[0], vh[1]}, bh1[2] = {vh[2], vh[3]};
                uint32_t bl0[2] = {vl[0], vl[1]}, bl1[2] = {vl[2], vl[3]};
                const int k0 = 2 * jh, k1 = 2 * jh + 1;
                MMA16816(o[dg], phi[k0], bh0);
                MMA16816(o[dg], phi[k0], bl0);
                MMA16816(o[dg], plo[k0], bh0);
                MMA16816(o[dg], phi[k1], bh1);
                MMA16816(o[dg], phi[k1], bl1);
                MMA16816(o[dg], plo[k1], bh1);
            }
        }

        __syncthreads();
        issueKV(jt + 2);
        if (jt + 1 < 16) { CP_WAIT1(); __syncthreads(); }
    }

    const int grow = b * SEQ + qt * 128 + wid * 16 + (lane >> 2);
    const int cbase = h * HDIM + (lane & 3) * 2;
#pragma unroll
    for (int dg = 0; dg < 8; dg++) {
        const int col = cbase + dg * 8;
        uint32_t hp0 = bf16x2_of(o[dg][0], o[dg][1]);
        uint32_t lp0 = split_lo(o[dg][0], o[dg][1], hp0);
        size_t off0 = (size_t)grow * D_MODEL + col;
        *reinterpret_cast<uint32_t*>(&Oh[off0]) = hp0;
        *reinterpret_cast<uint32_t*>(&Ol[off0]) = lp0;
        uint32_t hp1 = bf16x2_of(o[dg][2], o[dg][3]);
        uint32_t lp1 = split_lo(o[dg][2], o[dg][3], hp1);
        size_t off1 = off0 + (size_t)8 * D_MODEL;
        *reinterpret_cast<uint32_t*>(&Oh[off1]) = hp1;
        *reinterpret_cast<uint32_t*>(&Ol[off1]) = lp1;
    }
}

// ================= weight preparation =================
__global__ void wsplit4(const float* __restrict__ src, bf16* __restrict__ h,
                        bf16* __restrict__ l, int n4)
{
    int i = blockIdx.x * 256 + threadIdx.x;
    if (i >= n4) return;
    float4 v = reinterpret_cast<const float4*>(src)[i];
    uint32_t h0 = bf16x2_of(v.x, v.y), h1 = bf16x2_of(v.z, v.w);
    uint32_t l0 = split_lo(v.x, v.y, h0), l1 = split_lo(v.z, v.w, h1);
    reinterpret_cast<uint2*>(h)[i] = make_uint2(h0, h1);
    reinterpret_cast<uint2*>(l)[i] = make_uint2(l0, l1);
}

__global__ void qkv_pack(const float* __restrict__ q, const float* __restrict__ k,
                         const float* __restrict__ v, bf16* __restrict__ h, bf16* __restrict__ l)
{
    int i = blockIdx.x * 256 + threadIdx.x;
    if (i >= NLAYER * QKV3 * 256) return;
    int e = i * 4;
    int lay = e / (QKV3 * 1024);
    int rem = e - lay * (QKV3 * 1024);
    int n = rem >> 10, kk = rem & 1023;
    const float* src = (n < 1024) ? q : (n < 2048) ? k : v;
    float4 val = *reinterpret_cast<const float4*>(
        src + (size_t)lay * 1048576 + (size_t)(n & 1023) * 1024 + kk);
    uint32_t h0 = bf16x2_of(val.x, val.y), h1 = bf16x2_of(val.z, val.w);
    uint32_t l0 = split_lo(val.x, val.y, h0), l1 = split_lo(val.z, val.w, h1);
    reinterpret_cast<uint2*>(h)[i] = make_uint2(h0, h1);
    reinterpret_cast<uint2*>(l)[i] = make_uint2(l0, l1);
}

__global__ void qkvb_pack(const float* __restrict__ q, const float* __restrict__ k,
                          const float* __restrict__ v, float* __restrict__ out)
{
    int i = blockIdx.x * 256 + threadIdx.x;
    if (i >= NLAYER * QKV3) return;
    int lay = i / QKV3, n = i % QKV3;
    const float* src = (n < 1024) ? q : (n < 2048) ? k : v;
    out[i] = src[lay * 1024 + (n & 1023)];
}

__global__ void conv_repack(const float* __restrict__ w, bf16* __restrict__ h,
                            bf16* __restrict__ l, int OC, int IC)
{
    int K = IC * 3;
    int idx = blockIdx.x * 256 + threadIdx.x;
    if (idx >= OC * K) return;
    int c = idx / K, r = idx % K;
    int kk = r / IC, ic = r % IC;
    float v = w[(size_t)c * K + ic * 3 + kk];
    bf16 hv = __float2bfloat16_rn(v);
    h[idx] = hv;
    l[idx] = __float2bfloat16_rn(v - __bfloat162float(hv));
}

// ================= im2col (split outputs) =================
__global__ void im2col1s(const float* __restrict__ x, bf16* __restrict__ oh, bf16* __restrict__ ol)
{
    const int C4 = 192 / 4;
    int idx = blockIdx.x * 256 + threadIdx.x;
    if (idx >= BATCH * S1 * C4) return;
    int m = idx / C4, c4 = (idx % C4) * 4;
    int b = m / S1, s = m % S1;
    int kk = c4 / D_IN, ic = c4 % D_IN;
    float4 v = *reinterpret_cast<const float4*>(&x[((size_t)(b * S_IN + s + kk)) * D_IN + ic]);
    uint32_t h0 = bf16x2_of(v.x, v.y), h1 = bf16x2_of(v.z, v.w);
    uint32_t l0 = split_lo(v.x, v.y, h0), l1 = split_lo(v.z, v.w, h1);
    *reinterpret_cast<uint2*>(&oh[(size_t)m * 192 + c4]) = make_uint2(h0, h1);
    *reinterpret_cast<uint2*>(&ol[(size_t)m * 192 + c4]) = make_uint2(l0, l1);
}

__global__ void im2col2s(const bf16* __restrict__ ih, const bf16* __restrict__ il,
                         bf16* __restrict__ oh, bf16* __restrict__ ol)
{
    const int C8 = 1536 / 8;
    int idx = blockIdx.x * 256 + threadIdx.x;
    if (idx >= BATCH * SEQ * C8) return;
    int m = idx / C8, c8 = (idx % C8) * 8;
    int b = m / SEQ, s = m % SEQ;
    int kk = c8 / DH, ic = c8 % DH;
    size_t si = ((size_t)(b * S1 + s + kk)) * DH + ic;
    size_t di = (size_t)m * 1536 + c8;
    *reinterpret_cast<uint4*>(&oh[di]) = *reinterpret_cast<const uint4*>(&ih[si]);
    *reinterpret_cast<uint4*>(&ol[di]) = *reinterpret_cast<const uint4*>(&il[si]);
}

// ---------------- positional encoding add ----------------
__global__ void pos_add_kernel(float* __restrict__ h)
{
    int idx = blockIdx.x * 256 + threadIdx.x;
    if (idx >= BATCH * SEQ * D_MODEL) return;
    int d = idx & (D_MODEL - 1);
    int s = (idx >> 10) & (SEQ - 1);
    int i2 = d & ~1;
    float freq = expf((float)i2 * (-9.210340371976184f / 1024.0f));
    float ang  = (float)s * freq;
    double angd = (double)ang;
    double kq = rint(angd * 0.15915494309189535);
    float r = (float)(angd - kq * 6.283185307179586);
    float pe = (d & 1) ? cosf(r) : sinf(r);
    h[idx] += pe;
}

// ---------------- LayerNorm (torch-style) -> split bf16 output ----------------
__global__ void __launch_bounds__(256) layernorm_kernel(
    const float* __restrict__ x, const float* __restrict__ w,
    const float* __restrict__ b, bf16* __restrict__ yh, bf16* __restrict__ yl)
{
    __shared__ float red[8];
    __shared__ float sh_mean, sh_inv;
    const int row = blockIdx.x;
    const int t = threadIdx.x;
    const float* xr = x + (size_t)row * D_MODEL;
    float4 v = *reinterpret_cast<const float4*>(&xr[t * 4]);

    float s = v.x + v.y + v.z + v.w;
#pragma unroll
    for (int o = 16; o > 0; o >>= 1) s += __shfl_xor_sync(0xffffffffu, s, o);
    if ((t & 31) == 0) red[t >> 5] = s;
    __syncthreads();
    if (t == 0) {
        float tot = 0.f;
#pragma unroll
        for (int i = 0; i < 8; i++) tot += red[i];
        sh_mean = tot * (1.0f / 1024.0f);
    }
    __syncthreads();
    float mean = sh_mean;
    float d0 = v.x - mean, d1 = v.y - mean, d2 = v.z - mean, d3 = v.w - mean;
    float sq = d0 * d0 + d1 * d1 + d2 * d2 + d3 * d3;
#pragma unroll
    for (int o = 16; o > 0; o >>= 1) sq += __shfl_xor_sync(0xffffffffu, sq, o);
    if ((t & 31) == 0) red[t >> 5] = sq;
    __syncthreads();
    if (t == 0) {
        float tot = 0.f;
#pragma unroll
        for (int i = 0; i < 8; i++) tot += red[i];
        float var = tot * (1.0f / 1023.0f);
        sh_inv = 1.0f / (sqrtf(var) + EPSF);
    }
    __syncthreads();
    float inv = sh_inv;
    float4 w4 = *reinterpret_cast<const float4*>(&w[t * 4]);
    float4 b4 = *reinterpret_cast<const float4*>(&b[t * 4]);
    float o0 = w4.x * d0 * inv + b4.x;
    float o1 = w4.y * d1 * inv + b4.y;
    float o2 = w4.z * d2 * inv + b4.z;
    float o3 = w4.w * d3 * inv + b4.w;
    uint32_t h01 = bf16x2_of(o0, o1), h23 = bf16x2_of(o2, o3);
    uint32_t l01 = split_lo(o0, o1, h01), l23 = split_lo(o2, o3, h23);
    size_t off = (size_t)row * D_MODEL + t * 4;
    *reinterpret_cast<uint2*>(&yh[off]) = make_uint2(h01, h23);
    *reinterpret_cast<uint2*>(&yl[off]) = make_uint2(l01, l23);
}

// ---------------- mean pool + final fc ----------------
__global__ void pool_kernel(const float* __restrict__ h, float* __restrict__ out)
{
    int idx = blockIdx.x * 256 + threadIdx.x;
    if (idx >= BATCH * D_MODEL) return;
    int b = idx >> 10, d = idx & (D_MODEL - 1);
    const float* p = h + (size_t)(b * SEQ) * D_MODEL + d;
    float a[8];
#pragma unroll
    for (int i = 0; i < 8; i++) a[i] = 0.f;
    for (int i = 0; i < SEQ; i += 8) {
#pragma unroll
        for (int u = 0; u < 8; u++) a[u] += p[(size_t)(i + u) * D_MODEL];
    }
    float s = ((a[0] + a[1]) + (a[2] + a[3])) + ((a[4] + a[5]) + (a[6] + a[7]));
    out[idx] = s * (1.0f / 1024.0f);
}

__global__ void fc_kernel(const float* __restrict__ pool, const float* __restrict__ fcw,
                          const float* __restrict__ fcb, float* __restrict__ out)
{
    __shared__ float red[8];
    int b = blockIdx.x, t = threadIdx.x;
    float4 p  = *reinterpret_cast<const float4*>(&pool[b * D_MODEL + t * 4]);
    float4 w4 = *reinterpret_cast<const float4*>(&fcw[t * 4]);
    float s = p.x * w4.x + p.y * w4.y + p.z * w4.z + p.w * w4.w;
#pragma unroll
    for (int o = 16; o > 0; o >>= 1) s += __shfl_xor_sync(0xffffffffu, s, o);
    if ((t & 31) == 0) red[t >> 5] = s;
    __syncthreads();
    if (t == 0) {
        float tot = 0.f;
#pragma unroll
        for (int i = 0; i < 8; i++) tot += red[i];
        out[b] = tot + fcb[0];
    }
}

// ---------------- host orchestration ----------------
#define SYM(p, s) cudaGetSymbolAddress((void**)&p, s)

extern "C" void kernel_launch(void* const* d_in, const int* in_sizes, int n_in,
                              void* d_out, int out_size)
{
    (void)in_sizes; (void)n_in; (void)out_size;
    const float* x       = (const float*)d_in[0];
    const float* conv1_w = (const float*)d_in[1];
    const float* conv1_b = (const float*)d_in[2];
    const float* conv2_w = (const float*)d_in[3];
    const float* conv2_b = (const float*)d_in[4];
    const float* lnA_w   = (const float*)d_in[5];
    const float* lnA_b   = (const float*)d_in[6];
    const float* q_w     = (const float*)d_in[7];
    const float* q_b     = (const float*)d_in[8];
    const float* k_w     = (const float*)d_in[9];
    const float* k_b     = (const float*)d_in[10];
    const float* v_w     = (const float*)d_in[11];
    const float* v_b     = (const float*)d_in[12];
    const float* o_w     = (const float*)d_in[13];
    const float* o_b     = (const float*)d_in[14];
    const float* lnB_w   = (const float*)d_in[15];
    const float* lnB_b   = (const float*)d_in[16];
    const float* f1_w    = (const float*)d_in[17];
    const float* f1_b    = (const float*)d_in[18];
    const float* f2_w    = (const float*)d_in[19];
    const float* f2_b    = (const float*)d_in[20];
    const float* fc_w    = (const float*)d_in[21];
    const float* fc_b    = (const float*)d_in[22];
    float* out = (float*)d_out;

    float *p_h, *p_qkvb, *p_pool;
    bf16 *p_gah, *p_gal, *p_gbh, *p_gbl, *p_qvh, *p_qvl;
    bf16 *p_qkvh, *p_qkvl, *p_oh, *p_ol, *p_f1h, *p_f1l, *p_f2h, *p_f2l;
    bf16 *p_c1h, *p_c1l, *p_c2h, *p_c2l;
    SYM(p_h, g_h); SYM(p_qkvb, g_qkvb); SYM(p_pool, g_pool);
    SYM(p_gah, ga_h); SYM(p_gal, ga_l); SYM(p_gbh, gb_h); SYM(p_gbl, gb_l);
    SYM(p_qvh, g_qkvh); SYM(p_qvl, g_qkvl);
    SYM(p_qkvh, bw_qkv_h); SYM(p_qkvl, bw_qkv_l);
    SYM(p_oh, bw_o_h); SYM(p_ol, bw_o_l);
    SYM(p_f1h, bw_f1_h); SYM(p_f1l, bw_f1_l);
    SYM(p_f2h, bw_f2_h); SYM(p_f2l, bw_f2_l);
    SYM(p_c1h, bw_c1_h); SYM(p_c1l, bw_c1_l);
    SYM(p_c2h, bw_c2_h); SYM(p_c2l, bw_c2_l);

    cudaFuncSetAttribute(attention_mma, cudaFuncAttributeMaxDynamicSharedMemorySize, ATT_SMEM);
    cudaFuncSetAttribute(gemm_bf5<true, false, false>, cudaFuncAttributeMaxDynamicSharedMemorySize, GEMM_SMEM);
    cudaFuncSetAttribute(gemm_wide<false, false, false>, cudaFuncAttributeMaxDynamicSharedMemorySize, WGEMM_SMEM);
    cudaFuncSetAttribute(gemm_wide<false, false, true>,  cudaFuncAttributeMaxDynamicSharedMemorySize, WGEMM_SMEM);
    cudaFuncSetAttribute(gemm_wide<true, false, false>,  cudaFuncAttributeMaxDynamicSharedMemorySize, WGEMM_SMEM);
    cudaFuncSetAttribute(gemm_wide<true, true, false>,   cudaFuncAttributeMaxDynamicSharedMemorySize, WGEMM_SMEM);

    // ---- weight prep (split to bf16 hi/lo) ----
    qkv_pack<<<(NLAYER * QKV3 * 256 + 255) / 256, 256>>>(q_w, k_w, v_w, p_qkvh, p_qkvl);
    qkvb_pack<<<(NLAYER * QKV3 + 255) / 256, 256>>>(q_b, k_b, v_b, p_qkvb);
    wsplit4<<<(NLAYER * 1024 * 256 + 255) / 256, 256>>>(o_w, p_oh, p_ol, NLAYER * 1024 * 256);
    wsplit4<<<(NLAYER * 2048 * 256 + 255) / 256, 256>>>(f1_w, p_f1h, p_f1l, NLAYER * 2048 * 256);
    wsplit4<<<(NLAYER * 2048 * 256 + 255) / 256, 256>>>(f2_w, p_f2h, p_f2l, NLAYER * 2048 * 256);
    conv_repack<<<(512 * 192 + 255) / 256, 256>>>(conv1_w, p_c1h, p_c1l, 512, D_IN);
    conv_repack<<<(1024 * 1536 + 255) / 256, 256>>>(conv2_w, p_c2h, p_c2l, 1024, DH);

    // ---- conv frontend ----
    im2col1s<<<(BATCH * S1 * 48 + 255) / 256, 256>>>(x, p_gah, p_gal);
    gemm_bf5<true, false, false><<<dim3(4, 33), 512, GEMM_SMEM>>>(
        p_gah, p_gal, p_c1h, p_c1l, conv1_b, nullptr, nullptr, p_gbh, p_gbl,
        BATCH * S1, DH, 192);
    im2col2s<<<(BATCH * SEQ * 192 + 255) / 256, 256>>>(p_gbh, p_gbl, p_gah, p_gal);
    gemm_wide<false, false, false><<<dim3(4, 32), 512, WGEMM_SMEM>>>(
        p_gah, p_gal, p_c2h, p_c2l, conv2_b, nullptr, p_h, nullptr, nullptr,
        BATCH * SEQ, D_MODEL, 1536);
    pos_add_kernel<<<(BATCH * SEQ * D_MODEL) / 256, 256>>>(p_h);

    const int M = BATCH * SEQ;  // 4096

    for (int l = 0; l < NLAYER; l++) {
        size_t qkvo = (size_t)l * QKV3 * 1024;
        size_t oo   = (size_t)l * 1024 * 1024;
        size_t f1o  = (size_t)l * 2048 * 1024;
        size_t f2o  = (size_t)l * 1024 * 2048;
        size_t bo   = (size_t)l * D_MODEL;

        layernorm_kernel<<<M, 256>>>(p_h, lnA_w + bo, lnA_b + bo, p_gah, p_gal);
        gemm_wide<true, false, false><<<dim3(QKV3 / 256, 32), 512, WGEMM_SMEM>>>(
            p_gah, p_gal, p_qkvh + qkvo, p_qkvl + qkvo, p_qkvb + (size_t)l * QKV3,
            nullptr, nullptr, p_qvh, p_qvl, M, QKV3, 1024);

        attention_mma<<<dim3(SEQ / 128, NHEAD, BATCH), 256, ATT_SMEM>>>(
            p_qvh, p_qvl, p_gah, p_gal);

        gemm_wide<false, false, true><<<dim3(4, 32), 512, WGEMM_SMEM>>>(
            p_gah, p_gal, p_oh + oo, p_ol + oo, o_b + bo, p_h, p_h, nullptr, nullptr,
            M, D_MODEL, 1024);

        layernorm_kernel<<<M, 256>>>(p_h, lnB_w + bo, lnB_b + bo, p_gah, p_gal);
        gemm_wide<true, true, false><<<dim3(FFDIM / 256, 32), 512, WGEMM_SMEM>>>(
            p_gah, p_gal, p_f1h + f1o, p_f1l + f1o, f1_b + (size_t)l * FFDIM,
            nullptr, nullptr, p_gbh, p_gbl, M, FFDIM, 1024);
        gemm_wide<false, false, true><<<dim3(4, 32), 512, WGEMM_SMEM>>>(
            p_gbh, p_gbl, p_f2h + f2o, p_f2l + f2o, f2_b + bo, p_h, p_h, nullptr, nullptr,
            M, D_MODEL, 2048);
    }

    pool_kernel<<<(BATCH * D_MODEL) / 256, 256>>>(p_h, p_pool);
    fc_kernel<<<BATCH, 256>>>(p_pool, fc_w, fc_b, out);
}

// round 14
// speedup vs baseline: 1.7869x; 1.6088x over previous
#include <cuda_runtime.h>
#include <cuda_fp16.h>
#include <math.h>
#include <stdint.h>

// ---------------- problem dims ----------------
#define BATCH   4
#define S_IN    1028
#define D_IN    64
#define S1      1026
#define SEQ     1024
#define DH      512
#define D_MODEL 1024
#define NHEAD   16
#define HDIM    64
#define NLAYER  4
#define FFDIM   2048
#define QKV3    3072
#define EPSF    1e-6f

typedef __half f16;

// ---------------- scratch (device globals; no allocation allowed) ----------------
__device__ float g_h   [BATCH*SEQ*D_MODEL];
__device__ float g_qkvb[NLAYER*QKV3];
__device__ float g_pool[BATCH*D_MODEL];

// single-plane fp16 activations
__device__ f16 ga[4096*2048], gb[4096*2048];
__device__ f16 g_qkv[(size_t)4096*QKV3];
// split-fp16 weights (hi/lo planes)
__device__ f16 bw_qkv_h[NLAYER*QKV3*1024], bw_qkv_l[NLAYER*QKV3*1024];
__device__ f16 bw_o_h  [NLAYER*1024*1024], bw_o_l  [NLAYER*1024*1024];
__device__ f16 bw_f1_h [NLAYER*2048*1024], bw_f1_l [NLAYER*2048*1024];
__device__ f16 bw_f2_h [NLAYER*1024*2048], bw_f2_l [NLAYER*1024*2048];
__device__ f16 bw_c1_h [512*192],          bw_c1_l [512*192];
__device__ f16 bw_c2_h [1024*1536],        bw_c2_l [1024*1536];

// ================= helpers =================
__device__ __forceinline__ uint32_t smem_u32(const void* p) {
    uint32_t a;
    asm("{ .reg .u64 t; cvta.to.shared.u64 t, %1; cvt.u32.u64 %0, t; }" : "=r"(a) : "l"(p));
    return a;
}
// pack 2 fp32 -> f16x2 (first arg -> low 16 bits)
__device__ __forceinline__ uint32_t f16x2_of(float lo, float hi) {
    uint32_t r;
    asm("cvt.rn.f16x2.f32 %0, %1, %2;" : "=r"(r) : "f"(hi), "f"(lo));
    return r;
}
#define LDSM_X4(r, addr) \
    asm volatile("ldmatrix.sync.aligned.m8n8.x4.shared.b16 {%0,%1,%2,%3}, [%4];" \
        : "=r"((r)[0]), "=r"((r)[1]), "=r"((r)[2]), "=r"((r)[3]) : "r"(addr))
#define LDSM_X4T(r, addr) \
    asm volatile("ldmatrix.sync.aligned.m8n8.x4.trans.shared.b16 {%0,%1,%2,%3}, [%4];" \
        : "=r"((r)[0]), "=r"((r)[1]), "=r"((r)[2]), "=r"((r)[3]) : "r"(addr))
#define MMAF16(d, a, b) \
    asm volatile("mma.sync.aligned.m16n8k16.row.col.f32.f16.f16.f32 " \
        "{%0,%1,%2,%3}, {%4,%5,%6,%7}, {%8,%9}, {%0,%1,%2,%3};" \
        : "+f"((d)[0]), "+f"((d)[1]), "+f"((d)[2]), "+f"((d)[3]) \
        : "r"((a)[0]), "r"((a)[1]), "r"((a)[2]), "r"((a)[3]), "r"((b)[0]), "r"((b)[1]))
#define CP_ASYNC16(dst, src) \
    asm volatile("cp.async.cg.shared.global [%0], [%1], 16;" :: "r"(dst), "l"(src) : "memory")
#define CP_COMMIT()  asm volatile("cp.async.commit_group;" ::: "memory")
#define CP_WAIT1()   asm volatile("cp.async.wait_group 1;" ::: "memory")

// ================= 2-MMA GEMM: C[M,N] = A[M,K] @ (Bhi+Blo)[N,K]^T =================
// A single-plane fp16; B split-fp16. BK=64, CTA 128x256, 16 warps 32x64, 2 stages.
// stage: A 128x128B (16KB) + B 256x256B (64KB) = 80KB; x2 = 160KB.
#define WSTAGE 81920u
#define WGEMM_SMEM (2u * WSTAGE)

template<bool F16OUT, bool RELU, bool RESID>
__global__ void __launch_bounds__(512, 1) gemm_wide(
    const f16* __restrict__ Af,
    const f16* __restrict__ Bh, const f16* __restrict__ Bl,
    const float* __restrict__ bias, const float* __restrict__ resid,
    float* __restrict__ Cf, f16* __restrict__ Ch,
    int M, int N, int K)
{
    extern __shared__ char smem[];
    const uint32_t sb = smem_u32(smem);
    const int tid = threadIdx.x, lane = tid & 31, wid = tid >> 5;
    const int crow = blockIdx.y * 128, ccol = blockIdx.x * 256;
    const int NK = K >> 6;

    // ---- loader precompute ----
    // A: 1024 chunks (128 rows x 8), 2 per thread
    const f16* srcA[2];
    uint32_t dstA[2];
#pragma unroll
    for (int i = 0; i < 2; i++) {
        const int idx = tid + i * 512;
        const int row = idx >> 3, c = idx & 7;
        int gr = crow + row; if (gr > M - 1) gr = M - 1;
        srcA[i] = Af + (size_t)gr * K + c * 8;
        dstA[i] = (uint32_t)row * 128u + ((uint32_t)(c ^ (row & 7)) << 4);
    }
    // B: 4096 chunks (256 rows x 16), 8 per thread
    const f16* srcB[8];
    uint32_t dstB[8];
#pragma unroll
    for (int i = 0; i < 8; i++) {
        const int idx = tid + i * 512;
        const int row = idx >> 4, c = idx & 15;
        const int pl = c >> 3;
        srcB[i] = (pl ? Bl : Bh) + (size_t)(ccol + row) * K + (c & 7) * 8;
        dstB[i] = 16384u + (uint32_t)row * 256u
                + (((uint32_t)((c & 7) ^ (row & 7)) << 4) | ((uint32_t)(c & 8) << 4));
    }

    auto issue = [&](int kb) {
        if (kb < NK) {
            const uint32_t st = sb + (uint32_t)(kb & 1) * WSTAGE;
            const int ko = kb * 64;
#pragma unroll
            for (int i = 0; i < 2; i++)
                CP_ASYNC16(st + dstA[i], srcA[i] + ko);
#pragma unroll
            for (int i = 0; i < 8; i++)
                CP_ASYNC16(st + dstB[i], srcB[i] + ko);
        }
        CP_COMMIT();
    };

    const int wm = wid & 3, wn = wid >> 2;
    const uint32_t aoff = (uint32_t)(wm * 32 + (lane & 15)) * 128u;
    const uint32_t boff = 16384u + (uint32_t)(wn * 64 + (lane & 15)) * 256u;
    const uint32_t sel  = (uint32_t)(lane >> 4);
    const uint32_t axor = (uint32_t)(lane & 7);

    float acc[2][8][4];
#pragma unroll
    for (int i = 0; i < 2; i++)
#pragma unroll
        for (int j = 0; j < 8; j++)
#pragma unroll
            for (int e = 0; e < 4; e++) acc[i][j][e] = 0.f;

    issue(0); issue(1);

    for (int kb = 0; kb < NK; kb++) {
        CP_WAIT1();
        __syncthreads();
        const uint32_t st = sb + (uint32_t)(kb & 1) * WSTAGE;
#pragma unroll
        for (int ks = 0; ks < 4; ks++) {
            const uint32_t ch  = (((uint32_t)(ks * 2) + sel) ^ axor) << 4;
            uint32_t a[2][4];
#pragma unroll
            for (int i = 0; i < 2; i++)
                LDSM_X4(a[i], st + aoff + (uint32_t)i * (16u * 128u) + ch);
#pragma unroll
            for (int jj = 0; jj < 4; jj++) {
                const uint32_t rb = st + boff + (uint32_t)jj * (16u * 256u);
                uint32_t th[4], tl[4];
                LDSM_X4(th, rb + ch);
                LDSM_X4(tl, rb + ch + 128u);
                uint32_t b0h[2] = {th[0], th[2]}, b1h[2] = {th[1], th[3]};
                uint32_t b0l[2] = {tl[0], tl[2]}, b1l[2] = {tl[1], tl[3]};
                // hi pass (4 independent accumulators)
                MMAF16(acc[0][2 * jj],     a[0], b0h);
                MMAF16(acc[1][2 * jj],     a[1], b0h);
                MMAF16(acc[0][2 * jj + 1], a[0], b1h);
                MMAF16(acc[1][2 * jj + 1], a[1], b1h);
                // lo pass
                MMAF16(acc[0][2 * jj],     a[0], b0l);
                MMAF16(acc[1][2 * jj],     a[1], b0l);
                MMAF16(acc[0][2 * jj + 1], a[0], b1l);
                MMAF16(acc[1][2 * jj + 1], a[1], b1l);
            }
        }
        __syncthreads();
        issue(kb + 2);
    }

    // ---- epilogue ----
#pragma unroll
    for (int i = 0; i < 2; i++) {
        const int rb_ = crow + wm * 32 + i * 16 + (lane >> 2);
#pragma unroll
        for (int h = 0; h < 2; h++) {
            const int r = rb_ + h * 8;
            if (r >= M) continue;
            const size_t ro = (size_t)r * N;
#pragma unroll
            for (int j = 0; j < 8; j++) {
                const int c2 = ccol + wn * 64 + j * 8 + (lane & 3) * 2;
                float v0 = acc[i][j][2 * h]     + bias[c2];
                float v1 = acc[i][j][2 * h + 1] + bias[c2 + 1];
                if (RELU) { v0 = fmaxf(v0, 0.f); v1 = fmaxf(v1, 0.f); }
                if (RESID) { v0 += resid[ro + c2]; v1 += resid[ro + c2 + 1]; }
                if (F16OUT) {
                    *reinterpret_cast<uint32_t*>(&Ch[ro + c2]) = f16x2_of(v0, v1);
                } else {
                    *reinterpret_cast<float2*>(&Cf[ro + c2]) = make_float2(v0, v1);
                }
            }
        }
    }
}

// ================= fp16 MMA attention: softsign(QK^T/8) @ V =================
// K/V stage 16KB x2 + Q 16KB = 48KB.
#define ATT_SMEM (48 * 1024)

__global__ void __launch_bounds__(256, 1) attention_mma(
    const f16* __restrict__ QKV, f16* __restrict__ O)
{
    extern __shared__ char smem[];
    const uint32_t sb = smem_u32(smem);
    const int tid = threadIdx.x, lane = tid & 31, wid = tid >> 5;
    const int qt = blockIdx.x;
    const int h  = blockIdx.y;
    const int b  = blockIdx.z;
    const uint32_t QS = sb + 32768u;

    // ---- Q tile 128 x 64 (4 chunks/thread) ----
#pragma unroll
    for (int i = 0; i < 4; i++) {
        const int idx = tid + i * 256;
        const int row = idx >> 3, c = idx & 7;
        const f16* s = QKV + (size_t)(b * SEQ + qt * 128 + row) * QKV3 + h * HDIM + c * 8;
        CP_ASYNC16(QS + (uint32_t)row * 128u + ((uint32_t)(c ^ (row & 7)) << 4), s);
    }

    auto issueKV = [&](int jt) {
        if (jt < 16) {
#pragma unroll
            for (int i = 0; i < 4; i++) {
                const int idx = tid + i * 256;          // 0..1023
                const int mat = idx >> 9;               // 0 = K, 1 = V
                const int rem = idx & 511;
                const int row = rem >> 3, c = rem & 7;
                const f16* s = QKV + (size_t)(b * SEQ + jt * 64 + row) * QKV3
                             + 1024 + mat * 1024 + h * HDIM + c * 8;
                const uint32_t d = sb + (uint32_t)(jt & 1) * 16384u + (uint32_t)mat * 8192u
                                 + (uint32_t)row * 128u + ((uint32_t)(c ^ (row & 7)) << 4);
                CP_ASYNC16(d, s);
            }
        }
        CP_COMMIT();
    };

    issueKV(0);
    issueKV(1);

    CP_WAIT1();
    __syncthreads();

    // ---- Q fragments ----
    const uint32_t sel = (uint32_t)(lane >> 4);
    uint32_t qf[4][4];
    {
        const uint32_t arow = (uint32_t)(wid * 16 + (lane & 15));
        const uint32_t swz = arow & 7u;
        const uint32_t ra = QS + arow * 128u;
#pragma unroll
        for (int kt = 0; kt < 4; kt++)
            LDSM_X4(qf[kt], ra + ((((uint32_t)(2 * kt) + sel) ^ swz) << 4));
    }

    float o[8][4];
#pragma unroll
    for (int j = 0; j < 8; j++)
#pragma unroll
        for (int e = 0; e < 4; e++) o[j][e] = 0.f;

    for (int jt = 0; jt < 16; jt++) {
        const uint32_t ST = sb + (uint32_t)(jt & 1) * 16384u;

        // ---- S = Q @ K^T ----
        float s[8][4];
#pragma unroll
        for (int j = 0; j < 8; j++)
#pragma unroll
            for (int e = 0; e < 4; e++) s[j][e] = 0.f;

        const uint32_t brow = (uint32_t)(lane & 15);
#pragma unroll
        for (int kt = 0; kt < 4; kt++) {
#pragma unroll
            for (int ng = 0; ng < 4; ng++) {
                const uint32_t r = (uint32_t)(ng * 16) + brow;
                const uint32_t ch = (((uint32_t)(2 * kt) + sel) ^ (r & 7u)) << 4;
                uint32_t kf[4];
                LDSM_X4(kf, ST + r * 128u + ch);
                uint32_t bh0[2] = {kf[0], kf[2]}, bh1[2] = {kf[1], kf[3]};
                MMAF16(s[2 * ng],     qf[kt], bh0);
                MMAF16(s[2 * ng + 1], qf[kt], bh1);
            }
        }

        // ---- softsign in registers ----
#pragma unroll
        for (int j = 0; j < 8; j++)
#pragma unroll
            for (int e = 0; e < 4; e++) {
                float t = s[j][e] * 0.125f;
                s[j][e] = __fdividef(t, 1.0f + fabsf(t));
            }

        // ---- pack P (C-frag -> A-frag direct mapping) ----
        uint32_t pf[4][4];
#pragma unroll
        for (int kt = 0; kt < 4; kt++) {
            const float* p0 = s[2 * kt];
            const float* p1 = s[2 * kt + 1];
            pf[kt][0] = f16x2_of(p0[0], p0[1]);
            pf[kt][1] = f16x2_of(p0[2], p0[3]);
            pf[kt][2] = f16x2_of(p1[0], p1[1]);
            pf[kt][3] = f16x2_of(p1[2], p1[3]);
        }

        // ---- O += P @ V ----
#pragma unroll
        for (int dg = 0; dg < 8; dg++) {
#pragma unroll
            for (int jh = 0; jh < 2; jh++) {
                const uint32_t r = (uint32_t)(jh * 32 + lane);
                const uint32_t ch = ((uint32_t)dg ^ (r & 7u)) << 4;
                uint32_t vf[4];
                LDSM_X4T(vf, ST + 8192u + r * 128u + ch);
                uint32_t bh0[2] = {vf[0], vf[1]}, bh1[2] = {vf[2], vf[3]};
                MMAF16(o[dg], pf[2 * jh],     bh0);
                MMAF16(o[dg], pf[2 * jh + 1], bh1);
            }
        }

        __syncthreads();
        issueKV(jt + 2);
        if (jt + 1 < 16) { CP_WAIT1(); __syncthreads(); }
    }

    // ---- epilogue: fp16 out ----
    const int grow = b * SEQ + qt * 128 + wid * 16 + (lane >> 2);
    const int cbase = h * HDIM + (lane & 3) * 2;
#pragma unroll
    for (int dg = 0; dg < 8; dg++) {
        const int col = cbase + dg * 8;
        size_t off0 = (size_t)grow * D_MODEL + col;
        *reinterpret_cast<uint32_t*>(&O[off0]) = f16x2_of(o[dg][0], o[dg][1]);
        size_t off1 = off0 + (size_t)8 * D_MODEL;
        *reinterpret_cast<uint32_t*>(&O[off1]) = f16x2_of(o[dg][2], o[dg][3]);
    }
}

// ================= weight preparation (split fp16) =================
__global__ void wsplit4(const float* __restrict__ src, f16* __restrict__ h,
                        f16* __restrict__ l, int n4)
{
    int i = blockIdx.x * 256 + threadIdx.x;
    if (i >= n4) return;
    float4 v = reinterpret_cast<const float4*>(src)[i];
    f16 hx = __float2half_rn(v.x), hy = __float2half_rn(v.y);
    f16 hz = __float2half_rn(v.z), hw = __float2half_rn(v.w);
    uint32_t h0 = f16x2_of(__half2float(hx), __half2float(hy));
    uint32_t h1 = f16x2_of(__half2float(hz), __half2float(hw));
    uint32_t l0 = f16x2_of(v.x - __half2float(hx), v.y - __half2float(hy));
    uint32_t l1 = f16x2_of(v.z - __half2float(hz), v.w - __half2float(hw));
    reinterpret_cast<uint2*>(h)[i] = make_uint2(h0, h1);
    reinterpret_cast<uint2*>(l)[i] = make_uint2(l0, l1);
}

__global__ void qkv_pack(const float* __restrict__ q, const float* __restrict__ k,
                         const float* __restrict__ v, f16* __restrict__ h, f16* __restrict__ l)
{
    int i = blockIdx.x * 256 + threadIdx.x;
    if (i >= NLAYER * QKV3 * 256) return;
    int e = i * 4;
    int lay = e / (QKV3 * 1024);
    int rem = e - lay * (QKV3 * 1024);
    int n = rem >> 10, kk = rem & 1023;
    const float* src = (n < 1024) ? q : (n < 2048) ? k : v;
    float4 val = *reinterpret_cast<const float4*>(
        src + (size_t)lay * 1048576 + (size_t)(n & 1023) * 1024 + kk);
    f16 hx = __float2half_rn(val.x), hy = __float2half_rn(val.y);
    f16 hz = __float2half_rn(val.z), hw = __float2half_rn(val.w);
    uint32_t h0 = f16x2_of(__half2float(hx), __half2float(hy));
    uint32_t h1 = f16x2_of(__half2float(hz), __half2float(hw));
    uint32_t l0 = f16x2_of(val.x - __half2float(hx), val.y - __half2float(hy));
    uint32_t l1 = f16x2_of(val.z - __half2float(hz), val.w - __half2float(hw));
    reinterpret_cast<uint2*>(h)[i] = make_uint2(h0, h1);
    reinterpret_cast<uint2*>(l)[i] = make_uint2(l0, l1);
}

__global__ void qkvb_pack(const float* __restrict__ q, const float* __restrict__ k,
                          const float* __restrict__ v, float* __restrict__ out)
{
    int i = blockIdx.x * 256 + threadIdx.x;
    if (i >= NLAYER * QKV3) return;
    int lay = i / QKV3, n = i % QKV3;
    const float* src = (n < 1024) ? q : (n < 2048) ? k : v;
    out[i] = src[lay * 1024 + (n & 1023)];
}

__global__ void conv_repack(const float* __restrict__ w, f16* __restrict__ h,
                            f16* __restrict__ l, int OC, int IC)
{
    int K = IC * 3;
    int idx = blockIdx.x * 256 + threadIdx.x;
    if (idx >= OC * K) return;
    int c = idx / K, r = idx % K;
    int kk = r / IC, ic = r % IC;
    float v = w[(size_t)c * K + ic * 3 + kk];
    f16 hv = __float2half_rn(v);
    h[idx] = hv;
    l[idx] = __float2half_rn(v - __half2float(hv));
}

// ================= im2col (single fp16 out) =================
__global__ void im2col1s(const float* __restrict__ x, f16* __restrict__ o)
{
    const int C4 = 192 / 4;
    int idx = blockIdx.x * 256 + threadIdx.x;
    if (idx >= BATCH * S1 * C4) return;
    int m = idx / C4, c4 = (idx % C4) * 4;
    int b = m / S1, s = m % S1;
    int kk = c4 / D_IN, ic = c4 % D_IN;
    float4 v = *reinterpret_cast<const float4*>(&x[((size_t)(b * S_IN + s + kk)) * D_IN + ic]);
    uint32_t h0 = f16x2_of(v.x, v.y), h1 = f16x2_of(v.z, v.w);
    *reinterpret_cast<uint2*>(&o[(size_t)m * 192 + c4]) = make_uint2(h0, h1);
}

__global__ void im2col2s(const f16* __restrict__ in, f16* __restrict__ o)
{
    const int C8 = 1536 / 8;
    int idx = blockIdx.x * 256 + threadIdx.x;
    if (idx >= BATCH * SEQ * C8) return;
    int m = idx / C8, c8 = (idx % C8) * 8;
    int b = m / SEQ, s = m % SEQ;
    int kk = c8 / DH, ic = c8 % DH;
    size_t si = ((size_t)(b * S1 + s + kk)) * DH + ic;
    *reinterpret_cast<uint4*>(&o[(size_t)m * 1536 + c8]) = *reinterpret_cast<const uint4*>(&in[si]);
}

// ---------------- positional encoding add ----------------
__global__ void pos_add_kernel(float* __restrict__ h)
{
    int idx = blockIdx.x * 256 + threadIdx.x;
    if (idx >= BATCH * SEQ * D_MODEL) return;
    int d = idx & (D_MODEL - 1);
    int s = (idx >> 10) & (SEQ - 1);
    int i2 = d & ~1;
    float freq = expf((float)i2 * (-9.210340371976184f / 1024.0f));
    float ang  = (float)s * freq;
    double angd = (double)ang;
    double kq = rint(angd * 0.15915494309189535);
    float r = (float)(angd - kq * 6.283185307179586);
    float pe = (d & 1) ? cosf(r) : sinf(r);
    h[idx] += pe;
}

// ---------------- LayerNorm (torch-style) -> single fp16 out ----------------
__global__ void __launch_bounds__(256) layernorm_kernel(
    const float* __restrict__ x, const float* __restrict__ w,
    const float* __restrict__ b, f16* __restrict__ y)
{
    __shared__ float red[8];
    __shared__ float sh_mean, sh_inv;
    const int row = blockIdx.x;
    const int t = threadIdx.x;
    const float* xr = x + (size_t)row * D_MODEL;
    float4 v = *reinterpret_cast<const float4*>(&xr[t * 4]);

    float s = v.x + v.y + v.z + v.w;
#pragma unroll
    for (int o = 16; o > 0; o >>= 1) s += __shfl_xor_sync(0xffffffffu, s, o);
    if ((t & 31) == 0) red[t >> 5] = s;
    __syncthreads();
    if (t == 0) {
        float tot = 0.f;
#pragma unroll
        for (int i = 0; i < 8; i++) tot += red[i];
        sh_mean = tot * (1.0f / 1024.0f);
    }
    __syncthreads();
    float mean = sh_mean;
    float d0 = v.x - mean, d1 = v.y - mean, d2 = v.z - mean, d3 = v.w - mean;
    float sq = d0 * d0 + d1 * d1 + d2 * d2 + d3 * d3;
#pragma unroll
    for (int o = 16; o > 0; o >>= 1) sq += __shfl_xor_sync(0xffffffffu, sq, o);
    if ((t & 31) == 0) red[t >> 5] = sq;
    __syncthreads();
    if (t == 0) {
        float tot = 0.f;
#pragma unroll
        for (int i = 0; i < 8; i++) tot += red[i];
        float var = tot * (1.0f / 1023.0f);
        sh_inv = 1.0f / (sqrtf(var) + EPSF);
    }
    __syncthreads();
    float inv = sh_inv;
    float4 w4 = *reinterpret_cast<const float4*>(&w[t * 4]);
    float4 b4 = *reinterpret_cast<const float4*>(&b[t * 4]);
    float o0 = w4.x * d0 * inv + b4.x;
    float o1 = w4.y * d1 * inv + b4.y;
    float o2 = w4.z * d2 * inv + b4.z;
    float o3 = w4.w * d3 * inv + b4.w;
    size_t off = (size_t)row * D_MODEL + t * 4;
    *reinterpret_cast<uint2*>(&y[off]) = make_uint2(f16x2_of(o0, o1), f16x2_of(o2, o3));
}

// ---------------- mean pool + final fc ----------------
__global__ void pool_kernel(const float* __restrict__ h, float* __restrict__ out)
{
    int idx = blockIdx.x * 256 + threadIdx.x;
    if (idx >= BATCH * D_MODEL) return;
    int b = idx >> 10, d = idx & (D_MODEL - 1);
    const float* p = h + (size_t)(b * SEQ) * D_MODEL + d;
    float a[8];
#pragma unroll
    for (int i = 0; i < 8; i++) a[i] = 0.f;
    for (int i = 0; i < SEQ; i += 8) {
#pragma unroll
        for (int u = 0; u < 8; u++) a[u] += p[(size_t)(i + u) * D_MODEL];
    }
    float s = ((a[0] + a[1]) + (a[2] + a[3])) + ((a[4] + a[5]) + (a[6] + a[7]));
    out[idx] = s * (1.0f / 1024.0f);
}

__global__ void fc_kernel(const float* __restrict__ pool, const float* __restrict__ fcw,
                          const float* __restrict__ fcb, float* __restrict__ out)
{
    __shared__ float red[8];
    int b = blockIdx.x, t = threadIdx.x;
    float4 p  = *reinterpret_cast<const float4*>(&pool[b * D_MODEL + t * 4]);
    float4 w4 = *reinterpret_cast<const float4*>(&fcw[t * 4]);
    float s = p.x * w4.x + p.y * w4.y + p.z * w4.z + p.w * w4.w;
#pragma unroll
    for (int o = 16; o > 0; o >>= 1) s += __shfl_xor_sync(0xffffffffu, s, o);
    if ((t & 31) == 0) red[t >> 5] = s;
    __syncthreads();
    if (t == 0) {
        float tot = 0.f;
#pragma unroll
        for (int i = 0; i < 8; i++) tot += red[i];
        out[b] = tot + fcb[0];
    }
}

// ---------------- host orchestration ----------------
#define SYM(p, s) cudaGetSymbolAddress((void**)&p, s)

extern "C" void kernel_launch(void* const* d_in, const int* in_sizes, int n_in,
                              void* d_out, int out_size)
{
    (void)in_sizes; (void)n_in; (void)out_size;
    const float* x       = (const float*)d_in[0];
    const float* conv1_w = (const float*)d_in[1];
    const float* conv1_b = (const float*)d_in[2];
    const float* conv2_w = (const float*)d_in[3];
    const float* conv2_b = (const float*)d_in[4];
    const float* lnA_w   = (const float*)d_in[5];
    const float* lnA_b   = (const float*)d_in[6];
    const float* q_w     = (const float*)d_in[7];
    const float* q_b     = (const float*)d_in[8];
    const float* k_w     = (const float*)d_in[9];
    const float* k_b     = (const float*)d_in[10];
    const float* v_w     = (const float*)d_in[11];
    const float* v_b     = (const float*)d_in[12];
    const float* o_w     = (const float*)d_in[13];
    const float* o_b     = (const float*)d_in[14];
    const float* lnB_w   = (const float*)d_in[15];
    const float* lnB_b   = (const float*)d_in[16];
    const float* f1_w    = (const float*)d_in[17];
    const float* f1_b    = (const float*)d_in[18];
    const float* f2_w    = (const float*)d_in[19];
    const float* f2_b    = (const float*)d_in[20];
    const float* fc_w    = (const float*)d_in[21];
    const float* fc_b    = (const float*)d_in[22];
    float* out = (float*)d_out;

    float *p_h, *p_qkvb, *p_pool;
    f16 *p_ga, *p_gb, *p_qv;
    f16 *p_qkvh, *p_qkvl, *p_oh, *p_ol, *p_f1h, *p_f1l, *p_f2h, *p_f2l;
    f16 *p_c1h, *p_c1l, *p_c2h, *p_c2l;
    SYM(p_h, g_h); SYM(p_qkvb, g_qkvb); SYM(p_pool, g_pool);
    SYM(p_ga, ga); SYM(p_gb, gb); SYM(p_qv, g_qkv);
    SYM(p_qkvh, bw_qkv_h); SYM(p_qkvl, bw_qkv_l);
    SYM(p_oh, bw_o_h); SYM(p_ol, bw_o_l);
    SYM(p_f1h, bw_f1_h); SYM(p_f1l, bw_f1_l);
    SYM(p_f2h, bw_f2_h); SYM(p_f2l, bw_f2_l);
    SYM(p_c1h, bw_c1_h); SYM(p_c1l, bw_c1_l);
    SYM(p_c2h, bw_c2_h); SYM(p_c2l, bw_c2_l);

    cudaFuncSetAttribute(attention_mma, cudaFuncAttributeMaxDynamicSharedMemorySize, ATT_SMEM);
    cudaFuncSetAttribute(gemm_wide<false, false, false>, cudaFuncAttributeMaxDynamicSharedMemorySize, WGEMM_SMEM);
    cudaFuncSetAttribute(gemm_wide<false, false, true>,  cudaFuncAttributeMaxDynamicSharedMemorySize, WGEMM_SMEM);
    cudaFuncSetAttribute(gemm_wide<true, false, false>,  cudaFuncAttributeMaxDynamicSharedMemorySize, WGEMM_SMEM);
    cudaFuncSetAttribute(gemm_wide<true, true, false>,   cudaFuncAttributeMaxDynamicSharedMemorySize, WGEMM_SMEM);

    // ---- weight prep (split fp16 hi/lo) ----
    qkv_pack<<<(NLAYER * QKV3 * 256 + 255) / 256, 256>>>(q_w, k_w, v_w, p_qkvh, p_qkvl);
    qkvb_pack<<<(NLAYER * QKV3 + 255) / 256, 256>>>(q_b, k_b, v_b, p_qkvb);
    wsplit4<<<(NLAYER * 1024 * 256 + 255) / 256, 256>>>(o_w, p_oh, p_ol, NLAYER * 1024 * 256);
    wsplit4<<<(NLAYER * 2048 * 256 + 255) / 256, 256>>>(f1_w, p_f1h, p_f1l, NLAYER * 2048 * 256);
    wsplit4<<<(NLAYER * 2048 * 256 + 255) / 256, 256>>>(f2_w, p_f2h, p_f2l, NLAYER * 2048 * 256);
    conv_repack<<<(512 * 192 + 255) / 256, 256>>>(conv1_w, p_c1h, p_c1l, 512, D_IN);
    conv_repack<<<(1024 * 1536 + 255) / 256, 256>>>(conv2_w, p_c2h, p_c2l, 1024, DH);

    // ---- conv frontend ----
    im2col1s<<<(BATCH * S1 * 48 + 255) / 256, 256>>>(x, p_ga);
    gemm_wide<true, false, false><<<dim3(2, 33), 512, WGEMM_SMEM>>>(
        p_ga, p_c1h, p_c1l, conv1_b, nullptr, nullptr, p_gb,
        BATCH * S1, DH, 192);
    im2col2s<<<(BATCH * SEQ * 192 + 255) / 256, 256>>>(p_gb, p_ga);
    gemm_wide<false, false, false><<<dim3(4, 32), 512, WGEMM_SMEM>>>(
        p_ga, p_c2h, p_c2l, conv2_b, nullptr, p_h, nullptr,
        BATCH * SEQ, D_MODEL, 1536);
    pos_add_kernel<<<(BATCH * SEQ * D_MODEL) / 256, 256>>>(p_h);

    const int M = BATCH * SEQ;  // 4096

    for (int l = 0; l < NLAYER; l++) {
        size_t qkvo = (size_t)l * QKV3 * 1024;
        size_t oo   = (size_t)l * 1024 * 1024;
        size_t f1o  = (size_t)l * 2048 * 1024;
        size_t f2o  = (size_t)l * 1024 * 2048;
        size_t bo   = (size_t)l * D_MODEL;

        layernorm_kernel<<<M, 256>>>(p_h, lnA_w + bo, lnA_b + bo, p_ga);
        gemm_wide<true, false, false><<<dim3(QKV3 / 256, 32), 512, WGEMM_SMEM>>>(
            p_ga, p_qkvh + qkvo, p_qkvl + qkvo, p_qkvb + (size_t)l * QKV3,
            nullptr, nullptr, p_qv, M, QKV3, 1024);

        attention_mma<<<dim3(SEQ / 128, NHEAD, BATCH), 256, ATT_SMEM>>>(p_qv, p_ga);

        gemm_wide<false, false, true><<<dim3(4, 32), 512, WGEMM_SMEM>>>(
            p_ga, p_oh + oo, p_ol + oo, o_b + bo, p_h, p_h, nullptr,
            M, D_MODEL, 1024);

        layernorm_kernel<<<M, 256>>>(p_h, lnB_w + bo, lnB_b + bo, p_ga);
        gemm_wide<true, true, false><<<dim3(FFDIM / 256, 32), 512, WGEMM_SMEM>>>(
            p_ga, p_f1h + f1o, p_f1l + f1o, f1_b + (size_t)l * FFDIM,
            nullptr, nullptr, p_gb, M, FFDIM, 1024);
        gemm_wide<false, false, true><<<dim3(4, 32), 512, WGEMM_SMEM>>>(
            p_gb, p_f2h + f2o, p_f2l + f2o, f2_b + bo, p_h, p_h, nullptr,
            M, D_MODEL, 2048);
    }

    pool_kernel<<<(BATCH * D_MODEL) / 256, 256>>>(p_h, p_pool);
    fc_kernel<<<BATCH, 256>>>(p_pool, fc_w, fc_b, out);
}

// round 15
// speedup vs baseline: 1.8019x; 1.0084x over previous
#include <cuda_runtime.h>
#include <cuda_fp16.h>
#include <math.h>
#include <stdint.h>

// ---------------- problem dims ----------------
#define BATCH   4
#define S_IN    1028
#define D_IN    64
#define S1      1026
#define SEQ     1024
#define DH      512
#define D_MODEL 1024
#define NHEAD   16
#define HDIM    64
#define NLAYER  4
#define FFDIM   2048
#define QKV3    3072
#define EPSF    1e-6f

typedef __half f16;

// ---------------- scratch (device globals; no allocation allowed) ----------------
__device__ float g_h   [BATCH*SEQ*D_MODEL];
__device__ float g_qkvb[NLAYER*QKV3];
__device__ float g_pool[BATCH*D_MODEL];

// single-plane fp16 activations
__device__ f16 ga[4096*2048], gb[4096*2048];
__device__ f16 g_qkv[(size_t)4096*QKV3];
// split-fp16 weights (hi/lo planes)
__device__ f16 bw_qkv_h[NLAYER*QKV3*1024], bw_qkv_l[NLAYER*QKV3*1024];
__device__ f16 bw_o_h  [NLAYER*1024*1024], bw_o_l  [NLAYER*1024*1024];
__device__ f16 bw_f1_h [NLAYER*2048*1024], bw_f1_l [NLAYER*2048*1024];
__device__ f16 bw_f2_h [NLAYER*1024*2048], bw_f2_l [NLAYER*1024*2048];
__device__ f16 bw_c1_h [512*192],          bw_c1_l [512*192];
__device__ f16 bw_c2_h [1024*1536],        bw_c2_l [1024*1536];

// ================= helpers =================
__device__ __forceinline__ uint32_t smem_u32(const void* p) {
    uint32_t a;
    asm("{ .reg .u64 t; cvta.to.shared.u64 t, %1; cvt.u32.u64 %0, t; }" : "=r"(a) : "l"(p));
    return a;
}
// pack 2 fp32 -> f16x2 (first arg -> low 16 bits)
__device__ __forceinline__ uint32_t f16x2_of(float lo, float hi) {
    uint32_t r;
    asm("cvt.rn.f16x2.f32 %0, %1, %2;" : "=r"(r) : "f"(hi), "f"(lo));
    return r;
}
// positional encoding pair for (s, even col d): pe0 = sin, pe1 = cos
__device__ __forceinline__ void pe_pair(int s, int d_even, float& pe0, float& pe1) {
    float freq = expf((float)d_even * (-9.210340371976184f / 1024.0f));
    float ang  = (float)s * freq;
    double angd = (double)ang;
    double kq = rint(angd * 0.15915494309189535);
    float r = (float)(angd - kq * 6.283185307179586);
    pe0 = sinf(r);
    pe1 = cosf(r);
}
#define LDSM_X4(r, addr) \
    asm volatile("ldmatrix.sync.aligned.m8n8.x4.shared.b16 {%0,%1,%2,%3}, [%4];" \
        : "=r"((r)[0]), "=r"((r)[1]), "=r"((r)[2]), "=r"((r)[3]) : "r"(addr))
#define LDSM_X4T(r, addr) \
    asm volatile("ldmatrix.sync.aligned.m8n8.x4.trans.shared.b16 {%0,%1,%2,%3}, [%4];" \
        : "=r"((r)[0]), "=r"((r)[1]), "=r"((r)[2]), "=r"((r)[3]) : "r"(addr))
#define MMAF16(d, a, b) \
    asm volatile("mma.sync.aligned.m16n8k16.row.col.f32.f16.f16.f32 " \
        "{%0,%1,%2,%3}, {%4,%5,%6,%7}, {%8,%9}, {%0,%1,%2,%3};" \
        : "+f"((d)[0]), "+f"((d)[1]), "+f"((d)[2]), "+f"((d)[3]) \
        : "r"((a)[0]), "r"((a)[1]), "r"((a)[2]), "r"((a)[3]), "r"((b)[0]), "r"((b)[1]))
#define CP_ASYNC16(dst, src) \
    asm volatile("cp.async.cg.shared.global [%0], [%1], 16;" :: "r"(dst), "l"(src) : "memory")
#define CP_COMMIT()  asm volatile("cp.async.commit_group;" ::: "memory")
#define CP_WAIT1()   asm volatile("cp.async.wait_group 1;" ::: "memory")

// ================= 2-MMA GEMM: C[M,N] = A[M,K] @ (Bhi+Blo)[N,K]^T =================
// A single-plane fp16; B split-fp16. BK=64, CTA 128x256, 16 warps 32x64, 2 stages.
#define WSTAGE 81920u
#define WGEMM_SMEM (2u * WSTAGE)

template<bool F16OUT, bool RELU, bool RESID, bool PE>
__global__ void __launch_bounds__(512, 1) gemm_wide(
    const f16* __restrict__ Af,
    const f16* __restrict__ Bh, const f16* __restrict__ Bl,
    const float* __restrict__ bias, const float* __restrict__ resid,
    float* __restrict__ Cf, f16* __restrict__ Ch,
    int M, int N, int K)
{
    extern __shared__ char smem[];
    const uint32_t sb = smem_u32(smem);
    const int tid = threadIdx.x, lane = tid & 31, wid = tid >> 5;
    const int crow = blockIdx.y * 128, ccol = blockIdx.x * 256;
    const int NK = K >> 6;

    // ---- loader precompute ----
    const f16* srcA[2];
    uint32_t dstA[2];
#pragma unroll
    for (int i = 0; i < 2; i++) {
        const int idx = tid + i * 512;
        const int row = idx >> 3, c = idx & 7;
        int gr = crow + row; if (gr > M - 1) gr = M - 1;
        srcA[i] = Af + (size_t)gr * K + c * 8;
        dstA[i] = (uint32_t)row * 128u + ((uint32_t)(c ^ (row & 7)) << 4);
    }
    const f16* srcB[8];
    uint32_t dstB[8];
#pragma unroll
    for (int i = 0; i < 8; i++) {
        const int idx = tid + i * 512;
        const int row = idx >> 4, c = idx & 15;
        const int pl = c >> 3;
        srcB[i] = (pl ? Bl : Bh) + (size_t)(ccol + row) * K + (c & 7) * 8;
        dstB[i] = 16384u + (uint32_t)row * 256u
                + (((uint32_t)((c & 7) ^ (row & 7)) << 4) | ((uint32_t)(c & 8) << 4));
    }

    auto issue = [&](int kb) {
        if (kb < NK) {
            const uint32_t st = sb + (uint32_t)(kb & 1) * WSTAGE;
            const int ko = kb * 64;
#pragma unroll
            for (int i = 0; i < 2; i++)
                CP_ASYNC16(st + dstA[i], srcA[i] + ko);
#pragma unroll
            for (int i = 0; i < 8; i++)
                CP_ASYNC16(st + dstB[i], srcB[i] + ko);
        }
        CP_COMMIT();
    };

    const int wm = wid & 3, wn = wid >> 2;
    const uint32_t aoff = (uint32_t)(wm * 32 + (lane & 15)) * 128u;
    const uint32_t boff = 16384u + (uint32_t)(wn * 64 + (lane & 15)) * 256u;
    const uint32_t sel  = (uint32_t)(lane >> 4);
    const uint32_t axor = (uint32_t)(lane & 7);

    float acc[2][8][4];
#pragma unroll
    for (int i = 0; i < 2; i++)
#pragma unroll
        for (int j = 0; j < 8; j++)
#pragma unroll
            for (int e = 0; e < 4; e++) acc[i][j][e] = 0.f;

    issue(0); issue(1);

    for (int kb = 0; kb < NK; kb++) {
        CP_WAIT1();
        __syncthreads();
        const uint32_t st = sb + (uint32_t)(kb & 1) * WSTAGE;
#pragma unroll
        for (int ks = 0; ks < 4; ks++) {
            const uint32_t ch  = (((uint32_t)(ks * 2) + sel) ^ axor) << 4;
            uint32_t a[2][4];
#pragma unroll
            for (int i = 0; i < 2; i++)
                LDSM_X4(a[i], st + aoff + (uint32_t)i * (16u * 128u) + ch);
#pragma unroll
            for (int jj = 0; jj < 4; jj++) {
                const uint32_t rb = st + boff + (uint32_t)jj * (16u * 256u);
                uint32_t th[4], tl[4];
                LDSM_X4(th, rb + ch);
                LDSM_X4(tl, rb + ch + 128u);
                uint32_t b0h[2] = {th[0], th[2]}, b1h[2] = {th[1], th[3]};
                uint32_t b0l[2] = {tl[0], tl[2]}, b1l[2] = {tl[1], tl[3]};
                MMAF16(acc[0][2 * jj],     a[0], b0h);
                MMAF16(acc[1][2 * jj],     a[1], b0h);
                MMAF16(acc[0][2 * jj + 1], a[0], b1h);
                MMAF16(acc[1][2 * jj + 1], a[1], b1h);
                MMAF16(acc[0][2 * jj],     a[0], b0l);
                MMAF16(acc[1][2 * jj],     a[1], b0l);
                MMAF16(acc[0][2 * jj + 1], a[0], b1l);
                MMAF16(acc[1][2 * jj + 1], a[1], b1l);
            }
        }
        __syncthreads();
        issue(kb + 2);
    }

    // ---- epilogue ----
#pragma unroll
    for (int i = 0; i < 2; i++) {
        const int rb_ = crow + wm * 32 + i * 16 + (lane >> 2);
#pragma unroll
        for (int h = 0; h < 2; h++) {
            const int r = rb_ + h * 8;
            if (r >= M) continue;
            const size_t ro = (size_t)r * N;
#pragma unroll
            for (int j = 0; j < 8; j++) {
                const int c2 = ccol + wn * 64 + j * 8 + (lane & 3) * 2;
                float v0 = acc[i][j][2 * h]     + bias[c2];
                float v1 = acc[i][j][2 * h + 1] + bias[c2 + 1];
                if (RELU) { v0 = fmaxf(v0, 0.f); v1 = fmaxf(v1, 0.f); }
                if (RESID) { v0 += resid[ro + c2]; v1 += resid[ro + c2 + 1]; }
                if (PE) {
                    float pe0, pe1;
                    pe_pair(r & (SEQ - 1), c2, pe0, pe1);
                    v0 += pe0; v1 += pe1;
                }
                if (F16OUT) {
                    *reinterpret_cast<uint32_t*>(&Ch[ro + c2]) = f16x2_of(v0, v1);
                } else {
                    *reinterpret_cast<float2*>(&Cf[ro + c2]) = make_float2(v0, v1);
                }
            }
        }
    }
}

// ================= fp16 MMA attention: softsign(QK^T/8) @ V, KV tile 128 =================
// stage: K 16KB + V 16KB = 32KB; x2 + Q 16KB = 80KB.
#define ATT_SMEM (80 * 1024)

__global__ void __launch_bounds__(256, 1) attention_mma(
    const f16* __restrict__ QKV, f16* __restrict__ O)
{
    extern __shared__ char smem[];
    const uint32_t sb = smem_u32(smem);
    const int tid = threadIdx.x, lane = tid & 31, wid = tid >> 5;
    const int qt = blockIdx.x;
    const int h  = blockIdx.y;
    const int b  = blockIdx.z;
    const uint32_t QS = sb + 65536u;

    // ---- Q tile 128 x 64 (4 chunks/thread) ----
#pragma unroll
    for (int i = 0; i < 4; i++) {
        const int idx = tid + i * 256;
        const int row = idx >> 3, c = idx & 7;
        const f16* s = QKV + (size_t)(b * SEQ + qt * 128 + row) * QKV3 + h * HDIM + c * 8;
        CP_ASYNC16(QS + (uint32_t)row * 128u + ((uint32_t)(c ^ (row & 7)) << 4), s);
    }

    auto issueKV = [&](int jt) {
        if (jt < 8) {
#pragma unroll
            for (int i = 0; i < 8; i++) {
                const int idx = tid + i * 256;          // 0..2047
                const int mat = idx >> 10;              // 0 = K, 1 = V
                const int rem = idx & 1023;
                const int row = rem >> 3, c = rem & 7;
                const f16* s = QKV + (size_t)(b * SEQ + jt * 128 + row) * QKV3
                             + 1024 + mat * 1024 + h * HDIM + c * 8;
                const uint32_t d = sb + (uint32_t)(jt & 1) * 32768u + (uint32_t)mat * 16384u
                                 + (uint32_t)row * 128u + ((uint32_t)(c ^ (row & 7)) << 4);
                CP_ASYNC16(d, s);
            }
        }
        CP_COMMIT();
    };

    issueKV(0);
    issueKV(1);

    CP_WAIT1();
    __syncthreads();

    // ---- Q fragments ----
    const uint32_t sel = (uint32_t)(lane >> 4);
    uint32_t qf[4][4];
    {
        const uint32_t arow = (uint32_t)(wid * 16 + (lane & 15));
        const uint32_t swz = arow & 7u;
        const uint32_t ra = QS + arow * 128u;
#pragma unroll
        for (int kt = 0; kt < 4; kt++)
            LDSM_X4(qf[kt], ra + ((((uint32_t)(2 * kt) + sel) ^ swz) << 4));
    }

    float o[8][4];
#pragma unroll
    for (int j = 0; j < 8; j++)
#pragma unroll
        for (int e = 0; e < 4; e++) o[j][e] = 0.f;

    for (int jt = 0; jt < 8; jt++) {
        const uint32_t ST = sb + (uint32_t)(jt & 1) * 32768u;

        // ---- S = Q @ K^T (128 wide) ----
        float s[16][4];
#pragma unroll
        for (int j = 0; j < 16; j++)
#pragma unroll
            for (int e = 0; e < 4; e++) s[j][e] = 0.f;

        const uint32_t brow = (uint32_t)(lane & 15);
#pragma unroll
        for (int kt = 0; kt < 4; kt++) {
#pragma unroll
            for (int ng = 0; ng < 8; ng++) {
                const uint32_t r = (uint32_t)(ng * 16) + brow;
                const uint32_t ch = (((uint32_t)(2 * kt) + sel) ^ (r & 7u)) << 4;
                uint32_t kf[4];
                LDSM_X4(kf, ST + r * 128u + ch);
                uint32_t bh0[2] = {kf[0], kf[2]}, bh1[2] = {kf[1], kf[3]};
                MMAF16(s[2 * ng],     qf[kt], bh0);
                MMAF16(s[2 * ng + 1], qf[kt], bh1);
            }
        }

        // ---- softsign in registers ----
#pragma unroll
        for (int j = 0; j < 16; j++)
#pragma unroll
            for (int e = 0; e < 4; e++) {
                float t = s[j][e] * 0.125f;
                s[j][e] = __fdividef(t, 1.0f + fabsf(t));
            }

        // ---- pack P (C-frag -> A-frag direct mapping) ----
        uint32_t pf[8][4];
#pragma unroll
        for (int kt = 0; kt < 8; kt++) {
            const float* p0 = s[2 * kt];
            const float* p1 = s[2 * kt + 1];
            pf[kt][0] = f16x2_of(p0[0], p0[1]);
            pf[kt][1] = f16x2_of(p0[2], p0[3]);
            pf[kt][2] = f16x2_of(p1[0], p1[1]);
            pf[kt][3] = f16x2_of(p1[2], p1[3]);
        }

        // ---- O += P @ V (V 128 x 64) ----
#pragma unroll
        for (int dg = 0; dg < 8; dg++) {
#pragma unroll
            for (int jh = 0; jh < 4; jh++) {
                const uint32_t r = (uint32_t)(jh * 32 + lane);
                const uint32_t ch = ((uint32_t)dg ^ (r & 7u)) << 4;
                uint32_t vf[4];
                LDSM_X4T(vf, ST + 16384u + r * 128u + ch);
                uint32_t bh0[2] = {vf[0], vf[1]}, bh1[2] = {vf[2], vf[3]};
                MMAF16(o[dg], pf[2 * jh],     bh0);
                MMAF16(o[dg], pf[2 * jh + 1], bh1);
            }
        }

        __syncthreads();
        issueKV(jt + 2);
        if (jt + 1 < 8) { CP_WAIT1(); __syncthreads(); }
    }

    // ---- epilogue: fp16 out ----
    const int grow = b * SEQ + qt * 128 + wid * 16 + (lane >> 2);
    const int cbase = h * HDIM + (lane & 3) * 2;
#pragma unroll
    for (int dg = 0; dg < 8; dg++) {
        const int col = cbase + dg * 8;
        size_t off0 = (size_t)grow * D_MODEL + col;
        *reinterpret_cast<uint32_t*>(&O[off0]) = f16x2_of(o[dg][0], o[dg][1]);
        size_t off1 = off0 + (size_t)8 * D_MODEL;
        *reinterpret_cast<uint32_t*>(&O[off1]) = f16x2_of(o[dg][2], o[dg][3]);
    }
}

// ================= weight preparation (split fp16) =================
__device__ __forceinline__ void split_store(const float* __restrict__ src,
                                            f16* __restrict__ h, f16* __restrict__ l, int i)
{
    float4 v = reinterpret_cast<const float4*>(src)[i];
    f16 hx = __float2half_rn(v.x), hy = __float2half_rn(v.y);
    f16 hz = __float2half_rn(v.z), hw = __float2half_rn(v.w);
    uint32_t h0 = f16x2_of(__half2float(hx), __half2float(hy));
    uint32_t h1 = f16x2_of(__half2float(hz), __half2float(hw));
    uint32_t l0 = f16x2_of(v.x - __half2float(hx), v.y - __half2float(hy));
    uint32_t l1 = f16x2_of(v.z - __half2float(hz), v.w - __half2float(hw));
    reinterpret_cast<uint2*>(h)[i] = make_uint2(h0, h1);
    reinterpret_cast<uint2*>(l)[i] = make_uint2(l0, l1);
}

#define N4_O  (NLAYER * 1024 * 256)
#define N4_F1 (NLAYER * 2048 * 256)
#define N4_F2 (NLAYER * 2048 * 256)

__global__ void wsplit_all(const float* __restrict__ ow, f16* __restrict__ oh, f16* __restrict__ ol,
                           const float* __restrict__ f1w, f16* __restrict__ f1h, f16* __restrict__ f1l,
                           const float* __restrict__ f2w, f16* __restrict__ f2h, f16* __restrict__ f2l)
{
    int i = blockIdx.x * 256 + threadIdx.x;
    if (i < N4_O) { split_store(ow, oh, ol, i); return; }
    i -= N4_O;
    if (i < N4_F1) { split_store(f1w, f1h, f1l, i); return; }
    i -= N4_F1;
    if (i < N4_F2) split_store(f2w, f2h, f2l, i);
}

__global__ void qkv_pack(const float* __restrict__ q, const float* __restrict__ k,
                         const float* __restrict__ v, f16* __restrict__ h, f16* __restrict__ l)
{
    int i = blockIdx.x * 256 + threadIdx.x;
    if (i >= NLAYER * QKV3 * 256) return;
    int e = i * 4;
    int lay = e / (QKV3 * 1024);
    int rem = e - lay * (QKV3 * 1024);
    int n = rem >> 10, kk = rem & 1023;
    const float* src = (n < 1024) ? q : (n < 2048) ? k : v;
    float4 val = *reinterpret_cast<const float4*>(
        src + (size_t)lay * 1048576 + (size_t)(n & 1023) * 1024 + kk);
    f16 hx = __float2half_rn(val.x), hy = __float2half_rn(val.y);
    f16 hz = __float2half_rn(val.z), hw = __float2half_rn(val.w);
    uint32_t h0 = f16x2_of(__half2float(hx), __half2float(hy));
    uint32_t h1 = f16x2_of(__half2float(hz), __half2float(hw));
    uint32_t l0 = f16x2_of(val.x - __half2float(hx), val.y - __half2float(hy));
    uint32_t l1 = f16x2_of(val.z - __half2float(hz), val.w - __half2float(hw));
    reinterpret_cast<uint2*>(h)[i] = make_uint2(h0, h1);
    reinterpret_cast<uint2*>(l)[i] = make_uint2(l0, l1);
}

__global__ void qkvb_pack(const float* __restrict__ q, const float* __restrict__ k,
                          const float* __restrict__ v, float* __restrict__ out)
{
    int i = blockIdx.x * 256 + threadIdx.x;
    if (i >= NLAYER * QKV3) return;
    int lay = i / QKV3, n = i % QKV3;
    const float* src = (n < 1024) ? q : (n < 2048) ? k : v;
    out[i] = src[lay * 1024 + (n & 1023)];
}

__global__ void conv_repack(const float* __restrict__ w, f16* __restrict__ h,
                            f16* __restrict__ l, int OC, int IC)
{
    int K = IC * 3;
    int idx = blockIdx.x * 256 + threadIdx.x;
    if (idx >= OC * K) return;
    int c = idx / K, r = idx % K;
    int kk = r / IC, ic = r % IC;
    float v = w[(size_t)c * K + ic * 3 + kk];
    f16 hv = __float2half_rn(v);
    h[idx] = hv;
    l[idx] = __float2half_rn(v - __half2float(hv));
}

// ================= im2col (single fp16 out) =================
__global__ void im2col1s(const float* __restrict__ x, f16* __restrict__ o)
{
    const int C4 = 192 / 4;
    int idx = blockIdx.x * 256 + threadIdx.x;
    if (idx >= BATCH * S1 * C4) return;
    int m = idx / C4, c4 = (idx % C4) * 4;
    int b = m / S1, s = m % S1;
    int kk = c4 / D_IN, ic = c4 % D_IN;
    float4 v = *reinterpret_cast<const float4*>(&x[((size_t)(b * S_IN + s + kk)) * D_IN + ic]);
    uint32_t h0 = f16x2_of(v.x, v.y), h1 = f16x2_of(v.z, v.w);
    *reinterpret_cast<uint2*>(&o[(size_t)m * 192 + c4]) = make_uint2(h0, h1);
}

__global__ void im2col2s(const f16* __restrict__ in, f16* __restrict__ o)
{
    const int C8 = 1536 / 8;
    int idx = blockIdx.x * 256 + threadIdx.x;
    if (idx >= BATCH * SEQ * C8) return;
    int m = idx / C8, c8 = (idx % C8) * 8;
    int b = m / SEQ, s = m % SEQ;
    int kk = c8 / DH, ic = c8 % DH;
    size_t si = ((size_t)(b * S1 + s + kk)) * DH + ic;
    *reinterpret_cast<uint4*>(&o[(size_t)m * 1536 + c8]) = *reinterpret_cast<const uint4*>(&in[si]);
}

// ---------------- LayerNorm (torch-style) -> single fp16 out ----------------
__global__ void __launch_bounds__(256) layernorm_kernel(
    const float* __restrict__ x, const float* __restrict__ w,
    const float* __restrict__ b, f16* __restrict__ y)
{
    __shared__ float red[8];
    __shared__ float sh_mean, sh_inv;
    const int row = blockIdx.x;
    const int t = threadIdx.x;
    const float* xr = x + (size_t)row * D_MODEL;
    float4 v = *reinterpret_cast<const float4*>(&xr[t * 4]);

    float s = v.x + v.y + v.z + v.w;
#pragma unroll
    for (int o = 16; o > 0; o >>= 1) s += __shfl_xor_sync(0xffffffffu, s, o);
    if ((t & 31) == 0) red[t >> 5] = s;
    __syncthreads();
    if (t == 0) {
        float tot = 0.f;
#pragma unroll
        for (int i = 0; i < 8; i++) tot += red[i];
        sh_mean = tot * (1.0f / 1024.0f);
    }
    __syncthreads();
    float mean = sh_mean;
    float d0 = v.x - mean, d1 = v.y - mean, d2 = v.z - mean, d3 = v.w - mean;
    float sq = d0 * d0 + d1 * d1 + d2 * d2 + d3 * d3;
#pragma unroll
    for (int o = 16; o > 0; o >>= 1) sq += __shfl_xor_sync(0xffffffffu, sq, o);
    if ((t & 31) == 0) red[t >> 5] = sq;
    __syncthreads();
    if (t == 0) {
        float tot = 0.f;
#pragma unroll
        for (int i = 0; i < 8; i++) tot += red[i];
        float var = tot * (1.0f / 1023.0f);
        sh_inv = 1.0f / (sqrtf(var) + EPSF);
    }
    __syncthreads();
    float inv = sh_inv;
    float4 w4 = *reinterpret_cast<const float4*>(&w[t * 4]);
    float4 b4 = *reinterpret_cast<const float4*>(&b[t * 4]);
    float o0 = w4.x * d0 * inv + b4.x;
    float o1 = w4.y * d1 * inv + b4.y;
    float o2 = w4.z * d2 * inv + b4.z;
    float o3 = w4.w * d3 * inv + b4.w;
    size_t off = (size_t)row * D_MODEL + t * 4;
    *reinterpret_cast<uint2*>(&y[off]) = make_uint2(f16x2_of(o0, o1), f16x2_of(o2, o3));
}

// ---------------- mean pool + final fc ----------------
__global__ void pool_kernel(const float* __restrict__ h, float* __restrict__ out)
{
    int idx = blockIdx.x * 256 + threadIdx.x;
    if (idx >= BATCH * D_MODEL) return;
    int b = idx >> 10, d = idx & (D_MODEL - 1);
    const float* p = h + (size_t)(b * SEQ) * D_MODEL + d;
    float a[8];
#pragma unroll
    for (int i = 0; i < 8; i++) a[i] = 0.f;
    for (int i = 0; i < SEQ; i += 8) {
#pragma unroll
        for (int u = 0; u < 8; u++) a[u] += p[(size_t)(i + u) * D_MODEL];
    }
    float s = ((a[0] + a[1]) + (a[2] + a[3])) + ((a[4] + a[5]) + (a[6] + a[7]));
    out[idx] = s * (1.0f / 1024.0f);
}

__global__ void fc_kernel(const float* __restrict__ pool, const float* __restrict__ fcw,
                          const float* __restrict__ fcb, float* __restrict__ out)
{
    __shared__ float red[8];
    int b = blockIdx.x, t = threadIdx.x;
    float4 p  = *reinterpret_cast<const float4*>(&pool[b * D_MODEL + t * 4]);
    float4 w4 = *reinterpret_cast<const float4*>(&fcw[t * 4]);
    float s = p.x * w4.x + p.y * w4.y + p.z * w4.z + p.w * w4.w;
#pragma unroll
    for (int o = 16; o > 0; o >>= 1) s += __shfl_xor_sync(0xffffffffu, s, o);
    if ((t & 31) == 0) red[t >> 5] = s;
    __syncthreads();
    if (t == 0) {
        float tot = 0.f;
#pragma unroll
        for (int i = 0; i < 8; i++) tot += red[i];
        out[b] = tot + fcb[0];
    }
}

// ---------------- host orchestration ----------------
#define SYM(p, s) cudaGetSymbolAddress((void**)&p, s)

extern "C" void kernel_launch(void* const* d_in, const int* in_sizes, int n_in,
                              void* d_out, int out_size)
{
    (void)in_sizes; (void)n_in; (void)out_size;
    const float* x       = (const float*)d_in[0];
    const float* conv1_w = (const float*)d_in[1];
    const float* conv1_b = (const float*)d_in[2];
    const float* conv2_w = (const float*)d_in[3];
    const float* conv2_b = (const float*)d_in[4];
    const float* lnA_w   = (const float*)d_in[5];
    const float* lnA_b   = (const float*)d_in[6];
    const float* q_w     = (const float*)d_in[7];
    const float* q_b     = (const float*)d_in[8];
    const float* k_w     = (const float*)d_in[9];
    const float* k_b     = (const float*)d_in[10];
    const float* v_w     = (const float*)d_in[11];
    const float* v_b     = (const float*)d_in[12];
    const float* o_w     = (const float*)d_in[13];
    const float* o_b     = (const float*)d_in[14];
    const float* lnB_w   = (const float*)d_in[15];
    const float* lnB_b   = (const float*)d_in[16];
    const float* f1_w    = (const float*)d_in[17];
    const float* f1_b    = (const float*)d_in[18];
    const float* f2_w    = (const float*)d_in[19];
    const float* f2_b    = (const float*)d_in[20];
    const float* fc_w    = (const float*)d_in[21];
    const float* fc_b    = (const float*)d_in[22];
    float* out = (float*)d_out;

    float *p_h, *p_qkvb, *p_pool;
    f16 *p_ga, *p_gb, *p_qv;
    f16 *p_qkvh, *p_qkvl, *p_oh, *p_ol, *p_f1h, *p_f1l, *p_f2h, *p_f2l;
    f16 *p_c1h, *p_c1l, *p_c2h, *p_c2l;
    SYM(p_h, g_h); SYM(p_qkvb, g_qkvb); SYM(p_pool, g_pool);
    SYM(p_ga, ga); SYM(p_gb, gb); SYM(p_qv, g_qkv);
    SYM(p_qkvh, bw_qkv_h); SYM(p_qkvl, bw_qkv_l);
    SYM(p_oh, bw_o_h); SYM(p_ol, bw_o_l);
    SYM(p_f1h, bw_f1_h); SYM(p_f1l, bw_f1_l);
    SYM(p_f2h, bw_f2_h); SYM(p_f2l, bw_f2_l);
    SYM(p_c1h, bw_c1_h); SYM(p_c1l, bw_c1_l);
    SYM(p_c2h, bw_c2_h); SYM(p_c2l, bw_c2_l);

    cudaFuncSetAttribute(attention_mma, cudaFuncAttributeMaxDynamicSharedMemorySize, ATT_SMEM);
    cudaFuncSetAttribute(gemm_wide<false, false, false, false>, cudaFuncAttributeMaxDynamicSharedMemorySize, WGEMM_SMEM);
    cudaFuncSetAttribute(gemm_wide<false, false, false, true>,  cudaFuncAttributeMaxDynamicSharedMemorySize, WGEMM_SMEM);
    cudaFuncSetAttribute(gemm_wide<false, false, true, false>,  cudaFuncAttributeMaxDynamicSharedMemorySize, WGEMM_SMEM);
    cudaFuncSetAttribute(gemm_wide<true, false, false, false>,  cudaFuncAttributeMaxDynamicSharedMemorySize, WGEMM_SMEM);
    cudaFuncSetAttribute(gemm_wide<true, true, false, false>,   cudaFuncAttributeMaxDynamicSharedMemorySize, WGEMM_SMEM);

    // ---- weight prep (split fp16 hi/lo) ----
    qkv_pack<<<(NLAYER * QKV3 * 256 + 255) / 256, 256>>>(q_w, k_w, v_w, p_qkvh, p_qkvl);
    qkvb_pack<<<(NLAYER * QKV3 + 255) / 256, 256>>>(q_b, k_b, v_b, p_qkvb);
    wsplit_all<<<(N4_O + N4_F1 + N4_F2 + 255) / 256, 256>>>(
        o_w, p_oh, p_ol, f1_w, p_f1h, p_f1l, f2_w, p_f2h, p_f2l);
    conv_repack<<<(512 * 192 + 255) / 256, 256>>>(conv1_w, p_c1h, p_c1l, 512, D_IN);
    conv_repack<<<(1024 * 1536 + 255) / 256, 256>>>(conv2_w, p_c2h, p_c2l, 1024, DH);

    // ---- conv frontend (pos-enc fused into conv2 epilogue) ----
    im2col1s<<<(BATCH * S1 * 48 + 255) / 256, 256>>>(x, p_ga);
    gemm_wide<true, false, false, false><<<dim3(2, 33), 512, WGEMM_SMEM>>>(
        p_ga, p_c1h, p_c1l, conv1_b, nullptr, nullptr, p_gb,
        BATCH * S1, DH, 192);
    im2col2s<<<(BATCH * SEQ * 192 + 255) / 256, 256>>>(p_gb, p_ga);
    gemm_wide<false, false, false, true><<<dim3(4, 32), 512, WGEMM_SMEM>>>(
        p_ga, p_c2h, p_c2l, conv2_b, nullptr, p_h, nullptr,
        BATCH * SEQ, D_MODEL, 1536);

    const int M = BATCH * SEQ;  // 4096

    for (int l = 0; l < NLAYER; l++) {
        size_t qkvo = (size_t)l * QKV3 * 1024;
        size_t oo   = (size_t)l * 1024 * 1024;
        size_t f1o  = (size_t)l * 2048 * 1024;
        size_t f2o  = (size_t)l * 1024 * 2048;
        size_t bo   = (size_t)l * D_MODEL;

        layernorm_kernel<<<M, 256>>>(p_h, lnA_w + bo, lnA_b + bo, p_ga);
        gemm_wide<true, false, false, false><<<dim3(QKV3 / 256, 32), 512, WGEMM_SMEM>>>(
            p_ga, p_qkvh + qkvo, p_qkvl + qkvo, p_qkvb + (size_t)l * QKV3,
            nullptr, nullptr, p_qv, M, QKV3, 1024);

        attention_mma<<<dim3(SEQ / 128, NHEAD, BATCH), 256, ATT_SMEM>>>(p_qv, p_ga);

        gemm_wide<false, false, true, false><<<dim3(4, 32), 512, WGEMM_SMEM>>>(
            p_ga, p_oh + oo, p_ol + oo, o_b + bo, p_h, p_h, nullptr,
            M, D_MODEL, 1024);

        layernorm_kernel<<<M, 256>>>(p_h, lnB_w + bo, lnB_b + bo, p_ga);
        gemm_wide<true, true, false, false><<<dim3(FFDIM / 256, 32), 512, WGEMM_SMEM>>>(
            p_ga, p_f1h + f1o, p_f1l + f1o, f1_b + (size_t)l * FFDIM,
            nullptr, nullptr, p_gb, M, FFDIM, 1024);
        gemm_wide<false, false, true, false><<<dim3(4, 32), 512, WGEMM_SMEM>>>(
            p_gb, p_f2h + f2o, p_f2l + f2o, f2_b + bo, p_h, p_h, nullptr,
            M, D_MODEL, 2048);
    }

    pool_kernel<<<(BATCH * D_MODEL) / 256, 256>>>(p_h, p_pool);
    fc_kernel<<<BATCH, 256>>>(p_pool, fc_w, fc_b, out);
}

// round 17
// speedup vs baseline: 1.8092x; 1.0040x over previous
#include <cuda_runtime.h>
#include <cuda_fp16.h>
#include <math.h>
#include <stdint.h>

// ---------------- problem dims ----------------
#define BATCH   4
#define S_IN    1028
#define D_IN    64
#define S1      1026
#define SEQ     1024
#define DH      512
#define D_MODEL 1024
#define NHEAD   16
#define HDIM    64
#define NLAYER  4
#define FFDIM   2048
#define QKV3    3072
#define EPSF    1e-6f

typedef __half f16;

// ---------------- scratch (device globals; no allocation allowed) ----------------
__device__ float g_h   [BATCH*SEQ*D_MODEL];
__device__ float g_qkvb[NLAYER*QKV3];
__device__ float g_pool[BATCH*D_MODEL];

// single-plane fp16 activations
__device__ f16 ga[4096*2048], gb[4096*2048];
__device__ f16 g_qkv[(size_t)4096*QKV3];
// split-fp16 weights (hi/lo planes)
__device__ f16 bw_qkv_h[NLAYER*QKV3*1024], bw_qkv_l[NLAYER*QKV3*1024];
__device__ f16 bw_o_h  [NLAYER*1024*1024], bw_o_l  [NLAYER*1024*1024];
__device__ f16 bw_f1_h [NLAYER*2048*1024], bw_f1_l [NLAYER*2048*1024];
__device__ f16 bw_f2_h [NLAYER*1024*2048], bw_f2_l [NLAYER*1024*2048];
__device__ f16 bw_c1_h [512*192],          bw_c1_l [512*192];
__device__ f16 bw_c2_h [1024*1536],        bw_c2_l [1024*1536];

// ================= helpers =================
__device__ __forceinline__ uint32_t smem_u32(const void* p) {
    uint32_t a;
    asm("{ .reg .u64 t; cvta.to.shared.u64 t, %1; cvt.u32.u64 %0, t; }" : "=r"(a) : "l"(p));
    return a;
}
// pack 2 fp32 -> f16x2 (first arg -> low 16 bits)
__device__ __forceinline__ uint32_t f16x2_of(float lo, float hi) {
    uint32_t r;
    asm("cvt.rn.f16x2.f32 %0, %1, %2;" : "=r"(r) : "f"(hi), "f"(lo));
    return r;
}
// positional encoding pair for (s, even col d): pe0 = sin, pe1 = cos
__device__ __forceinline__ void pe_pair(int s, int d_even, float& pe0, float& pe1) {
    float freq = expf((float)d_even * (-9.210340371976184f / 1024.0f));
    float ang  = (float)s * freq;
    double angd = (double)ang;
    double kq = rint(angd * 0.15915494309189535);
    float r = (float)(angd - kq * 6.283185307179586);
    pe0 = sinf(r);
    pe1 = cosf(r);
}
#define LDSM_X4(r, addr) \
    asm volatile("ldmatrix.sync.aligned.m8n8.x4.shared.b16 {%0,%1,%2,%3}, [%4];" \
        : "=r"((r)[0]), "=r"((r)[1]), "=r"((r)[2]), "=r"((r)[3]) : "r"(addr))
#define LDSM_X4T(r, addr) \
    asm volatile("ldmatrix.sync.aligned.m8n8.x4.trans.shared.b16 {%0,%1,%2,%3}, [%4];" \
        : "=r"((r)[0]), "=r"((r)[1]), "=r"((r)[2]), "=r"((r)[3]) : "r"(addr))
#define MMAF16(d, a, b) \
    asm volatile("mma.sync.aligned.m16n8k16.row.col.f32.f16.f16.f32 " \
        "{%0,%1,%2,%3}, {%4,%5,%6,%7}, {%8,%9}, {%0,%1,%2,%3};" \
        : "+f"((d)[0]), "+f"((d)[1]), "+f"((d)[2]), "+f"((d)[3]) \
        : "r"((a)[0]), "r"((a)[1]), "r"((a)[2]), "r"((a)[3]), "r"((b)[0]), "r"((b)[1]))
#define CP_ASYNC16(dst, src) \
    asm volatile("cp.async.cg.shared.global [%0], [%1], 16;" :: "r"(dst), "l"(src) : "memory")
#define CP_COMMIT()  asm volatile("cp.async.commit_group;" ::: "memory")
#define CP_WAIT1()   asm volatile("cp.async.wait_group 1;" ::: "memory")

// ================= 2-MMA GEMM: C[M,N] = A[M,K] @ (Bhi+Blo)[N,K]^T =================
// A single-plane fp16; B split-fp16. BK=64, CTA 128x256, 16 warps 32x64, 2 stages.
#define WSTAGE 81920u
#define WGEMM_SMEM (2u * WSTAGE)

template<bool F16OUT, bool RELU, bool RESID, bool PE>
__global__ void __launch_bounds__(512, 1) gemm_wide(
    const f16* __restrict__ Af,
    const f16* __restrict__ Bh, const f16* __restrict__ Bl,
    const float* __restrict__ bias, const float* __restrict__ resid,
    float* __restrict__ Cf, f16* __restrict__ Ch,
    int M, int N, int K)
{
    extern __shared__ char smem[];
    const uint32_t sb = smem_u32(smem);
    const int tid = threadIdx.x, lane = tid & 31, wid = tid >> 5;
    const int crow = blockIdx.y * 128, ccol = blockIdx.x * 256;
    const int NK = K >> 6;

    // ---- loader precompute ----
    const f16* srcA[2];
    uint32_t dstA[2];
#pragma unroll
    for (int i = 0; i < 2; i++) {
        const int idx = tid + i * 512;
        const int row = idx >> 3, c = idx & 7;
        int gr = crow + row; if (gr > M - 1) gr = M - 1;
        srcA[i] = Af + (size_t)gr * K + c * 8;
        dstA[i] = (uint32_t)row * 128u + ((uint32_t)(c ^ (row & 7)) << 4);
    }
    const f16* srcB[8];
    uint32_t dstB[8];
#pragma unroll
    for (int i = 0; i < 8; i++) {
        const int idx = tid + i * 512;
        const int row = idx >> 4, c = idx & 15;
        const int pl = c >> 3;
        srcB[i] = (pl ? Bl : Bh) + (size_t)(ccol + row) * K + (c & 7) * 8;
        dstB[i] = 16384u + (uint32_t)row * 256u
                + (((uint32_t)((c & 7) ^ (row & 7)) << 4) | ((uint32_t)(c & 8) << 4));
    }

    auto issue = [&](int kb) {
        if (kb < NK) {
            const uint32_t st = sb + (uint32_t)(kb & 1) * WSTAGE;
            const int ko = kb * 64;
#pragma unroll
            for (int i = 0; i < 2; i++)
                CP_ASYNC16(st + dstA[i], srcA[i] + ko);
#pragma unroll
            for (int i = 0; i < 8; i++)
                CP_ASYNC16(st + dstB[i], srcB[i] + ko);
        }
        CP_COMMIT();
    };

    const int wm = wid & 3, wn = wid >> 2;
    const uint32_t aoff = (uint32_t)(wm * 32 + (lane & 15)) * 128u;
    const uint32_t boff = 16384u + (uint32_t)(wn * 64 + (lane & 15)) * 256u;
    const uint32_t sel  = (uint32_t)(lane >> 4);
    const uint32_t axor = (uint32_t)(lane & 7);

    float acc[2][8][4];
#pragma unroll
    for (int i = 0; i < 2; i++)
#pragma unroll
        for (int j = 0; j < 8; j++)
#pragma unroll
            for (int e = 0; e < 4; e++) acc[i][j][e] = 0.f;

    issue(0); issue(1);

    for (int kb = 0; kb < NK; kb++) {
        CP_WAIT1();
        __syncthreads();
        const uint32_t st = sb + (uint32_t)(kb & 1) * WSTAGE;
#pragma unroll
        for (int ks = 0; ks < 4; ks++) {
            const uint32_t ch  = (((uint32_t)(ks * 2) + sel) ^ axor) << 4;
            uint32_t a[2][4];
#pragma unroll
            for (int i = 0; i < 2; i++)
                LDSM_X4(a[i], st + aoff + (uint32_t)i * (16u * 128u) + ch);
#pragma unroll
            for (int jj = 0; jj < 4; jj++) {
                const uint32_t rb = st + boff + (uint32_t)jj * (16u * 256u);
                uint32_t th[4], tl[4];
                LDSM_X4(th, rb + ch);
                LDSM_X4(tl, rb + ch + 128u);
                uint32_t b0h[2] = {th[0], th[2]}, b1h[2] = {th[1], th[3]};
                uint32_t b0l[2] = {tl[0], tl[2]}, b1l[2] = {tl[1], tl[3]};
                MMAF16(acc[0][2 * jj],     a[0], b0h);
                MMAF16(acc[1][2 * jj],     a[1], b0h);
                MMAF16(acc[0][2 * jj + 1], a[0], b1h);
                MMAF16(acc[1][2 * jj + 1], a[1], b1h);
                MMAF16(acc[0][2 * jj],     a[0], b0l);
                MMAF16(acc[1][2 * jj],     a[1], b0l);
                MMAF16(acc[0][2 * jj + 1], a[0], b1l);
                MMAF16(acc[1][2 * jj + 1], a[1], b1l);
            }
        }
        __syncthreads();
        issue(kb + 2);
    }

    // ---- epilogue ----
#pragma unroll
    for (int i = 0; i < 2; i++) {
        const int rb_ = crow + wm * 32 + i * 16 + (lane >> 2);
#pragma unroll
        for (int h = 0; h < 2; h++) {
            const int r = rb_ + h * 8;
            if (r >= M) continue;
            const size_t ro = (size_t)r * N;
#pragma unroll
            for (int j = 0; j < 8; j++) {
                const int c2 = ccol + wn * 64 + j * 8 + (lane & 3) * 2;
                float v0 = acc[i][j][2 * h]     + bias[c2];
                float v1 = acc[i][j][2 * h + 1] + bias[c2 + 1];
                if (RELU) { v0 = fmaxf(v0, 0.f); v1 = fmaxf(v1, 0.f); }
                if (RESID) { v0 += resid[ro + c2]; v1 += resid[ro + c2 + 1]; }
                if (PE) {
                    float pe0, pe1;
                    pe_pair(r & (SEQ - 1), c2, pe0, pe1);
                    v0 += pe0; v1 += pe1;
                }
                if (F16OUT) {
                    *reinterpret_cast<uint32_t*>(&Ch[ro + c2]) = f16x2_of(v0, v1);
                } else {
                    *reinterpret_cast<float2*>(&Cf[ro + c2]) = make_float2(v0, v1);
                }
            }
        }
    }
}

// ================= fp16 MMA attention: softsign(QK^T/8) @ V, KV tile 128 =================
#define ATT_SMEM (80 * 1024)

__global__ void __launch_bounds__(256, 1) attention_mma(
    const f16* __restrict__ QKV, f16* __restrict__ O)
{
    extern __shared__ char smem[];
    const uint32_t sb = smem_u32(smem);
    const int tid = threadIdx.x, lane = tid & 31, wid = tid >> 5;
    const int qt = blockIdx.x;
    const int h  = blockIdx.y;
    const int b  = blockIdx.z;
    const uint32_t QS = sb + 65536u;

    // ---- Q tile 128 x 64 (4 chunks/thread) ----
#pragma unroll
    for (int i = 0; i < 4; i++) {
        const int idx = tid + i * 256;
        const int row = idx >> 3, c = idx & 7;
        const f16* s = QKV + (size_t)(b * SEQ + qt * 128 + row) * QKV3 + h * HDIM + c * 8;
        CP_ASYNC16(QS + (uint32_t)row * 128u + ((uint32_t)(c ^ (row & 7)) << 4), s);
    }

    auto issueKV = [&](int jt) {
        if (jt < 8) {
#pragma unroll
            for (int i = 0; i < 8; i++) {
                const int idx = tid + i * 256;          // 0..2047
                const int mat = idx >> 10;              // 0 = K, 1 = V
                const int rem = idx & 1023;
                const int row = rem >> 3, c = rem & 7;
                const f16* s = QKV + (size_t)(b * SEQ + jt * 128 + row) * QKV3
                             + 1024 + mat * 1024 + h * HDIM + c * 8;
                const uint32_t d = sb + (uint32_t)(jt & 1) * 32768u + (uint32_t)mat * 16384u
                                 + (uint32_t)row * 128u + ((uint32_t)(c ^ (row & 7)) << 4);
                CP_ASYNC16(d, s);
            }
        }
        CP_COMMIT();
    };

    issueKV(0);
    issueKV(1);

    CP_WAIT1();
    __syncthreads();

    // ---- Q fragments ----
    const uint32_t sel = (uint32_t)(lane >> 4);
    uint32_t qf[4][4];
    {
        const uint32_t arow = (uint32_t)(wid * 16 + (lane & 15));
        const uint32_t swz = arow & 7u;
        const uint32_t ra = QS + arow * 128u;
#pragma unroll
        for (int kt = 0; kt < 4; kt++)
            LDSM_X4(qf[kt], ra + ((((uint32_t)(2 * kt) + sel) ^ swz) << 4));
    }

    float o[8][4];
#pragma unroll
    for (int j = 0; j < 8; j++)
#pragma unroll
        for (int e = 0; e < 4; e++) o[j][e] = 0.f;

    for (int jt = 0; jt < 8; jt++) {
        const uint32_t ST = sb + (uint32_t)(jt & 1) * 32768u;

        // ---- S = Q @ K^T (128 wide) ----
        float s[16][4];
#pragma unroll
        for (int j = 0; j < 16; j++)
#pragma unroll
            for (int e = 0; e < 4; e++) s[j][e] = 0.f;

        const uint32_t brow = (uint32_t)(lane & 15);
#pragma unroll
        for (int kt = 0; kt < 4; kt++) {
#pragma unroll
            for (int ng = 0; ng < 8; ng++) {
                const uint32_t r = (uint32_t)(ng * 16) + brow;
                const uint32_t ch = (((uint32_t)(2 * kt) + sel) ^ (r & 7u)) << 4;
                uint32_t kf[4];
                LDSM_X4(kf, ST + r * 128u + ch);
                uint32_t bh0[2] = {kf[0], kf[2]}, bh1[2] = {kf[1], kf[3]};
                MMAF16(s[2 * ng],     qf[kt], bh0);
                MMAF16(s[2 * ng + 1], qf[kt], bh1);
            }
        }

        // ---- softsign in registers ----
#pragma unroll
        for (int j = 0; j < 16; j++)
#pragma unroll
            for (int e = 0; e < 4; e++) {
                float t = s[j][e] * 0.125f;
                s[j][e] = __fdividef(t, 1.0f + fabsf(t));
            }

        // ---- pack P (C-frag -> A-frag direct mapping) ----
        uint32_t pf[8][4];
#pragma unroll
        for (int kt = 0; kt < 8; kt++) {
            const float* p0 = s[2 * kt];
            const float* p1 = s[2 * kt + 1];
            pf[kt][0] = f16x2_of(p0[0], p0[1]);
            pf[kt][1] = f16x2_of(p0[2], p0[3]);
            pf[kt][2] = f16x2_of(p1[0], p1[1]);
            pf[kt][3] = f16x2_of(p1[2], p1[3]);
        }

        // ---- O += P @ V (V 128 x 64) ----
#pragma unroll
        for (int dg = 0; dg < 8; dg++) {
#pragma unroll
            for (int jh = 0; jh < 4; jh++) {
                const uint32_t r = (uint32_t)(jh * 32 + lane);
                const uint32_t ch = ((uint32_t)dg ^ (r & 7u)) << 4;
                uint32_t vf[4];
                LDSM_X4T(vf, ST + 16384u + r * 128u + ch);
                uint32_t bh0[2] = {vf[0], vf[1]}, bh1[2] = {vf[2], vf[3]};
                MMAF16(o[dg], pf[2 * jh],     bh0);
                MMAF16(o[dg], pf[2 * jh + 1], bh1);
            }
        }

        __syncthreads();
        issueKV(jt + 2);
        if (jt + 1 < 8) { CP_WAIT1(); __syncthreads(); }
    }

    // ---- epilogue: fp16 out ----
    const int grow = b * SEQ + qt * 128 + wid * 16 + (lane >> 2);
    const int cbase = h * HDIM + (lane & 3) * 2;
#pragma unroll
    for (int dg = 0; dg < 8; dg++) {
        const int col = cbase + dg * 8;
        size_t off0 = (size_t)grow * D_MODEL + col;
        *reinterpret_cast<uint32_t*>(&O[off0]) = f16x2_of(o[dg][0], o[dg][1]);
        size_t off1 = off0 + (size_t)8 * D_MODEL;
        *reinterpret_cast<uint32_t*>(&O[off1]) = f16x2_of(o[dg][2], o[dg][3]);
    }
}

// ================= weight preparation (split fp16) =================
__device__ __forceinline__ void split_store(const float* __restrict__ src,
                                            f16* __restrict__ h, f16* __restrict__ l, int i)
{
    float4 v = reinterpret_cast<const float4*>(src)[i];
    f16 hx = __float2half_rn(v.x), hy = __float2half_rn(v.y);
    f16 hz = __float2half_rn(v.z), hw = __float2half_rn(v.w);
    uint32_t h0 = f16x2_of(__half2float(hx), __half2float(hy));
    uint32_t h1 = f16x2_of(__half2float(hz), __half2float(hw));
    uint32_t l0 = f16x2_of(v.x - __half2float(hx), v.y - __half2float(hy));
    uint32_t l1 = f16x2_of(v.z - __half2float(hz), v.w - __half2float(hw));
    reinterpret_cast<uint2*>(h)[i] = make_uint2(h0, h1);
    reinterpret_cast<uint2*>(l)[i] = make_uint2(l0, l1);
}

#define N4_O  (NLAYER * 1024 * 256)
#define N4_F1 (NLAYER * 2048 * 256)
#define N4_F2 (NLAYER * 2048 * 256)

__global__ void wsplit_all(const float* __restrict__ ow, f16* __restrict__ oh, f16* __restrict__ ol,
                           const float* __restrict__ f1w, f16* __restrict__ f1h, f16* __restrict__ f1l,
                           const float* __restrict__ f2w, f16* __restrict__ f2h, f16* __restrict__ f2l)
{
    int i = blockIdx.x * 256 + threadIdx.x;
    if (i < N4_O) { split_store(ow, oh, ol, i); return; }
    i -= N4_O;
    if (i < N4_F1) { split_store(f1w, f1h, f1l, i); return; }
    i -= N4_F1;
    if (i < N4_F2) split_store(f2w, f2h, f2l, i);
}

__global__ void qkv_pack(const float* __restrict__ q, const float* __restrict__ k,
                         const float* __restrict__ v, f16* __restrict__ h, f16* __restrict__ l)
{
    int i = blockIdx.x * 256 + threadIdx.x;
    if (i >= NLAYER * QKV3 * 256) return;
    int e = i * 4;
    int lay = e / (QKV3 * 1024);
    int rem = e - lay * (QKV3 * 1024);
    int n = rem >> 10, kk = rem & 1023;
    const float* src = (n < 1024) ? q : (n < 2048) ? k : v;
    float4 val = *reinterpret_cast<const float4*>(
        src + (size_t)lay * 1048576 + (size_t)(n & 1023) * 1024 + kk);
    f16 hx = __float2half_rn(val.x), hy = __float2half_rn(val.y);
    f16 hz = __float2half_rn(val.z), hw = __float2half_rn(val.w);
    uint32_t h0 = f16x2_of(__half2float(hx), __half2float(hy));
    uint32_t h1 = f16x2_of(__half2float(hz), __half2float(hw));
    uint32_t l0 = f16x2_of(val.x - __half2float(hx), val.y - __half2float(hy));
    uint32_t l1 = f16x2_of(val.z - __half2float(hz), val.w - __half2float(hw));
    reinterpret_cast<uint2*>(h)[i] = make_uint2(h0, h1);
    reinterpret_cast<uint2*>(l)[i] = make_uint2(l0, l1);
}

__global__ void qkvb_pack(const float* __restrict__ q, const float* __restrict__ k,
                          const float* __restrict__ v, float* __restrict__ out)
{
    int i = blockIdx.x * 256 + threadIdx.x;
    if (i >= NLAYER * QKV3) return;
    int lay = i / QKV3, n = i % QKV3;
    const float* src = (n < 1024) ? q : (n < 2048) ? k : v;
    out[i] = src[lay * 1024 + (n & 1023)];
}

// both conv weight repacks in one launch: idx < 512*192 -> conv1, else conv2
#define NC1 (512 * 192)
#define NC2 (1024 * 1536)
__global__ void conv_repack2(const float* __restrict__ w1, f16* __restrict__ h1, f16* __restrict__ l1,
                             const float* __restrict__ w2, f16* __restrict__ h2, f16* __restrict__ l2)
{
    int idx = blockIdx.x * 256 + threadIdx.x;
    const float* w; f16 *h, *l; int IC;
    if (idx < NC1) { w = w1; h = h1; l = l1; IC = D_IN; }
    else if (idx < NC1 + NC2) { idx -= NC1; w = w2; h = h2; l = l2; IC = DH; }
    else return;
    int K = IC * 3;
    int c = idx / K, r = idx % K;
    int kk = r / IC, ic = r % IC;
    float v = w[(size_t)c * K + ic * 3 + kk];
    f16 hv = __float2half_rn(v);
    h[idx] = hv;
    l[idx] = __float2half_rn(v - __half2float(hv));
}

// ================= im2col (single fp16 out) =================
__global__ void im2col1s(const float* __restrict__ x, f16* __restrict__ o)
{
    const int C4 = 192 / 4;
    int idx = blockIdx.x * 256 + threadIdx.x;
    if (idx >= BATCH * S1 * C4) return;
    int m = idx / C4, c4 = (idx % C4) * 4;
    int b = m / S1, s = m % S1;
    int kk = c4 / D_IN, ic = c4 % D_IN;
    float4 v = *reinterpret_cast<const float4*>(&x[((size_t)(b * S_IN + s + kk)) * D_IN + ic]);
    *reinterpret_cast<uint2*>(&o[(size_t)m * 192 + c4]) =
        make_uint2(f16x2_of(v.x, v.y), f16x2_of(v.z, v.w));
}

__global__ void im2col2s(const f16* __restrict__ in, f16* __restrict__ o)
{
    const int C8 = 1536 / 8;
    int idx = blockIdx.x * 256 + threadIdx.x;
    if (idx >= BATCH * SEQ * C8) return;
    int m = idx / C8, c8 = (idx % C8) * 8;
    int b = m / SEQ, s = m % SEQ;
    int kk = c8 / DH, ic = c8 % DH;
    size_t si = ((size_t)(b * S1 + s + kk)) * DH + ic;
    *reinterpret_cast<uint4*>(&o[(size_t)m * 1536 + c8]) = *reinterpret_cast<const uint4*>(&in[si]);
}

// ---------------- LayerNorm (torch-style) -> single fp16 out ----------------
__global__ void __launch_bounds__(256) layernorm_kernel(
    const float* __restrict__ x, const float* __restrict__ w,
    const float* __restrict__ b, f16* __restrict__ y)
{
    __shared__ float red[8];
    __shared__ float sh_mean, sh_inv;
    const int row = blockIdx.x;
    const int t = threadIdx.x;
    const float* xr = x + (size_t)row * D_MODEL;
    float4 v = *reinterpret_cast<const float4*>(&xr[t * 4]);

    float s = v.x + v.y + v.z + v.w;
#pragma unroll
    for (int o = 16; o > 0; o >>= 1) s += __shfl_xor_sync(0xffffffffu, s, o);
    if ((t & 31) == 0) red[t >> 5] = s;
    __syncthreads();
    if (t == 0) {
        float tot = 0.f;
#pragma unroll
        for (int i = 0; i < 8; i++) tot += red[i];
        sh_mean = tot * (1.0f / 1024.0f);
    }
    __syncthreads();
    float mean = sh_mean;
    float d0 = v.x - mean, d1 = v.y - mean, d2 = v.z - mean, d3 = v.w - mean;
    float sq = d0 * d0 + d1 * d1 + d2 * d2 + d3 * d3;
#pragma unroll
    for (int o = 16; o > 0; o >>= 1) sq += __shfl_xor_sync(0xffffffffu, sq, o);
    if ((t & 31) == 0) red[t >> 5] = sq;
    __syncthreads();
    if (t == 0) {
        float tot = 0.f;
#pragma unroll
        for (int i = 0; i < 8; i++) tot += red[i];
        float var = tot * (1.0f / 1023.0f);
        sh_inv = 1.0f / (sqrtf(var) + EPSF);
    }
    __syncthreads();
    float inv = sh_inv;
    float4 w4 = *reinterpret_cast<const float4*>(&w[t * 4]);
    float4 b4 = *reinterpret_cast<const float4*>(&b[t * 4]);
    float o0 = w4.x * d0 * inv + b4.x;
    float o1 = w4.y * d1 * inv + b4.y;
    float o2 = w4.z * d2 * inv + b4.z;
    float o3 = w4.w * d3 * inv + b4.w;
    size_t off = (size_t)row * D_MODEL + t * 4;
    *reinterpret_cast<uint2*>(&y[off]) = make_uint2(f16x2_of(o0, o1), f16x2_of(o2, o3));
}

// ---------------- mean pool + final fc ----------------
__global__ void pool_kernel(const float* __restrict__ h, float* __restrict__ out)
{
    int idx = blockIdx.x * 256 + threadIdx.x;
    if (idx >= BATCH * D_MODEL) return;
    int b = idx >> 10, d = idx & (D_MODEL - 1);
    const float* p = h + (size_t)(b * SEQ) * D_MODEL + d;
    float a[8];
#pragma unroll
    for (int i = 0; i < 8; i++) a[i] = 0.f;
    for (int i = 0; i < SEQ; i += 8) {
#pragma unroll
        for (int u = 0; u < 8; u++) a[u] += p[(size_t)(i + u) * D_MODEL];
    }
    float s = ((a[0] + a[1]) + (a[2] + a[3])) + ((a[4] + a[5]) + (a[6] + a[7]));
    out[idx] = s * (1.0f / 1024.0f);
}

__global__ void fc_kernel(const float* __restrict__ pool, const float* __restrict__ fcw,
                          const float* __restrict__ fcb, float* __restrict__ out)
{
    __shared__ float red[8];
    int b = blockIdx.x, t = threadIdx.x;
    float4 p  = *reinterpret_cast<const float4*>(&pool[b * D_MODEL + t * 4]);
    float4 w4 = *reinterpret_cast<const float4*>(&fcw[t * 4]);
    float s = p.x * w4.x + p.y * w4.y + p.z * w4.z + p.w * w4.w;
#pragma unroll
    for (int o = 16; o > 0; o >>= 1) s += __shfl_xor_sync(0xffffffffu, s, o);
    if ((t & 31) == 0) red[t >> 5] = s;
    __syncthreads();
    if (t == 0) {
        float tot = 0.f;
#pragma unroll
        for (int i = 0; i < 8; i++) tot += red[i];
        out[b] = tot + fcb[0];
    }
}

// ---------------- host orchestration ----------------
#define SYM(p, s) cudaGetSymbolAddress((void**)&p, s)

extern "C" void kernel_launch(void* const* d_in, const int* in_sizes, int n_in,
                              void* d_out, int out_size)
{
    (void)in_sizes; (void)n_in; (void)out_size;
    const float* x       = (const float*)d_in[0];
    const float* conv1_w = (const float*)d_in[1];
    const float* conv1_b = (const float*)d_in[2];
    const float* conv2_w = (const float*)d_in[3];
    const float* conv2_b = (const float*)d_in[4];
    const float* lnA_w   = (const float*)d_in[5];
    const float* lnA_b   = (const float*)d_in[6];
    const float* q_w     = (const float*)d_in[7];
    const float* q_b     = (const float*)d_in[8];
    const float* k_w     = (const float*)d_in[9];
    const float* k_b     = (const float*)d_in[10];
    const float* v_w     = (const float*)d_in[11];
    const float* v_b     = (const float*)d_in[12];
    const float* o_w     = (const float*)d_in[13];
    const float* o_b     = (const float*)d_in[14];
    const float* lnB_w   = (const float*)d_in[15];
    const float* lnB_b   = (const float*)d_in[16];
    const float* f1_w    = (const float*)d_in[17];
    const float* f1_b    = (const float*)d_in[18];
    const float* f2_w    = (const float*)d_in[19];
    const float* f2_b    = (const float*)d_in[20];
    const float* fc_w    = (const float*)d_in[21];
    const float* fc_b    = (const float*)d_in[22];
    float* out = (float*)d_out;

    float *p_h, *p_qkvb, *p_pool;
    f16 *p_ga, *p_gb, *p_qv;
    f16 *p_qkvh, *p_qkvl, *p_oh, *p_ol, *p_f1h, *p_f1l, *p_f2h, *p_f2l;
    f16 *p_c1h, *p_c1l, *p_c2h, *p_c2l;
    SYM(p_h, g_h); SYM(p_qkvb, g_qkvb); SYM(p_pool, g_pool);
    SYM(p_ga, ga); SYM(p_gb, gb); SYM(p_qv, g_qkv);
    SYM(p_qkvh, bw_qkv_h); SYM(p_qkvl, bw_qkv_l);
    SYM(p_oh, bw_o_h); SYM(p_ol, bw_o_l);
    SYM(p_f1h, bw_f1_h); SYM(p_f1l, bw_f1_l);
    SYM(p_f2h, bw_f2_h); SYM(p_f2l, bw_f2_l);
    SYM(p_c1h, bw_c1_h); SYM(p_c1l, bw_c1_l);
    SYM(p_c2h, bw_c2_h); SYM(p_c2l, bw_c2_l);

    cudaFuncSetAttribute(attention_mma, cudaFuncAttributeMaxDynamicSharedMemorySize, ATT_SMEM);
    cudaFuncSetAttribute(gemm_wide<false, false, false, false>, cudaFuncAttributeMaxDynamicSharedMemorySize, WGEMM_SMEM);
    cudaFuncSetAttribute(gemm_wide<false, false, false, true>,  cudaFuncAttributeMaxDynamicSharedMemorySize, WGEMM_SMEM);
    cudaFuncSetAttribute(gemm_wide<false, false, true, false>,  cudaFuncAttributeMaxDynamicSharedMemorySize, WGEMM_SMEM);
    cudaFuncSetAttribute(gemm_wide<true, false, false, false>,  cudaFuncAttributeMaxDynamicSharedMemorySize, WGEMM_SMEM);
    cudaFuncSetAttribute(gemm_wide<true, true, false, false>,   cudaFuncAttributeMaxDynamicSharedMemorySize, WGEMM_SMEM);

    // ---- weight prep (split fp16 hi/lo) ----
    qkv_pack<<<(NLAYER * QKV3 * 256 + 255) / 256, 256>>>(q_w, k_w, v_w, p_qkvh, p_qkvl);
    qkvb_pack<<<(NLAYER * QKV3 + 255) / 256, 256>>>(q_b, k_b, v_b, p_qkvb);
    wsplit_all<<<(N4_O + N4_F1 + N4_F2 + 255) / 256, 256>>>(
        o_w, p_oh, p_ol, f1_w, p_f1h, p_f1l, f2_w, p_f2h, p_f2l);
    conv_repack2<<<(NC1 + NC2 + 255) / 256, 256>>>(
        conv1_w, p_c1h, p_c1l, conv2_w, p_c2h, p_c2l);

    // ---- conv frontend (pos-enc fused into conv2 epilogue) ----
    im2col1s<<<(BATCH * S1 * 48 + 255) / 256, 256>>>(x, p_ga);
    gemm_wide<true, false, false, false><<<dim3(2, 33), 512, WGEMM_SMEM>>>(
        p_ga, p_c1h, p_c1l, conv1_b, nullptr, nullptr, p_gb,
        BATCH * S1, DH, 192);
    im2col2s<<<(BATCH * SEQ * 192 + 255) / 256, 256>>>(p_gb, p_ga);
    gemm_wide<false, false, false, true><<<dim3(4, 32), 512, WGEMM_SMEM>>>(
        p_ga, p_c2h, p_c2l, conv2_b, nullptr, p_h, nullptr,
        BATCH * SEQ, D_MODEL, 1536);

    const int M = BATCH * SEQ;  // 4096

    for (int l = 0; l < NLAYER; l++) {
        size_t qkvo = (size_t)l * QKV3 * 1024;
        size_t oo   = (size_t)l * 1024 * 1024;
        size_t f1o  = (size_t)l * 2048 * 1024;
        size_t f2o  = (size_t)l * 1024 * 2048;
        size_t bo   = (size_t)l * D_MODEL;

        layernorm_kernel<<<M, 256>>>(p_h, lnA_w + bo, lnA_b + bo, p_ga);
        gemm_wide<true, false, false, false><<<dim3(QKV3 / 256, 32), 512, WGEMM_SMEM>>>(
            p_ga, p_qkvh + qkvo, p_qkvl + qkvo, p_qkvb + (size_t)l * QKV3,
            nullptr, nullptr, p_qv, M, QKV3, 1024);

        attention_mma<<<dim3(SEQ / 128, NHEAD, BATCH), 256, ATT_SMEM>>>(p_qv, p_ga);

        gemm_wide<false, false, true, false><<<dim3(4, 32), 512, WGEMM_SMEM>>>(
            p_ga, p_oh + oo, p_ol + oo, o_b + bo, p_h, p_h, nullptr,
            M, D_MODEL, 1024);

        layernorm_kernel<<<M, 256>>>(p_h, lnB_w + bo, lnB_b + bo, p_ga);
        gemm_wide<true, true, false, false><<<dim3(FFDIM / 256, 32), 512, WGEMM_SMEM>>>(
            p_ga, p_f1h + f1o, p_f1l + f1o, f1_b + (size_t)l * FFDIM,
            nullptr, nullptr, p_gb, M, FFDIM, 1024);
        gemm_wide<false, false, true, false><<<dim3(4, 32), 512, WGEMM_SMEM>>>(
            p_gb, p_f2h + f2o, p_f2l + f2o, f2_b + bo, p_h, p_h, nullptr,
            M, D_MODEL, 2048);
    }

    pool_kernel<<<(BATCH * D_MODEL) / 256, 256>>>(p_h, p_pool);
    fc_kernel<<<BATCH, 256>>>(p_pool, fc_w, fc_b, out);
}